// round 12
// baseline (speedup 1.0000x reference)
#include <cuda_runtime.h>
#include <cuda_fp16.h>
#include <cstdint>
#include <cstddef>

// ---------------------------------------------------------------------------
// Problem constants
// ---------------------------------------------------------------------------
#define BB   128
#define DD   512
#define HH   8
#define LL   6
#define SS   200
#define LAT  256
#define OUTD 6
#define DKH  64
#define DFF  2048
#define NTOK (BB*SS)   // 25600

// ---------------------------------------------------------------------------
// Device scratch
// ---------------------------------------------------------------------------
__device__ __align__(256) float  g_x   [NTOK*DD];
__device__ __align__(256) float  g_t1  [NTOK*(DD/2)];
__device__ __align__(256) float  g_s1  [BB*(DD/2)];
__device__ __align__(256) float  g_bqkv[LL*3*DD];
__device__ __align__(256) float  g_pe  [SS*DD];

__device__ __align__(256) __half g_z16  [BB*LAT];
__device__ __align__(256) __half g_x16  [NTOK*DD];
__device__ __align__(256) __half g_qkv16[NTOK*3*DD];
__device__ __align__(256) __half g_ctx16[NTOK*DD];
__device__ __align__(256) __half g_h116 [NTOK*DFF];
__device__ __align__(256) __half g_tmp16[NTOK*DD];

__device__ __align__(256) __half g_wqkvT[LL*3*DD*DD];
__device__ __align__(256) __half g_woT  [LL*DD*DD];
__device__ __align__(256) __half g_w1T  [LL*DFF*DD];
__device__ __align__(256) __half g_w2T  [LL*DD*DFF];
__device__ __align__(256) __half g_wlatT[(size_t)(DD*SS)*LAT];
__device__ __align__(256) __half g_wp1T [(DD/2)*DD];
__device__ __align__(256) __half g_ws1T [(DD/2)*LAT];

// ---------------------------------------------------------------------------
// Helpers
// ---------------------------------------------------------------------------
__device__ __forceinline__ uint32_t smem_u32(const void* p) {
    uint32_t a;
    asm("{ .reg .u64 t; cvta.to.shared.u64 t, %1; cvt.u32.u64 %0, t; }"
        : "=r"(a) : "l"(p));
    return a;
}
__device__ __forceinline__ float gelu_f(float x) {
    return 0.5f * x * (1.0f + erff(x * 0.7071067811865475f));
}

#define LDMATRIX_X4(r0, r1, r2, r3, addr)                                     \
    asm volatile("ldmatrix.sync.aligned.m8n8.x4.shared.b16 "                  \
                 "{%0, %1, %2, %3}, [%4];"                                    \
                 : "=r"(r0), "=r"(r1), "=r"(r2), "=r"(r3) : "r"(addr))

#define LDMATRIX_X4_T(r0, r1, r2, r3, addr)                                   \
    asm volatile("ldmatrix.sync.aligned.m8n8.x4.trans.shared.b16 "            \
                 "{%0, %1, %2, %3}, [%4];"                                    \
                 : "=r"(r0), "=r"(r1), "=r"(r2), "=r"(r3) : "r"(addr))

#define MMA16816(c, a, b)                                                     \
    asm volatile("mma.sync.aligned.m16n8k16.row.col.f32.f16.f16.f32 "         \
                 "{%0, %1, %2, %3}, {%4, %5, %6, %7}, {%8, %9}, "             \
                 "{%0, %1, %2, %3};"                                          \
                 : "+f"((c)[0]), "+f"((c)[1]), "+f"((c)[2]), "+f"((c)[3])     \
                 : "r"((a)[0]), "r"((a)[1]), "r"((a)[2]), "r"((a)[3]),        \
                   "r"((b)[0]), "r"((b)[1]))

// swizzled byte offset inside a 128x64h (128B-row) tile
__device__ __forceinline__ uint32_t swz(int row, int colb) {
    return (uint32_t)(row * 128 + (colb ^ ((row & 7) << 4)));
}

// ---------------------------------------------------------------------------
// fp16 tensor-core GEMM (mma.sync):  C[M,N] = act(A[M,K] @ Bt[N,K]^T + bias)
//   CTA tile 128x128, block = 512 (16 warps, 4x4 grid), warp tile 32x32.
//   Small warp tile -> 32 acc regs -> <=64 regs/thread -> 2 CTAs/SM of 512
//   threads = 32 warps/SM for latency hiding.
//   3-stage cp.async pipeline (2 in flight), swizzled smem, ONE barrier/stage.
//   grid = (n_tiles, M/128). N is the C row-stride; pointers may be
//   pre-offset for column-split launches.
//   OM bit0: fp32 C; bit1: fp16 C16.  ACT: 0 none, 1 gelu, 2 gelu + pe[col].
// ---------------------------------------------------------------------------
#define TBUF  16384
#define GSMEM (6*TBUF)

template <int ACT, int OM>
__global__ void __launch_bounds__(512, 2)
hgemm_kernel(int M, int N, int K,
             const __half* __restrict__ A, const __half* __restrict__ Bt,
             const float* __restrict__ bias,
             float* __restrict__ C, __half* __restrict__ C16,
             const float* __restrict__ pe)
{
    extern __shared__ char smem[];
    const uint32_t sb = smem_u32(smem);
    const int tid  = threadIdx.x;
    const int wid  = tid >> 5;
    const int lane = tid & 31;
    const int wm   = wid & 3;          // 4 m-tiles of 32
    const int wn   = wid >> 2;         // 4 n-tiles of 32

    const size_t n0 = (size_t)blockIdx.x * 128;
    const size_t m0 = (size_t)blockIdx.y * 128;
    const __half* Ab = A  + m0 * (size_t)K;
    const __half* Bb = Bt + n0 * (size_t)K;
    const int NS = K >> 6;

    const int ldr  = tid >> 3;          // 0..63
    const int ldcb = (tid & 7) << 4;    // 16B chunk

    auto load_stage = [&](int s) {
        const uint32_t st  = (uint32_t)(s % 3);
        const uint32_t sa  = sb + st * TBUF;
        const uint32_t sbb = sb + 3 * TBUF + st * TBUF;
        const int k0 = s << 6;
#pragma unroll
        for (int i = 0; i < 2; i++) {
            int r = ldr + (i << 6);
            uint32_t off = swz(r, ldcb);
            const void* ag = Ab + (size_t)r * K + k0 + (ldcb >> 1);
            asm volatile("cp.async.cg.shared.global [%0], [%1], 16;"
                         :: "r"(sa + off), "l"(ag) : "memory");
            const void* bg = Bb + (size_t)r * K + k0 + (ldcb >> 1);
            asm volatile("cp.async.cg.shared.global [%0], [%1], 16;"
                         :: "r"(sbb + off), "l"(bg) : "memory");
        }
        asm volatile("cp.async.commit_group;" ::: "memory");
    };

    load_stage(0);
    load_stage(1);

    float acc[2][4][4];
#pragma unroll
    for (int i = 0; i < 2; i++)
#pragma unroll
        for (int j = 0; j < 4; j++)
#pragma unroll
            for (int kq = 0; kq < 4; kq++) acc[i][j][kq] = 0.f;

    const int a_row = wm * 32 + (lane & 15);             // + mt*16
    const int a_kob = (lane >> 4) << 4;
    const int b_row = wn * 32 + (lane & 7) + ((lane >> 4) << 3);  // + nt2*16
    const int b_kob = ((lane >> 3) & 1) << 4;

    for (int s = 0; s < NS; s++) {
        if (s + 1 < NS) asm volatile("cp.async.wait_group 1;" ::: "memory");
        else            asm volatile("cp.async.wait_group 0;" ::: "memory");
        __syncthreads();

        if (s + 2 < NS) load_stage(s + 2);

        const uint32_t st  = (uint32_t)(s % 3);
        const uint32_t sa  = sb + st * TBUF;
        const uint32_t sbb = sb + 3 * TBUF + st * TBUF;

#pragma unroll
        for (int ks = 0; ks < 4; ks++) {
            uint32_t af[2][4];
#pragma unroll
            for (int mt = 0; mt < 2; mt++) {
                uint32_t addr = sa + swz(a_row + mt * 16, ks * 32 + a_kob);
                LDMATRIX_X4(af[mt][0], af[mt][1], af[mt][2], af[mt][3], addr);
            }
            uint32_t bf[4][2];
#pragma unroll
            for (int nt2 = 0; nt2 < 2; nt2++) {
                uint32_t addr = sbb + swz(b_row + nt2 * 16, ks * 32 + b_kob);
                LDMATRIX_X4(bf[2*nt2][0], bf[2*nt2][1],
                            bf[2*nt2+1][0], bf[2*nt2+1][1], addr);
            }
#pragma unroll
            for (int mt = 0; mt < 2; mt++)
#pragma unroll
                for (int nt = 0; nt < 4; nt++)
                    MMA16816(acc[mt][nt], af[mt], bf[nt]);
        }
    }

    // --- epilogue ---
#pragma unroll
    for (int mt = 0; mt < 2; mt++) {
#pragma unroll
        for (int nt = 0; nt < 4; nt++) {
            const size_t col = n0 + wn * 32 + nt * 8 + (lane & 3) * 2;
            const float b0 = bias[col], b1 = bias[col + 1];
            float p0 = 0.f, p1 = 0.f;
            if (ACT == 2) { p0 = pe[col]; p1 = pe[col + 1]; }
#pragma unroll
            for (int hh = 0; hh < 2; hh++) {
                const size_t row = m0 + wm * 32 + mt * 16 + (lane >> 2) + hh * 8;
                float v0 = acc[mt][nt][2*hh]   + b0;
                float v1 = acc[mt][nt][2*hh+1] + b1;
                if (ACT >= 1) { v0 = gelu_f(v0); v1 = gelu_f(v1); }
                if (ACT == 2) { v0 += p0; v1 += p1; }
                if (OM & 1) {
                    float2* dst = (float2*)(C + row * (size_t)N + col);
                    *dst = make_float2(v0, v1);
                }
                if (OM & 2) {
                    __half2* dst = (__half2*)(C16 + row * (size_t)N + col);
                    *dst = __floats2half2_rn(v0, v1);
                }
            }
        }
    }
}

// ---------------------------------------------------------------------------
// Tensor-core attention. grid = (4, H, B); block = 256 (8 warps).
// ---------------------------------------------------------------------------
#define KVST 72
#define PST  232
#define AK_OFF 0
#define AV_OFF 32256
#define AS_OFF 64512
#define ASMEM  94208

__global__ void __launch_bounds__(256, 2)
attn_mma_kernel(const __half* __restrict__ QKV, const float* __restrict__ bias,
                __half* __restrict__ O)
{
    extern __shared__ char smem[];
    const uint32_t sb = smem_u32(smem);
    const int it  = blockIdx.x;
    const int h   = blockIdx.y;
    const int b   = blockIdx.z;
    const int tid = threadIdx.x;
    const int wid = tid >> 5, lane = tid & 31;
    const int i0  = it * 64;
    const size_t tok0 = (size_t)b * SS;
    const int hoff = h * DKH;

    for (int p = tid; p < 224 * 8; p += 256) {
        int j = p >> 3, c = (p & 7) << 3;
        uint4 kv = make_uint4(0, 0, 0, 0), vv = make_uint4(0, 0, 0, 0);
        if (j < SS) {
            kv = *(const uint4*)(QKV + (tok0 + j) * 1536 + 512 + hoff + c);
            vv = *(const uint4*)(QKV + (tok0 + j) * 1536 + 1024 + hoff + c);
        }
        *(uint4*)(smem + AK_OFF + j * (KVST * 2) + c * 2) = kv;
        *(uint4*)(smem + AV_OFF + j * (KVST * 2) + c * 2) = vv;
    }
    __syncthreads();

    // ---- scores = QK^T / 8 -> fp16 buffer ----
    {
        const int wm = wid & 3;
        const int wn = wid >> 2;
        uint32_t aq[4][4];
        {
            const int r_lo = i0 + wm * 16 + (lane >> 2);
            const int r_hi = r_lo + 8;
            const int h2   = lane & 3;
#pragma unroll
            for (int ks = 0; ks < 4; ks++) {
                uint32_t v0 = 0, v1 = 0, v2 = 0, v3 = 0;
                if (r_lo < SS) {
                    const uint32_t* p =
                        (const uint32_t*)(QKV + (tok0 + r_lo) * 1536 + hoff);
                    v0 = p[8 * ks + h2];
                    v2 = p[8 * ks + 4 + h2];
                }
                if (r_hi < SS) {
                    const uint32_t* p =
                        (const uint32_t*)(QKV + (tok0 + r_hi) * 1536 + hoff);
                    v1 = p[8 * ks + h2];
                    v3 = p[8 * ks + 4 + h2];
                }
                aq[ks][0] = v0; aq[ks][1] = v1; aq[ks][2] = v2; aq[ks][3] = v3;
            }
        }
        const int brow = (lane & 7) + ((lane >> 4) << 3);
        const int bkof = ((lane >> 3) & 1) << 3;
        float acc[7][2][4];
#pragma unroll
        for (int g = 0; g < 7; g++)
#pragma unroll
            for (int q = 0; q < 2; q++)
#pragma unroll
                for (int r = 0; r < 4; r++) acc[g][q][r] = 0.f;

#pragma unroll
        for (int ks = 0; ks < 4; ks++) {
#pragma unroll
            for (int g = 0; g < 7; g++) {
                int ncol = wn * 112 + g * 16;
                uint32_t baddr = sb + AK_OFF +
                    (uint32_t)((ncol + brow) * (KVST * 2) + (ks * 16 + bkof) * 2);
                uint32_t b0, b1, b2, b3;
                LDMATRIX_X4(b0, b1, b2, b3, baddr);
                uint32_t bf0[2] = {b0, b1}, bf1[2] = {b2, b3};
                MMA16816(acc[g][0], aq[ks], bf0);
                MMA16816(acc[g][1], aq[ks], bf1);
            }
        }
        __half* ps = (__half*)(smem + AS_OFF);
        const int r0 = wm * 16 + (lane >> 2);
#pragma unroll
        for (int g = 0; g < 7; g++)
#pragma unroll
            for (int q = 0; q < 2; q++) {
                int col = wn * 112 + g * 16 + q * 8 + (lane & 3) * 2;
                *(__half2*)&ps[r0 * PST + col] =
                    __floats2half2_rn(acc[g][q][0] * 0.125f, acc[g][q][1] * 0.125f);
                *(__half2*)&ps[(r0 + 8) * PST + col] =
                    __floats2half2_rn(acc[g][q][2] * 0.125f, acc[g][q][3] * 0.125f);
            }
    }
    __syncthreads();

    // ---- softmax (+bias), in place fp16 -> P ----
    {
        __half* ps = (__half*)(smem + AS_OFF);
        for (int i = wid; i < 64; i += 8) {
            int gi = i0 + i;
            if (gi < SS) {
                const float* brow = bias + ((size_t)h * SS + gi) * SS;
                float vals[7];
                float m = -1e30f;
#pragma unroll
                for (int t = 0; t < 7; t++) {
                    int j = lane + t * 32;
                    float s = -1e30f;
                    if (j < SS) s = __half2float(ps[i * PST + j]) + brow[j];
                    vals[t] = s;
                    m = fmaxf(m, s);
                }
#pragma unroll
                for (int o = 16; o > 0; o >>= 1)
                    m = fmaxf(m, __shfl_xor_sync(0xffffffffu, m, o));
                float sum = 0.f;
#pragma unroll
                for (int t = 0; t < 7; t++) {
                    int j = lane + t * 32;
                    float e = (j < SS) ? expf(vals[t] - m) : 0.f;
                    vals[t] = e;
                    sum += e;
                }
#pragma unroll
                for (int o = 16; o > 0; o >>= 1)
                    sum += __shfl_xor_sync(0xffffffffu, sum, o);
                float inv = 1.f / sum;
#pragma unroll
                for (int t = 0; t < 7; t++)
                    ps[i * PST + lane + t * 32] = __float2half(vals[t] * inv);
            } else {
#pragma unroll
                for (int t = 0; t < 7; t++)
                    ps[i * PST + lane + t * 32] = __float2half(0.f);
            }
        }
    }
    __syncthreads();

    // ---- ctx = P @ V ----
    {
        const int wm = wid & 3;
        const int wn = wid >> 2;
        const int arow = wm * 16 + (lane & 15);
        const int akof = (lane >> 4) << 3;
        const int vrow = lane & 15;
        const int vcol = (lane >> 4) << 3;
        float acc[4][4];
#pragma unroll
        for (int i = 0; i < 4; i++)
#pragma unroll
            for (int j = 0; j < 4; j++) acc[i][j] = 0.f;

#pragma unroll
        for (int ks = 0; ks < 14; ks++) {
            uint32_t a[4];
            uint32_t aaddr = sb + AS_OFF +
                (uint32_t)(arow * (PST * 2) + (ks * 16 + akof) * 2);
            LDMATRIX_X4(a[0], a[1], a[2], a[3], aaddr);
#pragma unroll
            for (int g = 0; g < 2; g++) {
                int n0c = wn * 32 + g * 16;
                uint32_t baddr = sb + AV_OFF +
                    (uint32_t)((ks * 16 + vrow) * (KVST * 2) + (n0c + vcol) * 2);
                uint32_t b0, b1, b2, b3;
                LDMATRIX_X4_T(b0, b1, b2, b3, baddr);
                uint32_t bf0[2] = {b0, b1}, bf1[2] = {b2, b3};
                MMA16816(acc[g * 2 + 0], a, bf0);
                MMA16816(acc[g * 2 + 1], a, bf1);
            }
        }
#pragma unroll
        for (int nt = 0; nt < 4; nt++) {
            int col = hoff + wn * 32 + nt * 8 + (lane & 3) * 2;
#pragma unroll
            for (int hh = 0; hh < 2; hh++) {
                int row = i0 + wm * 16 + (lane >> 2) + hh * 8;
                if (row < SS) {
                    __half2* dst = (__half2*)(O + (tok0 + row) * DD + col);
                    *dst = __floats2half2_rn(acc[nt][2 * hh], acc[nt][2 * hh + 1]);
                }
            }
        }
    }
}

// ---------------------------------------------------------------------------
// transpose + convert: src f32 [R,C] -> dst f16 [C,R]  (R,C % 32 == 0)
// ---------------------------------------------------------------------------
__global__ void transp_kernel(const float* __restrict__ src,
                              __half* __restrict__ dst,
                              int R, int C, size_t sstride, size_t dstride)
{
    __shared__ float t[32][33];
    src += (size_t)blockIdx.z * sstride;
    dst += (size_t)blockIdx.z * dstride;
    const int c0 = blockIdx.x << 5, r0 = blockIdx.y << 5;
    const int x = threadIdx.x;    // 0..7
    const int y = threadIdx.y;    // 0..31

    float4 v = *(const float4*)(src + (size_t)(r0 + y) * C + c0 + x * 4);
    t[y][x * 4 + 0] = v.x;
    t[y][x * 4 + 1] = v.y;
    t[y][x * 4 + 2] = v.z;
    t[y][x * 4 + 3] = v.w;
    __syncthreads();

    __half2 h01 = __floats2half2_rn(t[x * 4 + 0][y], t[x * 4 + 1][y]);
    __half2 h23 = __floats2half2_rn(t[x * 4 + 2][y], t[x * 4 + 3][y]);
    uint2 hv;
    hv.x = *(uint32_t*)&h01;
    hv.y = *(uint32_t*)&h23;
    *(uint2*)(dst + (size_t)(c0 + y) * R + r0 + x * 4) = hv;
}

__global__ void concat_z_kernel(const float* __restrict__ zs,
                                const float* __restrict__ zk,
                                __half* __restrict__ z16)
{
    int i = blockIdx.x * blockDim.x + threadIdx.x;
    if (i >= BB * LAT) return;
    int b = i >> 8, c = i & 255;
    float v = (c < 128) ? zs[b * 128 + c] : zk[b * 128 + (c - 128)];
    z16[i] = __float2half(v);
}

__global__ void concat_bqkv_kernel(const float* __restrict__ bq,
                                   const float* __restrict__ bk,
                                   const float* __restrict__ bv,
                                   float* __restrict__ dst)
{
    int i = blockIdx.x * blockDim.x + threadIdx.x;
    if (i >= LL * 3 * DD) return;
    int l = i / (3 * DD), r = i % (3 * DD), part = r / DD, c = r % DD;
    const float* s = (part == 0) ? bq : (part == 1) ? bk : bv;
    dst[i] = s[l * DD + c];
}

// PE table: pe[s*512+d], bit-identical formula to the reference path.
__global__ void pe_kernel(float* __restrict__ pe)
{
    int s = blockIdx.x;
    int d = threadIdx.x;
    const float c = -9.210340371976184f / (float)DD;
    int de = d & ~1;
    float div = expf((float)de * c);
    float ang = (float)s * div;
    pe[s * DD + d] = (d & 1) ? cosf(ang) : sinf(ang);
}

// ---------------------------------------------------------------------------
// x = LN(x + res16) * g + be, in place; also emit fp16 copy.
// Warp per row, single-pass (sum + sumsq). grid NTOK/8, block 256.
// ---------------------------------------------------------------------------
__global__ void __launch_bounds__(256) ln_kernel(
    float* __restrict__ x, const __half* __restrict__ res,
    const float* __restrict__ g, const float* __restrict__ be,
    __half* __restrict__ x16)
{
    const int wid  = threadIdx.x >> 5;
    const int lane = threadIdx.x & 31;
    const size_t row = (size_t)blockIdx.x * 8 + wid;
    float* xr = x + row * DD;
    const __half* rr = res + row * DD;
    __half* hr = x16 + row * DD;

    float v[16];
    float s = 0.f, q = 0.f;
#pragma unroll
    for (int k = 0; k < 4; k++) {
        float4 xv = ((const float4*)xr)[lane + (k << 5)];
        uint2  rv = ((const uint2*)rr)[lane + (k << 5)];
        __half2 r01 = *(__half2*)&rv.x;
        __half2 r23 = *(__half2*)&rv.y;
        v[4*k+0] = xv.x + __low2float(r01);
        v[4*k+1] = xv.y + __high2float(r01);
        v[4*k+2] = xv.z + __low2float(r23);
        v[4*k+3] = xv.w + __high2float(r23);
#pragma unroll
        for (int j = 0; j < 4; j++) {
            s += v[4*k+j];
            q += v[4*k+j] * v[4*k+j];
        }
    }
#pragma unroll
    for (int o = 16; o > 0; o >>= 1) {
        s += __shfl_xor_sync(0xffffffffu, s, o);
        q += __shfl_xor_sync(0xffffffffu, q, o);
    }
    float mu  = s * (1.f / (float)DD);
    float var = q * (1.f / (float)DD) - mu * mu;
    float rstd = rsqrtf(var + 1e-5f);

#pragma unroll
    for (int k = 0; k < 4; k++) {
        float4 gv = ((const float4*)g)[lane + (k << 5)];
        float4 bv = ((const float4*)be)[lane + (k << 5)];
        float o0 = (v[4*k+0] - mu) * rstd * gv.x + bv.x;
        float o1 = (v[4*k+1] - mu) * rstd * gv.y + bv.y;
        float o2 = (v[4*k+2] - mu) * rstd * gv.z + bv.z;
        float o3 = (v[4*k+3] - mu) * rstd * gv.w + bv.w;
        ((float4*)xr)[lane + (k << 5)] = make_float4(o0, o1, o2, o3);
        __half2 h01 = __floats2half2_rn(o0, o1);
        __half2 h23 = __floats2half2_rn(o2, o3);
        uint2 hv;
        hv.x = *(uint32_t*)&h01;
        hv.y = *(uint32_t*)&h23;
        ((uint2*)hr)[lane + (k << 5)] = hv;
    }
}

// ---------------------------------------------------------------------------
// Head projection
// ---------------------------------------------------------------------------
template <int N>
__global__ void __launch_bounds__(256) head_kernel(
    const float* __restrict__ A, const float* __restrict__ W,
    const float* __restrict__ bias, float* __restrict__ out, int M, int K)
{
    __shared__ float ws[256 * N];
    for (int i = threadIdx.x; i < K * N; i += 256) ws[i] = W[i];
    __syncthreads();
    int m = blockIdx.x * 256 + threadIdx.x;
    if (m >= M) return;
    const float4* a = (const float4*)(A + (size_t)m * K);
    float acc[N];
#pragma unroll
    for (int n = 0; n < N; n++) acc[n] = bias[n];
    for (int k4 = 0; k4 < K / 4; k4++) {
        float4 av = a[k4];
#pragma unroll
        for (int n = 0; n < N; n++) {
            acc[n] += av.x * ws[(k4 * 4 + 0) * N + n];
            acc[n] += av.y * ws[(k4 * 4 + 1) * N + n];
            acc[n] += av.z * ws[(k4 * 4 + 2) * N + n];
            acc[n] += av.w * ws[(k4 * 4 + 3) * N + n];
        }
    }
#pragma unroll
    for (int n = 0; n < N; n++) out[(size_t)m * N + n] = acc[n];
}

// ---------------------------------------------------------------------------
// Host launcher
// ---------------------------------------------------------------------------
extern "C" void kernel_launch(void* const* d_in, const int* in_sizes, int n_in,
                              void* d_out, int out_size)
{
    const float* z_style   = (const float*)d_in[0];
    const float* z_skill   = (const float*)d_in[1];
    const float* W_lat     = (const float*)d_in[2];
    const float* b_lat     = (const float*)d_in[3];
    const float* temp_bias = (const float*)d_in[4];
    const float* Wq  = (const float*)d_in[5];
    const float* bq  = (const float*)d_in[6];
    const float* Wk  = (const float*)d_in[7];
    const float* bk  = (const float*)d_in[8];
    const float* Wv  = (const float*)d_in[9];
    const float* bv  = (const float*)d_in[10];
    const float* Wo  = (const float*)d_in[11];
    const float* bo  = (const float*)d_in[12];
    const float* g1  = (const float*)d_in[13];
    const float* be1 = (const float*)d_in[14];
    const float* g2  = (const float*)d_in[15];
    const float* be2 = (const float*)d_in[16];
    const float* W1  = (const float*)d_in[17];
    const float* bf1 = (const float*)d_in[18];
    const float* W2  = (const float*)d_in[19];
    const float* bf2 = (const float*)d_in[20];
    const float* Wp1 = (const float*)d_in[21];
    const float* bp1 = (const float*)d_in[22];
    const float* Wp2 = (const float*)d_in[23];
    const float* bp2 = (const float*)d_in[24];
    const float* Ws1 = (const float*)d_in[25];
    const float* bs1 = (const float*)d_in[26];
    const float* Ws2 = (const float*)d_in[27];
    const float* bs2 = (const float*)d_in[28];
    float* out = (float*)d_out;

    float *x, *t1, *s1, *bqkv, *pe;
    __half *z16, *x16, *qkv16, *ctx16, *h116, *tmp16;
    __half *wqkvT, *woT, *w1T, *w2T, *wlatT, *wp1T, *ws1T;
    cudaGetSymbolAddress((void**)&x,     g_x);
    cudaGetSymbolAddress((void**)&t1,    g_t1);
    cudaGetSymbolAddress((void**)&s1,    g_s1);
    cudaGetSymbolAddress((void**)&bqkv,  g_bqkv);
    cudaGetSymbolAddress((void**)&pe,    g_pe);
    cudaGetSymbolAddress((void**)&z16,   g_z16);
    cudaGetSymbolAddress((void**)&x16,   g_x16);
    cudaGetSymbolAddress((void**)&qkv16, g_qkv16);
    cudaGetSymbolAddress((void**)&ctx16, g_ctx16);
    cudaGetSymbolAddress((void**)&h116,  g_h116);
    cudaGetSymbolAddress((void**)&tmp16, g_tmp16);
    cudaGetSymbolAddress((void**)&wqkvT, g_wqkvT);
    cudaGetSymbolAddress((void**)&woT,   g_woT);
    cudaGetSymbolAddress((void**)&w1T,   g_w1T);
    cudaGetSymbolAddress((void**)&w2T,   g_w2T);
    cudaGetSymbolAddress((void**)&wlatT, g_wlatT);
    cudaGetSymbolAddress((void**)&wp1T,  g_wp1T);
    cudaGetSymbolAddress((void**)&ws1T,  g_ws1T);

    cudaFuncSetAttribute(hgemm_kernel<0,1>, cudaFuncAttributeMaxDynamicSharedMemorySize, GSMEM);
    cudaFuncSetAttribute(hgemm_kernel<0,2>, cudaFuncAttributeMaxDynamicSharedMemorySize, GSMEM);
    cudaFuncSetAttribute(hgemm_kernel<1,1>, cudaFuncAttributeMaxDynamicSharedMemorySize, GSMEM);
    cudaFuncSetAttribute(hgemm_kernel<1,2>, cudaFuncAttributeMaxDynamicSharedMemorySize, GSMEM);
    cudaFuncSetAttribute(hgemm_kernel<2,3>, cudaFuncAttributeMaxDynamicSharedMemorySize, GSMEM);
    cudaFuncSetAttribute(attn_mma_kernel, cudaFuncAttributeMaxDynamicSharedMemorySize, ASMEM);

    const dim3 tb(8, 32);

    // Launch order keeps launches #4-#6 = hgemm for ncu attribution.
    pe_kernel<<<SS, DD>>>(pe);                                               // 1
    transp_kernel<<<dim3((DD*SS)/32, LAT/32, 1), tb>>>(W_lat, wlatT, LAT, DD*SS, 0, 0);  // 2
    concat_z_kernel<<<(BB * LAT + 255) / 256, 256>>>(z_style, z_skill, z16); // 3

    // latent GEMM: x = gelu(z @ W_lat + b_lat) + PE, split into 3 col ranges
    {
        const int splits[4] = {0, 266, 533, 800};
        for (int si = 0; si < 3; si++) {            // launches 4,5,6
            int t0 = splits[si], nt = splits[si + 1] - splits[si];
            size_t off = (size_t)t0 * 128;
            hgemm_kernel<2,3><<<dim3(nt, 1), 512, GSMEM>>>(
                BB, DD*SS, LAT, z16, wlatT + off * LAT, b_lat + off,
                x + off, x16 + off, pe + off);
        }
    }

    transp_kernel<<<dim3(16, 16, LL), tb>>>(Wq, wqkvT,                   DD, DD, (size_t)DD*DD, (size_t)3*DD*DD);
    transp_kernel<<<dim3(16, 16, LL), tb>>>(Wk, wqkvT + (size_t)DD*DD,   DD, DD, (size_t)DD*DD, (size_t)3*DD*DD);
    transp_kernel<<<dim3(16, 16, LL), tb>>>(Wv, wqkvT + (size_t)2*DD*DD, DD, DD, (size_t)DD*DD, (size_t)3*DD*DD);
    transp_kernel<<<dim3(16, 16, LL), tb>>>(Wo, woT,  DD, DD,  (size_t)DD*DD,  (size_t)DD*DD);
    transp_kernel<<<dim3(64, 16, LL), tb>>>(W1, w1T,  DD, DFF, (size_t)DD*DFF, (size_t)DFF*DD);
    transp_kernel<<<dim3(16, 64, LL), tb>>>(W2, w2T,  DFF, DD, (size_t)DFF*DD, (size_t)DD*DFF);
    transp_kernel<<<dim3((DD/2)/32, DD/32, 1),  tb>>>(Wp1, wp1T, DD, DD/2, 0, 0);
    transp_kernel<<<dim3((DD/2)/32, LAT/32, 1), tb>>>(Ws1, ws1T, LAT, DD/2, 0, 0);
    concat_bqkv_kernel<<<(LL * 3 * DD + 255) / 256, 256>>>(bq, bk, bv, bqkv);

    for (int l = 0; l < LL; l++) {
        const __half* wqkv_l = wqkvT + (size_t)l * 3 * DD * DD;
        const __half* wo_l   = woT   + (size_t)l * DD * DD;
        const __half* w1_l   = w1T   + (size_t)l * DFF * DD;
        const __half* w2_l   = w2T   + (size_t)l * DD * DFF;

        hgemm_kernel<0,2><<<dim3(12, NTOK/128), 512, GSMEM>>>(
            NTOK, 3*DD, DD, x16, wqkv_l, bqkv + (size_t)l*3*DD, nullptr, qkv16, nullptr);

        attn_mma_kernel<<<dim3(4, HH, BB), 256, ASMEM>>>(qkv16, temp_bias, ctx16);

        hgemm_kernel<0,2><<<dim3(4, NTOK/128), 512, GSMEM>>>(
            NTOK, DD, DD, ctx16, wo_l, bo + (size_t)l*DD, nullptr, tmp16, nullptr);
        ln_kernel<<<NTOK/8, 256>>>(x, tmp16, g1 + l*DD, be1 + l*DD, x16);

        hgemm_kernel<1,2><<<dim3(16, NTOK/128), 512, GSMEM>>>(
            NTOK, DFF, DD, x16, w1_l, bf1 + (size_t)l*DFF, nullptr, h116, nullptr);
        hgemm_kernel<0,2><<<dim3(4, NTOK/128), 512, GSMEM>>>(
            NTOK, DD, DFF, h116, w2_l, bf2 + (size_t)l*DD, nullptr, tmp16, nullptr);
        ln_kernel<<<NTOK/8, 256>>>(x, tmp16, g2 + l*DD, be2 + l*DD, x16);
    }

    hgemm_kernel<1,1><<<dim3((DD/2)/128, NTOK/128), 512, GSMEM>>>(
        NTOK, DD/2, DD, x16, wp1T, bp1, t1, nullptr, nullptr);
    head_kernel<OUTD><<<(NTOK + 255) / 256, 256>>>(
        t1, Wp2, bp2, out, NTOK, DD/2);

    hgemm_kernel<1,1><<<dim3((DD/2)/128, 1), 512, GSMEM>>>(
        BB, DD/2, LAT, z16, ws1T, bs1, s1, nullptr, nullptr);
    head_kernel<5><<<(BB + 255) / 256, 256>>>(
        s1, Ws2, bs2, out + (size_t)NTOK * OUTD, BB, DD/2);
}

// round 13
// speedup vs baseline: 1.1223x; 1.1223x over previous
#include <cuda_runtime.h>
#include <cuda_fp16.h>
#include <cstdint>
#include <cstddef>

// ---------------------------------------------------------------------------
// Problem constants
// ---------------------------------------------------------------------------
#define BB   128
#define DD   512
#define HH   8
#define LL   6
#define SS   200
#define LAT  256
#define OUTD 6
#define DKH  64
#define DFF  2048
#define NTOK (BB*SS)   // 25600

// ---------------------------------------------------------------------------
// Device scratch
// ---------------------------------------------------------------------------
__device__ __align__(256) float  g_x   [NTOK*DD];
__device__ __align__(256) float  g_t1  [NTOK*(DD/2)];
__device__ __align__(256) float  g_s1  [BB*(DD/2)];
__device__ __align__(256) float  g_bqkv[LL*3*DD];
__device__ __align__(256) float  g_pe  [SS*DD];

__device__ __align__(256) __half g_z16  [BB*LAT];
__device__ __align__(256) __half g_x16  [NTOK*DD];
__device__ __align__(256) __half g_qkv16[NTOK*3*DD];
__device__ __align__(256) __half g_ctx16[NTOK*DD];
__device__ __align__(256) __half g_h116 [NTOK*DFF];
__device__ __align__(256) __half g_tmp16[NTOK*DD];

__device__ __align__(256) __half g_wqkvT[LL*3*DD*DD];
__device__ __align__(256) __half g_woT  [LL*DD*DD];
__device__ __align__(256) __half g_w1T  [LL*DFF*DD];
__device__ __align__(256) __half g_w2T  [LL*DD*DFF];
__device__ __align__(256) __half g_wlatT[(size_t)(DD*SS)*LAT];
__device__ __align__(256) __half g_wp1T [(DD/2)*DD];
__device__ __align__(256) __half g_ws1T [(DD/2)*LAT];

// ---------------------------------------------------------------------------
// Helpers
// ---------------------------------------------------------------------------
__device__ __forceinline__ uint32_t smem_u32(const void* p) {
    uint32_t a;
    asm("{ .reg .u64 t; cvta.to.shared.u64 t, %1; cvt.u32.u64 %0, t; }"
        : "=r"(a) : "l"(p));
    return a;
}
__device__ __forceinline__ float gelu_f(float x) {
    return 0.5f * x * (1.0f + erff(x * 0.7071067811865475f));
}

#define LDMATRIX_X4(r0, r1, r2, r3, addr)                                     \
    asm volatile("ldmatrix.sync.aligned.m8n8.x4.shared.b16 "                  \
                 "{%0, %1, %2, %3}, [%4];"                                    \
                 : "=r"(r0), "=r"(r1), "=r"(r2), "=r"(r3) : "r"(addr))

#define LDMATRIX_X4_T(r0, r1, r2, r3, addr)                                   \
    asm volatile("ldmatrix.sync.aligned.m8n8.x4.trans.shared.b16 "            \
                 "{%0, %1, %2, %3}, [%4];"                                    \
                 : "=r"(r0), "=r"(r1), "=r"(r2), "=r"(r3) : "r"(addr))

#define MMA16816(c, a, b)                                                     \
    asm volatile("mma.sync.aligned.m16n8k16.row.col.f32.f16.f16.f32 "         \
                 "{%0, %1, %2, %3}, {%4, %5, %6, %7}, {%8, %9}, "             \
                 "{%0, %1, %2, %3};"                                          \
                 : "+f"((c)[0]), "+f"((c)[1]), "+f"((c)[2]), "+f"((c)[3])     \
                 : "r"((a)[0]), "r"((a)[1]), "r"((a)[2]), "r"((a)[3]),        \
                   "r"((b)[0]), "r"((b)[1]))

// swizzled byte offset inside a 128x64h (128B-row) tile
__device__ __forceinline__ uint32_t swz(int row, int colb) {
    return (uint32_t)(row * 128 + (colb ^ ((row & 7) << 4)));
}

// ---------------------------------------------------------------------------
// fp16 tensor-core GEMM (mma.sync):  C[M,N] = act(A[M,K] @ Bt[N,K]^T + bias)
//   CTA tile 128x128, warp tile 64x32 (8 warps, 2x4). 3-stage cp.async
//   pipeline (2 in flight), swizzled smem, ONE barrier per stage.
//   (R9/R10 proven-best configuration.)
//   grid = (N/128, M/128), block = 256.
//   OM bit0: fp32 C; bit1: fp16 C16.  ACT: 0 none, 1 gelu, 2 gelu + pe[col].
// ---------------------------------------------------------------------------
#define TBUF  16384
#define GSMEM (6*TBUF)

template <int ACT, int OM>
__global__ void __launch_bounds__(256, 2)
hgemm_kernel(int M, int N, int K,
             const __half* __restrict__ A, const __half* __restrict__ Bt,
             const float* __restrict__ bias,
             float* __restrict__ C, __half* __restrict__ C16,
             const float* __restrict__ pe)
{
    extern __shared__ char smem[];
    const uint32_t sb = smem_u32(smem);
    const int tid  = threadIdx.x;
    const int wid  = tid >> 5;
    const int lane = tid & 31;
    const int wm   = wid >> 2;
    const int wn   = wid & 3;

    const size_t n0 = (size_t)blockIdx.x * 128;
    const size_t m0 = (size_t)blockIdx.y * 128;
    const __half* Ab = A  + m0 * (size_t)K;
    const __half* Bb = Bt + n0 * (size_t)K;
    const int NS = K >> 6;

    const int ldr  = tid >> 3;
    const int ldcb = (tid & 7) << 4;

    auto load_stage = [&](int s) {
        const uint32_t st  = (uint32_t)(s % 3);
        const uint32_t sa  = sb + st * TBUF;
        const uint32_t sbb = sb + 3 * TBUF + st * TBUF;
        const int k0 = s << 6;
#pragma unroll
        for (int i = 0; i < 4; i++) {
            int r = ldr + (i << 5);
            uint32_t off = swz(r, ldcb);
            const void* ag = Ab + (size_t)r * K + k0 + (ldcb >> 1);
            asm volatile("cp.async.cg.shared.global [%0], [%1], 16;"
                         :: "r"(sa + off), "l"(ag) : "memory");
            const void* bg = Bb + (size_t)r * K + k0 + (ldcb >> 1);
            asm volatile("cp.async.cg.shared.global [%0], [%1], 16;"
                         :: "r"(sbb + off), "l"(bg) : "memory");
        }
        asm volatile("cp.async.commit_group;" ::: "memory");
    };

    load_stage(0);
    load_stage(1);

    float acc[4][4][4];
#pragma unroll
    for (int i = 0; i < 4; i++)
#pragma unroll
        for (int j = 0; j < 4; j++)
#pragma unroll
            for (int kq = 0; kq < 4; kq++) acc[i][j][kq] = 0.f;

    const int a_row = wm * 64 + (lane & 15);
    const int a_kob = (lane >> 4) << 4;
    const int b_row = wn * 32 + (lane & 7) + ((lane >> 4) << 3);
    const int b_kob = ((lane >> 3) & 1) << 4;

    for (int s = 0; s < NS; s++) {
        if (s + 1 < NS) asm volatile("cp.async.wait_group 1;" ::: "memory");
        else            asm volatile("cp.async.wait_group 0;" ::: "memory");
        __syncthreads();

        if (s + 2 < NS) load_stage(s + 2);

        const uint32_t st  = (uint32_t)(s % 3);
        const uint32_t sa  = sb + st * TBUF;
        const uint32_t sbb = sb + 3 * TBUF + st * TBUF;

#pragma unroll
        for (int ks = 0; ks < 4; ks++) {
            uint32_t af[4][4];
#pragma unroll
            for (int mt = 0; mt < 4; mt++) {
                uint32_t addr = sa + swz(a_row + mt * 16, ks * 32 + a_kob);
                LDMATRIX_X4(af[mt][0], af[mt][1], af[mt][2], af[mt][3], addr);
            }
            uint32_t bf[4][2];
#pragma unroll
            for (int nt2 = 0; nt2 < 2; nt2++) {
                uint32_t addr = sbb + swz(b_row + nt2 * 16, ks * 32 + b_kob);
                LDMATRIX_X4(bf[2*nt2][0], bf[2*nt2][1],
                            bf[2*nt2+1][0], bf[2*nt2+1][1], addr);
            }
#pragma unroll
            for (int mt = 0; mt < 4; mt++)
#pragma unroll
                for (int nt = 0; nt < 4; nt++)
                    MMA16816(acc[mt][nt], af[mt], bf[nt]);
        }
    }

    // --- epilogue ---
#pragma unroll
    for (int mt = 0; mt < 4; mt++) {
#pragma unroll
        for (int nt = 0; nt < 4; nt++) {
            const size_t col = n0 + wn * 32 + nt * 8 + (lane & 3) * 2;
            const float b0 = bias[col], b1 = bias[col + 1];
            float p0 = 0.f, p1 = 0.f;
            if (ACT == 2) { p0 = pe[col]; p1 = pe[col + 1]; }
#pragma unroll
            for (int hh = 0; hh < 2; hh++) {
                const size_t row = m0 + wm * 64 + mt * 16 + (lane >> 2) + hh * 8;
                float v0 = acc[mt][nt][2*hh]   + b0;
                float v1 = acc[mt][nt][2*hh+1] + b1;
                if (ACT >= 1) { v0 = gelu_f(v0); v1 = gelu_f(v1); }
                if (ACT == 2) { v0 += p0; v1 += p1; }
                if (OM & 1) {
                    float2* dst = (float2*)(C + row * (size_t)N + col);
                    *dst = make_float2(v0, v1);
                }
                if (OM & 2) {
                    __half2* dst = (__half2*)(C16 + row * (size_t)N + col);
                    *dst = __floats2half2_rn(v0, v1);
                }
            }
        }
    }
}

// ---------------------------------------------------------------------------
// Tensor-core attention. grid = (4, H, B); block = 256 (8 warps).
// ---------------------------------------------------------------------------
#define KVST 72
#define PST  232
#define AK_OFF 0
#define AV_OFF 32256
#define AS_OFF 64512
#define ASMEM  94208

__global__ void __launch_bounds__(256, 2)
attn_mma_kernel(const __half* __restrict__ QKV, const float* __restrict__ bias,
                __half* __restrict__ O)
{
    extern __shared__ char smem[];
    const uint32_t sb = smem_u32(smem);
    const int it  = blockIdx.x;
    const int h   = blockIdx.y;
    const int b   = blockIdx.z;
    const int tid = threadIdx.x;
    const int wid = tid >> 5, lane = tid & 31;
    const int i0  = it * 64;
    const size_t tok0 = (size_t)b * SS;
    const int hoff = h * DKH;

    for (int p = tid; p < 224 * 8; p += 256) {
        int j = p >> 3, c = (p & 7) << 3;
        uint4 kv = make_uint4(0, 0, 0, 0), vv = make_uint4(0, 0, 0, 0);
        if (j < SS) {
            kv = *(const uint4*)(QKV + (tok0 + j) * 1536 + 512 + hoff + c);
            vv = *(const uint4*)(QKV + (tok0 + j) * 1536 + 1024 + hoff + c);
        }
        *(uint4*)(smem + AK_OFF + j * (KVST * 2) + c * 2) = kv;
        *(uint4*)(smem + AV_OFF + j * (KVST * 2) + c * 2) = vv;
    }
    __syncthreads();

    // ---- scores = QK^T / 8 -> fp16 buffer ----
    {
        const int wm = wid & 3;
        const int wn = wid >> 2;
        uint32_t aq[4][4];
        {
            const int r_lo = i0 + wm * 16 + (lane >> 2);
            const int r_hi = r_lo + 8;
            const int h2   = lane & 3;
#pragma unroll
            for (int ks = 0; ks < 4; ks++) {
                uint32_t v0 = 0, v1 = 0, v2 = 0, v3 = 0;
                if (r_lo < SS) {
                    const uint32_t* p =
                        (const uint32_t*)(QKV + (tok0 + r_lo) * 1536 + hoff);
                    v0 = p[8 * ks + h2];
                    v2 = p[8 * ks + 4 + h2];
                }
                if (r_hi < SS) {
                    const uint32_t* p =
                        (const uint32_t*)(QKV + (tok0 + r_hi) * 1536 + hoff);
                    v1 = p[8 * ks + h2];
                    v3 = p[8 * ks + 4 + h2];
                }
                aq[ks][0] = v0; aq[ks][1] = v1; aq[ks][2] = v2; aq[ks][3] = v3;
            }
        }
        const int brow = (lane & 7) + ((lane >> 4) << 3);
        const int bkof = ((lane >> 3) & 1) << 3;
        float acc[7][2][4];
#pragma unroll
        for (int g = 0; g < 7; g++)
#pragma unroll
            for (int q = 0; q < 2; q++)
#pragma unroll
                for (int r = 0; r < 4; r++) acc[g][q][r] = 0.f;

#pragma unroll
        for (int ks = 0; ks < 4; ks++) {
#pragma unroll
            for (int g = 0; g < 7; g++) {
                int ncol = wn * 112 + g * 16;
                uint32_t baddr = sb + AK_OFF +
                    (uint32_t)((ncol + brow) * (KVST * 2) + (ks * 16 + bkof) * 2);
                uint32_t b0, b1, b2, b3;
                LDMATRIX_X4(b0, b1, b2, b3, baddr);
                uint32_t bf0[2] = {b0, b1}, bf1[2] = {b2, b3};
                MMA16816(acc[g][0], aq[ks], bf0);
                MMA16816(acc[g][1], aq[ks], bf1);
            }
        }
        __half* ps = (__half*)(smem + AS_OFF);
        const int r0 = wm * 16 + (lane >> 2);
#pragma unroll
        for (int g = 0; g < 7; g++)
#pragma unroll
            for (int q = 0; q < 2; q++) {
                int col = wn * 112 + g * 16 + q * 8 + (lane & 3) * 2;
                *(__half2*)&ps[r0 * PST + col] =
                    __floats2half2_rn(acc[g][q][0] * 0.125f, acc[g][q][1] * 0.125f);
                *(__half2*)&ps[(r0 + 8) * PST + col] =
                    __floats2half2_rn(acc[g][q][2] * 0.125f, acc[g][q][3] * 0.125f);
            }
    }
    __syncthreads();

    // ---- softmax (+bias), in place fp16 -> P ----
    {
        __half* ps = (__half*)(smem + AS_OFF);
        for (int i = wid; i < 64; i += 8) {
            int gi = i0 + i;
            if (gi < SS) {
                const float* brow = bias + ((size_t)h * SS + gi) * SS;
                float vals[7];
                float m = -1e30f;
#pragma unroll
                for (int t = 0; t < 7; t++) {
                    int j = lane + t * 32;
                    float s = -1e30f;
                    if (j < SS) s = __half2float(ps[i * PST + j]) + brow[j];
                    vals[t] = s;
                    m = fmaxf(m, s);
                }
#pragma unroll
                for (int o = 16; o > 0; o >>= 1)
                    m = fmaxf(m, __shfl_xor_sync(0xffffffffu, m, o));
                float sum = 0.f;
#pragma unroll
                for (int t = 0; t < 7; t++) {
                    int j = lane + t * 32;
                    float e = (j < SS) ? expf(vals[t] - m) : 0.f;
                    vals[t] = e;
                    sum += e;
                }
#pragma unroll
                for (int o = 16; o > 0; o >>= 1)
                    sum += __shfl_xor_sync(0xffffffffu, sum, o);
                float inv = 1.f / sum;
#pragma unroll
                for (int t = 0; t < 7; t++)
                    ps[i * PST + lane + t * 32] = __float2half(vals[t] * inv);
            } else {
#pragma unroll
                for (int t = 0; t < 7; t++)
                    ps[i * PST + lane + t * 32] = __float2half(0.f);
            }
        }
    }
    __syncthreads();

    // ---- ctx = P @ V ----
    {
        const int wm = wid & 3;
        const int wn = wid >> 2;
        const int arow = wm * 16 + (lane & 15);
        const int akof = (lane >> 4) << 3;
        const int vrow = lane & 15;
        const int vcol = (lane >> 4) << 3;
        float acc[4][4];
#pragma unroll
        for (int i = 0; i < 4; i++)
#pragma unroll
            for (int j = 0; j < 4; j++) acc[i][j] = 0.f;

#pragma unroll
        for (int ks = 0; ks < 14; ks++) {
            uint32_t a[4];
            uint32_t aaddr = sb + AS_OFF +
                (uint32_t)(arow * (PST * 2) + (ks * 16 + akof) * 2);
            LDMATRIX_X4(a[0], a[1], a[2], a[3], aaddr);
#pragma unroll
            for (int g = 0; g < 2; g++) {
                int n0c = wn * 32 + g * 16;
                uint32_t baddr = sb + AV_OFF +
                    (uint32_t)((ks * 16 + vrow) * (KVST * 2) + (n0c + vcol) * 2);
                uint32_t b0, b1, b2, b3;
                LDMATRIX_X4_T(b0, b1, b2, b3, baddr);
                uint32_t bf0[2] = {b0, b1}, bf1[2] = {b2, b3};
                MMA16816(acc[g * 2 + 0], a, bf0);
                MMA16816(acc[g * 2 + 1], a, bf1);
            }
        }
#pragma unroll
        for (int nt = 0; nt < 4; nt++) {
            int col = hoff + wn * 32 + nt * 8 + (lane & 3) * 2;
#pragma unroll
            for (int hh = 0; hh < 2; hh++) {
                int row = i0 + wm * 16 + (lane >> 2) + hh * 8;
                if (row < SS) {
                    __half2* dst = (__half2*)(O + (tok0 + row) * DD + col);
                    *dst = __floats2half2_rn(acc[nt][2 * hh], acc[nt][2 * hh + 1]);
                }
            }
        }
    }
}

// ---------------------------------------------------------------------------
// transpose + convert: src f32 [R,C] -> dst f16 [C,R]  (R,C % 32 == 0)
// ---------------------------------------------------------------------------
__global__ void transp_kernel(const float* __restrict__ src,
                              __half* __restrict__ dst,
                              int R, int C, size_t sstride, size_t dstride)
{
    __shared__ float t[32][33];
    src += (size_t)blockIdx.z * sstride;
    dst += (size_t)blockIdx.z * dstride;
    const int c0 = blockIdx.x << 5, r0 = blockIdx.y << 5;
    const int x = threadIdx.x;    // 0..7
    const int y = threadIdx.y;    // 0..31

    float4 v = *(const float4*)(src + (size_t)(r0 + y) * C + c0 + x * 4);
    t[y][x * 4 + 0] = v.x;
    t[y][x * 4 + 1] = v.y;
    t[y][x * 4 + 2] = v.z;
    t[y][x * 4 + 3] = v.w;
    __syncthreads();

    __half2 h01 = __floats2half2_rn(t[x * 4 + 0][y], t[x * 4 + 1][y]);
    __half2 h23 = __floats2half2_rn(t[x * 4 + 2][y], t[x * 4 + 3][y]);
    uint2 hv;
    hv.x = *(uint32_t*)&h01;
    hv.y = *(uint32_t*)&h23;
    *(uint2*)(dst + (size_t)(c0 + y) * R + r0 + x * 4) = hv;
}

__global__ void concat_z_kernel(const float* __restrict__ zs,
                                const float* __restrict__ zk,
                                __half* __restrict__ z16)
{
    int i = blockIdx.x * blockDim.x + threadIdx.x;
    if (i >= BB * LAT) return;
    int b = i >> 8, c = i & 255;
    float v = (c < 128) ? zs[b * 128 + c] : zk[b * 128 + (c - 128)];
    z16[i] = __float2half(v);
}

__global__ void concat_bqkv_kernel(const float* __restrict__ bq,
                                   const float* __restrict__ bk,
                                   const float* __restrict__ bv,
                                   float* __restrict__ dst)
{
    int i = blockIdx.x * blockDim.x + threadIdx.x;
    if (i >= LL * 3 * DD) return;
    int l = i / (3 * DD), r = i % (3 * DD), part = r / DD, c = r % DD;
    const float* s = (part == 0) ? bq : (part == 1) ? bk : bv;
    dst[i] = s[l * DD + c];
}

// PE table: pe[s*512+d], bit-identical formula to the reference path.
__global__ void pe_kernel(float* __restrict__ pe)
{
    int s = blockIdx.x;
    int d = threadIdx.x;
    const float c = -9.210340371976184f / (float)DD;
    int de = d & ~1;
    float div = expf((float)de * c);
    float ang = (float)s * div;
    pe[s * DD + d] = (d & 1) ? cosf(ang) : sinf(ang);
}

// ---------------------------------------------------------------------------
// x = LN(x + res16) * g + be, in place; also emit fp16 copy.
// Warp per row, single-pass (sum + sumsq). grid NTOK/8, block 256.
// ---------------------------------------------------------------------------
__global__ void __launch_bounds__(256) ln_kernel(
    float* __restrict__ x, const __half* __restrict__ res,
    const float* __restrict__ g, const float* __restrict__ be,
    __half* __restrict__ x16)
{
    const int wid  = threadIdx.x >> 5;
    const int lane = threadIdx.x & 31;
    const size_t row = (size_t)blockIdx.x * 8 + wid;
    float* xr = x + row * DD;
    const __half* rr = res + row * DD;
    __half* hr = x16 + row * DD;

    float v[16];
    float s = 0.f, q = 0.f;
#pragma unroll
    for (int k = 0; k < 4; k++) {
        float4 xv = ((const float4*)xr)[lane + (k << 5)];
        uint2  rv = ((const uint2*)rr)[lane + (k << 5)];
        __half2 r01 = *(__half2*)&rv.x;
        __half2 r23 = *(__half2*)&rv.y;
        v[4*k+0] = xv.x + __low2float(r01);
        v[4*k+1] = xv.y + __high2float(r01);
        v[4*k+2] = xv.z + __low2float(r23);
        v[4*k+3] = xv.w + __high2float(r23);
#pragma unroll
        for (int j = 0; j < 4; j++) {
            s += v[4*k+j];
            q += v[4*k+j] * v[4*k+j];
        }
    }
#pragma unroll
    for (int o = 16; o > 0; o >>= 1) {
        s += __shfl_xor_sync(0xffffffffu, s, o);
        q += __shfl_xor_sync(0xffffffffu, q, o);
    }
    float mu  = s * (1.f / (float)DD);
    float var = q * (1.f / (float)DD) - mu * mu;
    float rstd = rsqrtf(var + 1e-5f);

#pragma unroll
    for (int k = 0; k < 4; k++) {
        float4 gv = ((const float4*)g)[lane + (k << 5)];
        float4 bv = ((const float4*)be)[lane + (k << 5)];
        float o0 = (v[4*k+0] - mu) * rstd * gv.x + bv.x;
        float o1 = (v[4*k+1] - mu) * rstd * gv.y + bv.y;
        float o2 = (v[4*k+2] - mu) * rstd * gv.z + bv.z;
        float o3 = (v[4*k+3] - mu) * rstd * gv.w + bv.w;
        ((float4*)xr)[lane + (k << 5)] = make_float4(o0, o1, o2, o3);
        __half2 h01 = __floats2half2_rn(o0, o1);
        __half2 h23 = __floats2half2_rn(o2, o3);
        uint2 hv;
        hv.x = *(uint32_t*)&h01;
        hv.y = *(uint32_t*)&h23;
        ((uint2*)hr)[lane + (k << 5)] = hv;
    }
}

// ---------------------------------------------------------------------------
// Head projection: out[M,N] = A[M,256] @ W[256,N] + bias, N<=6.
// Warp per row; lane covers 8 K-elements; warp-reduce each output.
// grid = ceil(M/8), block = 256 (8 warps). W cached in smem as [n][k].
// ---------------------------------------------------------------------------
template <int N>
__global__ void __launch_bounds__(256) head_kernel(
    const float* __restrict__ A, const float* __restrict__ W,
    const float* __restrict__ bias, float* __restrict__ out, int M)
{
    __shared__ float ws[N * 256];
    for (int i = threadIdx.x; i < N * 256; i += 256) {
        int n = i >> 8, k = i & 255;
        ws[i] = W[k * N + n];
    }
    __syncthreads();

    const int wid  = threadIdx.x >> 5;
    const int lane = threadIdx.x & 31;
    const int m = blockIdx.x * 8 + wid;
    if (m >= M) return;

    const float4* a4 = (const float4*)(A + (size_t)m * 256);
    float4 v0 = a4[lane];
    float4 v1 = a4[lane + 32];
    const int k0 = lane * 4;
    const int k1 = 128 + lane * 4;

    float acc[N];
#pragma unroll
    for (int n = 0; n < N; n++) {
        const float* w = ws + n * 256;
        acc[n] = v0.x * w[k0] + v0.y * w[k0 + 1] + v0.z * w[k0 + 2] + v0.w * w[k0 + 3]
               + v1.x * w[k1] + v1.y * w[k1 + 1] + v1.z * w[k1 + 2] + v1.w * w[k1 + 3];
    }
#pragma unroll
    for (int n = 0; n < N; n++)
#pragma unroll
        for (int o = 16; o > 0; o >>= 1)
            acc[n] += __shfl_xor_sync(0xffffffffu, acc[n], o);

    if (lane < N)
        out[(size_t)m * N + lane] = acc[lane] + bias[lane];
}

// ---------------------------------------------------------------------------
// Host launcher
// ---------------------------------------------------------------------------
extern "C" void kernel_launch(void* const* d_in, const int* in_sizes, int n_in,
                              void* d_out, int out_size)
{
    const float* z_style   = (const float*)d_in[0];
    const float* z_skill   = (const float*)d_in[1];
    const float* W_lat     = (const float*)d_in[2];
    const float* b_lat     = (const float*)d_in[3];
    const float* temp_bias = (const float*)d_in[4];
    const float* Wq  = (const float*)d_in[5];
    const float* bq  = (const float*)d_in[6];
    const float* Wk  = (const float*)d_in[7];
    const float* bk  = (const float*)d_in[8];
    const float* Wv  = (const float*)d_in[9];
    const float* bv  = (const float*)d_in[10];
    const float* Wo  = (const float*)d_in[11];
    const float* bo  = (const float*)d_in[12];
    const float* g1  = (const float*)d_in[13];
    const float* be1 = (const float*)d_in[14];
    const float* g2  = (const float*)d_in[15];
    const float* be2 = (const float*)d_in[16];
    const float* W1  = (const float*)d_in[17];
    const float* bf1 = (const float*)d_in[18];
    const float* W2  = (const float*)d_in[19];
    const float* bf2 = (const float*)d_in[20];
    const float* Wp1 = (const float*)d_in[21];
    const float* bp1 = (const float*)d_in[22];
    const float* Wp2 = (const float*)d_in[23];
    const float* bp2 = (const float*)d_in[24];
    const float* Ws1 = (const float*)d_in[25];
    const float* bs1 = (const float*)d_in[26];
    const float* Ws2 = (const float*)d_in[27];
    const float* bs2 = (const float*)d_in[28];
    float* out = (float*)d_out;

    float *x, *t1, *s1, *bqkv, *pe;
    __half *z16, *x16, *qkv16, *ctx16, *h116, *tmp16;
    __half *wqkvT, *woT, *w1T, *w2T, *wlatT, *wp1T, *ws1T;
    cudaGetSymbolAddress((void**)&x,     g_x);
    cudaGetSymbolAddress((void**)&t1,    g_t1);
    cudaGetSymbolAddress((void**)&s1,    g_s1);
    cudaGetSymbolAddress((void**)&bqkv,  g_bqkv);
    cudaGetSymbolAddress((void**)&pe,    g_pe);
    cudaGetSymbolAddress((void**)&z16,   g_z16);
    cudaGetSymbolAddress((void**)&x16,   g_x16);
    cudaGetSymbolAddress((void**)&qkv16, g_qkv16);
    cudaGetSymbolAddress((void**)&ctx16, g_ctx16);
    cudaGetSymbolAddress((void**)&h116,  g_h116);
    cudaGetSymbolAddress((void**)&tmp16, g_tmp16);
    cudaGetSymbolAddress((void**)&wqkvT, g_wqkvT);
    cudaGetSymbolAddress((void**)&woT,   g_woT);
    cudaGetSymbolAddress((void**)&w1T,   g_w1T);
    cudaGetSymbolAddress((void**)&w2T,   g_w2T);
    cudaGetSymbolAddress((void**)&wlatT, g_wlatT);
    cudaGetSymbolAddress((void**)&wp1T,  g_wp1T);
    cudaGetSymbolAddress((void**)&ws1T,  g_ws1T);

    cudaFuncSetAttribute(hgemm_kernel<0,1>, cudaFuncAttributeMaxDynamicSharedMemorySize, GSMEM);
    cudaFuncSetAttribute(hgemm_kernel<0,2>, cudaFuncAttributeMaxDynamicSharedMemorySize, GSMEM);
    cudaFuncSetAttribute(hgemm_kernel<1,1>, cudaFuncAttributeMaxDynamicSharedMemorySize, GSMEM);
    cudaFuncSetAttribute(hgemm_kernel<1,2>, cudaFuncAttributeMaxDynamicSharedMemorySize, GSMEM);
    cudaFuncSetAttribute(hgemm_kernel<2,3>, cudaFuncAttributeMaxDynamicSharedMemorySize, GSMEM);
    cudaFuncSetAttribute(attn_mma_kernel, cudaFuncAttributeMaxDynamicSharedMemorySize, ASMEM);

    const dim3 tb(8, 32);

    pe_kernel<<<SS, DD>>>(pe);
    transp_kernel<<<dim3((DD*SS)/32, LAT/32, 1), tb>>>(W_lat, wlatT, LAT, DD*SS, 0, 0);
    concat_z_kernel<<<(BB * LAT + 255) / 256, 256>>>(z_style, z_skill, z16);

    // latent GEMM: x = gelu(z @ W_lat + b_lat) + PE
    hgemm_kernel<2,3><<<dim3((DD*SS)/128, 1), 256, GSMEM>>>(
        BB, DD*SS, LAT, z16, wlatT, b_lat, x, x16, pe);

    transp_kernel<<<dim3(16, 16, LL), tb>>>(Wq, wqkvT,                   DD, DD, (size_t)DD*DD, (size_t)3*DD*DD);
    transp_kernel<<<dim3(16, 16, LL), tb>>>(Wk, wqkvT + (size_t)DD*DD,   DD, DD, (size_t)DD*DD, (size_t)3*DD*DD);
    transp_kernel<<<dim3(16, 16, LL), tb>>>(Wv, wqkvT + (size_t)2*DD*DD, DD, DD, (size_t)DD*DD, (size_t)3*DD*DD);
    transp_kernel<<<dim3(16, 16, LL), tb>>>(Wo, woT,  DD, DD,  (size_t)DD*DD,  (size_t)DD*DD);
    transp_kernel<<<dim3(64, 16, LL), tb>>>(W1, w1T,  DD, DFF, (size_t)DD*DFF, (size_t)DFF*DD);
    transp_kernel<<<dim3(16, 64, LL), tb>>>(W2, w2T,  DFF, DD, (size_t)DFF*DD, (size_t)DD*DFF);
    transp_kernel<<<dim3((DD/2)/32, DD/32, 1),  tb>>>(Wp1, wp1T, DD, DD/2, 0, 0);
    transp_kernel<<<dim3((DD/2)/32, LAT/32, 1), tb>>>(Ws1, ws1T, LAT, DD/2, 0, 0);
    concat_bqkv_kernel<<<(LL * 3 * DD + 255) / 256, 256>>>(bq, bk, bv, bqkv);

    for (int l = 0; l < LL; l++) {
        const __half* wqkv_l = wqkvT + (size_t)l * 3 * DD * DD;
        const __half* wo_l   = woT   + (size_t)l * DD * DD;
        const __half* w1_l   = w1T   + (size_t)l * DFF * DD;
        const __half* w2_l   = w2T   + (size_t)l * DD * DFF;

        hgemm_kernel<0,2><<<dim3(12, NTOK/128), 256, GSMEM>>>(
            NTOK, 3*DD, DD, x16, wqkv_l, bqkv + (size_t)l*3*DD, nullptr, qkv16, nullptr);

        attn_mma_kernel<<<dim3(4, HH, BB), 256, ASMEM>>>(qkv16, temp_bias, ctx16);

        hgemm_kernel<0,2><<<dim3(4, NTOK/128), 256, GSMEM>>>(
            NTOK, DD, DD, ctx16, wo_l, bo + (size_t)l*DD, nullptr, tmp16, nullptr);
        ln_kernel<<<NTOK/8, 256>>>(x, tmp16, g1 + l*DD, be1 + l*DD, x16);

        hgemm_kernel<1,2><<<dim3(16, NTOK/128), 256, GSMEM>>>(
            NTOK, DFF, DD, x16, w1_l, bf1 + (size_t)l*DFF, nullptr, h116, nullptr);
        hgemm_kernel<0,2><<<dim3(4, NTOK/128), 256, GSMEM>>>(
            NTOK, DD, DFF, h116, w2_l, bf2 + (size_t)l*DD, nullptr, tmp16, nullptr);
        ln_kernel<<<NTOK/8, 256>>>(x, tmp16, g2 + l*DD, be2 + l*DD, x16);
    }

    hgemm_kernel<1,1><<<dim3((DD/2)/128, NTOK/128), 256, GSMEM>>>(
        NTOK, DD/2, DD, x16, wp1T, bp1, t1, nullptr, nullptr);
    head_kernel<OUTD><<<(NTOK + 7) / 8, 256>>>(
        t1, Wp2, bp2, out, NTOK);

    hgemm_kernel<1,1><<<dim3((DD/2)/128, 1), 256, GSMEM>>>(
        BB, DD/2, LAT, z16, ws1T, bs1, s1, nullptr, nullptr);
    head_kernel<5><<<(BB + 7) / 8, 256>>>(
        s1, Ws2, bs2, out + (size_t)NTOK * OUTD, BB);
}

// round 14
// speedup vs baseline: 1.1420x; 1.0175x over previous
#include <cuda_runtime.h>
#include <cuda_fp16.h>
#include <cstdint>
#include <cstddef>

// ---------------------------------------------------------------------------
// Problem constants
// ---------------------------------------------------------------------------
#define BB   128
#define DD   512
#define HH   8
#define LL   6
#define SS   200
#define LAT  256
#define OUTD 6
#define DKH  64
#define DFF  2048
#define NTOK (BB*SS)   // 25600

// ---------------------------------------------------------------------------
// Device scratch
// ---------------------------------------------------------------------------
__device__ __align__(256) float  g_x   [NTOK*DD];
__device__ __align__(256) float  g_t1  [NTOK*(DD/2)];
__device__ __align__(256) float  g_s1  [BB*(DD/2)];
__device__ __align__(256) float  g_bqkv[LL*3*DD];
__device__ __align__(256) float  g_pe  [SS*DD];

__device__ __align__(256) __half g_z16  [BB*LAT];
__device__ __align__(256) __half g_x16  [NTOK*DD];
__device__ __align__(256) __half g_qkv16[NTOK*3*DD];
__device__ __align__(256) __half g_ctx16[NTOK*DD];
__device__ __align__(256) __half g_h116 [NTOK*DFF];
__device__ __align__(256) __half g_tmp16[NTOK*DD];

__device__ __align__(256) __half g_wqkvT[LL*3*DD*DD];
__device__ __align__(256) __half g_woT  [LL*DD*DD];
__device__ __align__(256) __half g_w1T  [LL*DFF*DD];
__device__ __align__(256) __half g_w2T  [LL*DD*DFF];
__device__ __align__(256) __half g_wlatT[(size_t)(DD*SS)*LAT];
__device__ __align__(256) __half g_wp1T [(DD/2)*DD];
__device__ __align__(256) __half g_ws1T [(DD/2)*LAT];

// ---------------------------------------------------------------------------
// Helpers
// ---------------------------------------------------------------------------
__device__ __forceinline__ uint32_t smem_u32(const void* p) {
    uint32_t a;
    asm("{ .reg .u64 t; cvta.to.shared.u64 t, %1; cvt.u32.u64 %0, t; }"
        : "=r"(a) : "l"(p));
    return a;
}
__device__ __forceinline__ float gelu_f(float x) {
    return 0.5f * x * (1.0f + erff(x * 0.7071067811865475f));
}

#define LDMATRIX_X4(r0, r1, r2, r3, addr)                                     \
    asm volatile("ldmatrix.sync.aligned.m8n8.x4.shared.b16 "                  \
                 "{%0, %1, %2, %3}, [%4];"                                    \
                 : "=r"(r0), "=r"(r1), "=r"(r2), "=r"(r3) : "r"(addr))

#define LDMATRIX_X4_T(r0, r1, r2, r3, addr)                                   \
    asm volatile("ldmatrix.sync.aligned.m8n8.x4.trans.shared.b16 "            \
                 "{%0, %1, %2, %3}, [%4];"                                    \
                 : "=r"(r0), "=r"(r1), "=r"(r2), "=r"(r3) : "r"(addr))

#define MMA16816(c, a, b)                                                     \
    asm volatile("mma.sync.aligned.m16n8k16.row.col.f32.f16.f16.f32 "         \
                 "{%0, %1, %2, %3}, {%4, %5, %6, %7}, {%8, %9}, "             \
                 "{%0, %1, %2, %3};"                                          \
                 : "+f"((c)[0]), "+f"((c)[1]), "+f"((c)[2]), "+f"((c)[3])     \
                 : "r"((a)[0]), "r"((a)[1]), "r"((a)[2]), "r"((a)[3]),        \
                   "r"((b)[0]), "r"((b)[1]))

// swizzled byte offset inside a 128x64h (128B-row) tile
__device__ __forceinline__ uint32_t swz(int row, int colb) {
    return (uint32_t)(row * 128 + (colb ^ ((row & 7) << 4)));
}

// ---------------------------------------------------------------------------
// fp16 tensor-core GEMM (mma.sync):  C[M,N] = act(A[M,K] @ Bt[N,K]^T + bias)
//   CTA tile 128x128, warp tile 64x32 (8 warps, 2x4). 3-stage cp.async
//   pipeline (2 in flight), swizzled smem, ONE barrier per stage.
//   LDSM addresses fully hoisted: the XOR swizzle mask is invariant under
//   row += 16k (mask = (row&7)<<4), so per-(ks) swizzled column offsets are
//   precomputed; the mainloop does one ADD per ldmatrix.
//   grid = (N/128, M/128), block = 256.
//   OM bit0: fp32 C; bit1: fp16 C16.  ACT: 0 none, 1 gelu, 2 gelu + pe[col].
// ---------------------------------------------------------------------------
#define TBUF  16384
#define GSMEM (6*TBUF)

template <int ACT, int OM>
__global__ void __launch_bounds__(256, 2)
hgemm_kernel(int M, int N, int K,
             const __half* __restrict__ A, const __half* __restrict__ Bt,
             const float* __restrict__ bias,
             float* __restrict__ C, __half* __restrict__ C16,
             const float* __restrict__ pe)
{
    extern __shared__ char smem[];
    const uint32_t sb = smem_u32(smem);
    const int tid  = threadIdx.x;
    const int wid  = tid >> 5;
    const int lane = tid & 31;
    const int wm   = wid >> 2;
    const int wn   = wid & 3;

    const size_t n0 = (size_t)blockIdx.x * 128;
    const size_t m0 = (size_t)blockIdx.y * 128;
    const __half* Ab = A  + m0 * (size_t)K;
    const __half* Bb = Bt + n0 * (size_t)K;
    const int NS = K >> 6;

    const int ldr  = tid >> 3;
    const int ldcb = (tid & 7) << 4;

    auto load_stage = [&](int s) {
        const uint32_t st  = (uint32_t)(s % 3);
        const uint32_t sa  = sb + st * TBUF;
        const uint32_t sbb = sb + 3 * TBUF + st * TBUF;
        const int k0 = s << 6;
#pragma unroll
        for (int i = 0; i < 4; i++) {
            int r = ldr + (i << 5);
            uint32_t off = swz(r, ldcb);
            const void* ag = Ab + (size_t)r * K + k0 + (ldcb >> 1);
            asm volatile("cp.async.cg.shared.global [%0], [%1], 16;"
                         :: "r"(sa + off), "l"(ag) : "memory");
            const void* bg = Bb + (size_t)r * K + k0 + (ldcb >> 1);
            asm volatile("cp.async.cg.shared.global [%0], [%1], 16;"
                         :: "r"(sbb + off), "l"(bg) : "memory");
        }
        asm volatile("cp.async.commit_group;" ::: "memory");
    };

    load_stage(0);
    load_stage(1);

    float acc[4][4][4];
#pragma unroll
    for (int i = 0; i < 4; i++)
#pragma unroll
        for (int j = 0; j < 4; j++)
#pragma unroll
            for (int kq = 0; kq < 4; kq++) acc[i][j][kq] = 0.f;

    const int a_row = wm * 64 + (lane & 15);
    const int a_kob = (lane >> 4) << 4;
    const int b_row = wn * 32 + (lane & 7) + ((lane >> 4) << 3);
    const int b_kob = ((lane >> 3) & 1) << 4;

    // --- hoisted LDSM address components (masks invariant under row+=16k) ---
    const uint32_t a_msk = (uint32_t)((a_row & 7) << 4);
    const uint32_t b_msk = (uint32_t)((b_row & 7) << 4);
    uint32_t a_off[4], b_off[4];   // per-ks: row-term + swizzled column
#pragma unroll
    for (int ks = 0; ks < 4; ks++) {
        a_off[ks] = (uint32_t)(a_row * 128) +
                    ((uint32_t)(ks * 32 + a_kob) ^ a_msk);
        b_off[ks] = (uint32_t)(b_row * 128) +
                    ((uint32_t)(ks * 32 + b_kob) ^ b_msk);
    }

    for (int s = 0; s < NS; s++) {
        if (s + 1 < NS) asm volatile("cp.async.wait_group 1;" ::: "memory");
        else            asm volatile("cp.async.wait_group 0;" ::: "memory");
        __syncthreads();

        if (s + 2 < NS) load_stage(s + 2);

        const uint32_t st  = (uint32_t)(s % 3);
        const uint32_t sa  = sb + st * TBUF;
        const uint32_t sbb = sb + 3 * TBUF + st * TBUF;

#pragma unroll
        for (int ks = 0; ks < 4; ks++) {
            const uint32_t abase = sa  + a_off[ks];
            const uint32_t bbase = sbb + b_off[ks];
            uint32_t af[4][4];
#pragma unroll
            for (int mt = 0; mt < 4; mt++) {
                LDMATRIX_X4(af[mt][0], af[mt][1], af[mt][2], af[mt][3],
                            abase + (uint32_t)(mt * 2048));
            }
            uint32_t bf[4][2];
#pragma unroll
            for (int nt2 = 0; nt2 < 2; nt2++) {
                LDMATRIX_X4(bf[2*nt2][0], bf[2*nt2][1],
                            bf[2*nt2+1][0], bf[2*nt2+1][1],
                            bbase + (uint32_t)(nt2 * 2048));
            }
#pragma unroll
            for (int mt = 0; mt < 4; mt++)
#pragma unroll
                for (int nt = 0; nt < 4; nt++)
                    MMA16816(acc[mt][nt], af[mt], bf[nt]);
        }
    }

    // --- epilogue ---
#pragma unroll
    for (int mt = 0; mt < 4; mt++) {
#pragma unroll
        for (int nt = 0; nt < 4; nt++) {
            const size_t col = n0 + wn * 32 + nt * 8 + (lane & 3) * 2;
            const float b0 = bias[col], b1 = bias[col + 1];
            float p0 = 0.f, p1 = 0.f;
            if (ACT == 2) { p0 = pe[col]; p1 = pe[col + 1]; }
#pragma unroll
            for (int hh = 0; hh < 2; hh++) {
                const size_t row = m0 + wm * 64 + mt * 16 + (lane >> 2) + hh * 8;
                float v0 = acc[mt][nt][2*hh]   + b0;
                float v1 = acc[mt][nt][2*hh+1] + b1;
                if (ACT >= 1) { v0 = gelu_f(v0); v1 = gelu_f(v1); }
                if (ACT == 2) { v0 += p0; v1 += p1; }
                if (OM & 1) {
                    float2* dst = (float2*)(C + row * (size_t)N + col);
                    *dst = make_float2(v0, v1);
                }
                if (OM & 2) {
                    __half2* dst = (__half2*)(C16 + row * (size_t)N + col);
                    *dst = __floats2half2_rn(v0, v1);
                }
            }
        }
    }
}

// ---------------------------------------------------------------------------
// Tensor-core attention. grid = (4, H, B); block = 256 (8 warps).
// ---------------------------------------------------------------------------
#define KVST 72
#define PST  232
#define AK_OFF 0
#define AV_OFF 32256
#define AS_OFF 64512
#define ASMEM  94208

__global__ void __launch_bounds__(256, 2)
attn_mma_kernel(const __half* __restrict__ QKV, const float* __restrict__ bias,
                __half* __restrict__ O)
{
    extern __shared__ char smem[];
    const uint32_t sb = smem_u32(smem);
    const int it  = blockIdx.x;
    const int h   = blockIdx.y;
    const int b   = blockIdx.z;
    const int tid = threadIdx.x;
    const int wid = tid >> 5, lane = tid & 31;
    const int i0  = it * 64;
    const size_t tok0 = (size_t)b * SS;
    const int hoff = h * DKH;

    for (int p = tid; p < 224 * 8; p += 256) {
        int j = p >> 3, c = (p & 7) << 3;
        uint4 kv = make_uint4(0, 0, 0, 0), vv = make_uint4(0, 0, 0, 0);
        if (j < SS) {
            kv = *(const uint4*)(QKV + (tok0 + j) * 1536 + 512 + hoff + c);
            vv = *(const uint4*)(QKV + (tok0 + j) * 1536 + 1024 + hoff + c);
        }
        *(uint4*)(smem + AK_OFF + j * (KVST * 2) + c * 2) = kv;
        *(uint4*)(smem + AV_OFF + j * (KVST * 2) + c * 2) = vv;
    }
    __syncthreads();

    // ---- scores = QK^T / 8 -> fp16 buffer ----
    {
        const int wm = wid & 3;
        const int wn = wid >> 2;
        uint32_t aq[4][4];
        {
            const int r_lo = i0 + wm * 16 + (lane >> 2);
            const int r_hi = r_lo + 8;
            const int h2   = lane & 3;
#pragma unroll
            for (int ks = 0; ks < 4; ks++) {
                uint32_t v0 = 0, v1 = 0, v2 = 0, v3 = 0;
                if (r_lo < SS) {
                    const uint32_t* p =
                        (const uint32_t*)(QKV + (tok0 + r_lo) * 1536 + hoff);
                    v0 = p[8 * ks + h2];
                    v2 = p[8 * ks + 4 + h2];
                }
                if (r_hi < SS) {
                    const uint32_t* p =
                        (const uint32_t*)(QKV + (tok0 + r_hi) * 1536 + hoff);
                    v1 = p[8 * ks + h2];
                    v3 = p[8 * ks + 4 + h2];
                }
                aq[ks][0] = v0; aq[ks][1] = v1; aq[ks][2] = v2; aq[ks][3] = v3;
            }
        }
        const int brow = (lane & 7) + ((lane >> 4) << 3);
        const int bkof = ((lane >> 3) & 1) << 3;
        float acc[7][2][4];
#pragma unroll
        for (int g = 0; g < 7; g++)
#pragma unroll
            for (int q = 0; q < 2; q++)
#pragma unroll
                for (int r = 0; r < 4; r++) acc[g][q][r] = 0.f;

#pragma unroll
        for (int ks = 0; ks < 4; ks++) {
#pragma unroll
            for (int g = 0; g < 7; g++) {
                int ncol = wn * 112 + g * 16;
                uint32_t baddr = sb + AK_OFF +
                    (uint32_t)((ncol + brow) * (KVST * 2) + (ks * 16 + bkof) * 2);
                uint32_t b0, b1, b2, b3;
                LDMATRIX_X4(b0, b1, b2, b3, baddr);
                uint32_t bf0[2] = {b0, b1}, bf1[2] = {b2, b3};
                MMA16816(acc[g][0], aq[ks], bf0);
                MMA16816(acc[g][1], aq[ks], bf1);
            }
        }
        __half* ps = (__half*)(smem + AS_OFF);
        const int r0 = wm * 16 + (lane >> 2);
#pragma unroll
        for (int g = 0; g < 7; g++)
#pragma unroll
            for (int q = 0; q < 2; q++) {
                int col = wn * 112 + g * 16 + q * 8 + (lane & 3) * 2;
                *(__half2*)&ps[r0 * PST + col] =
                    __floats2half2_rn(acc[g][q][0] * 0.125f, acc[g][q][1] * 0.125f);
                *(__half2*)&ps[(r0 + 8) * PST + col] =
                    __floats2half2_rn(acc[g][q][2] * 0.125f, acc[g][q][3] * 0.125f);
            }
    }
    __syncthreads();

    // ---- softmax (+bias), in place fp16 -> P ----
    {
        __half* ps = (__half*)(smem + AS_OFF);
        for (int i = wid; i < 64; i += 8) {
            int gi = i0 + i;
            if (gi < SS) {
                const float* brow = bias + ((size_t)h * SS + gi) * SS;
                float vals[7];
                float m = -1e30f;
#pragma unroll
                for (int t = 0; t < 7; t++) {
                    int j = lane + t * 32;
                    float s = -1e30f;
                    if (j < SS) s = __half2float(ps[i * PST + j]) + brow[j];
                    vals[t] = s;
                    m = fmaxf(m, s);
                }
#pragma unroll
                for (int o = 16; o > 0; o >>= 1)
                    m = fmaxf(m, __shfl_xor_sync(0xffffffffu, m, o));
                float sum = 0.f;
#pragma unroll
                for (int t = 0; t < 7; t++) {
                    int j = lane + t * 32;
                    float e = (j < SS) ? expf(vals[t] - m) : 0.f;
                    vals[t] = e;
                    sum += e;
                }
#pragma unroll
                for (int o = 16; o > 0; o >>= 1)
                    sum += __shfl_xor_sync(0xffffffffu, sum, o);
                float inv = 1.f / sum;
#pragma unroll
                for (int t = 0; t < 7; t++)
                    ps[i * PST + lane + t * 32] = __float2half(vals[t] * inv);
            } else {
#pragma unroll
                for (int t = 0; t < 7; t++)
                    ps[i * PST + lane + t * 32] = __float2half(0.f);
            }
        }
    }
    __syncthreads();

    // ---- ctx = P @ V ----
    {
        const int wm = wid & 3;
        const int wn = wid >> 2;
        const int arow = wm * 16 + (lane & 15);
        const int akof = (lane >> 4) << 3;
        const int vrow = lane & 15;
        const int vcol = (lane >> 4) << 3;
        float acc[4][4];
#pragma unroll
        for (int i = 0; i < 4; i++)
#pragma unroll
            for (int j = 0; j < 4; j++) acc[i][j] = 0.f;

#pragma unroll
        for (int ks = 0; ks < 14; ks++) {
            uint32_t a[4];
            uint32_t aaddr = sb + AS_OFF +
                (uint32_t)(arow * (PST * 2) + (ks * 16 + akof) * 2);
            LDMATRIX_X4(a[0], a[1], a[2], a[3], aaddr);
#pragma unroll
            for (int g = 0; g < 2; g++) {
                int n0c = wn * 32 + g * 16;
                uint32_t baddr = sb + AV_OFF +
                    (uint32_t)((ks * 16 + vrow) * (KVST * 2) + (n0c + vcol) * 2);
                uint32_t b0, b1, b2, b3;
                LDMATRIX_X4_T(b0, b1, b2, b3, baddr);
                uint32_t bf0[2] = {b0, b1}, bf1[2] = {b2, b3};
                MMA16816(acc[g * 2 + 0], a, bf0);
                MMA16816(acc[g * 2 + 1], a, bf1);
            }
        }
#pragma unroll
        for (int nt = 0; nt < 4; nt++) {
            int col = hoff + wn * 32 + nt * 8 + (lane & 3) * 2;
#pragma unroll
            for (int hh = 0; hh < 2; hh++) {
                int row = i0 + wm * 16 + (lane >> 2) + hh * 8;
                if (row < SS) {
                    __half2* dst = (__half2*)(O + (tok0 + row) * DD + col);
                    *dst = __floats2half2_rn(acc[nt][2 * hh], acc[nt][2 * hh + 1]);
                }
            }
        }
    }
}

// ---------------------------------------------------------------------------
// transpose + convert: src f32 [R,C] -> dst f16 [C,R]  (R,C % 32 == 0)
// ---------------------------------------------------------------------------
__global__ void transp_kernel(const float* __restrict__ src,
                              __half* __restrict__ dst,
                              int R, int C, size_t sstride, size_t dstride)
{
    __shared__ float t[32][33];
    src += (size_t)blockIdx.z * sstride;
    dst += (size_t)blockIdx.z * dstride;
    const int c0 = blockIdx.x << 5, r0 = blockIdx.y << 5;
    const int x = threadIdx.x;    // 0..7
    const int y = threadIdx.y;    // 0..31

    float4 v = *(const float4*)(src + (size_t)(r0 + y) * C + c0 + x * 4);
    t[y][x * 4 + 0] = v.x;
    t[y][x * 4 + 1] = v.y;
    t[y][x * 4 + 2] = v.z;
    t[y][x * 4 + 3] = v.w;
    __syncthreads();

    __half2 h01 = __floats2half2_rn(t[x * 4 + 0][y], t[x * 4 + 1][y]);
    __half2 h23 = __floats2half2_rn(t[x * 4 + 2][y], t[x * 4 + 3][y]);
    uint2 hv;
    hv.x = *(uint32_t*)&h01;
    hv.y = *(uint32_t*)&h23;
    *(uint2*)(dst + (size_t)(c0 + y) * R + r0 + x * 4) = hv;
}

__global__ void concat_z_kernel(const float* __restrict__ zs,
                                const float* __restrict__ zk,
                                __half* __restrict__ z16)
{
    int i = blockIdx.x * blockDim.x + threadIdx.x;
    if (i >= BB * LAT) return;
    int b = i >> 8, c = i & 255;
    float v = (c < 128) ? zs[b * 128 + c] : zk[b * 128 + (c - 128)];
    z16[i] = __float2half(v);
}

__global__ void concat_bqkv_kernel(const float* __restrict__ bq,
                                   const float* __restrict__ bk,
                                   const float* __restrict__ bv,
                                   float* __restrict__ dst)
{
    int i = blockIdx.x * blockDim.x + threadIdx.x;
    if (i >= LL * 3 * DD) return;
    int l = i / (3 * DD), r = i % (3 * DD), part = r / DD, c = r % DD;
    const float* s = (part == 0) ? bq : (part == 1) ? bk : bv;
    dst[i] = s[l * DD + c];
}

// PE table: pe[s*512+d], bit-identical formula to the reference path.
__global__ void pe_kernel(float* __restrict__ pe)
{
    int s = blockIdx.x;
    int d = threadIdx.x;
    const float c = -9.210340371976184f / (float)DD;
    int de = d & ~1;
    float div = expf((float)de * c);
    float ang = (float)s * div;
    pe[s * DD + d] = (d & 1) ? cosf(ang) : sinf(ang);
}

// ---------------------------------------------------------------------------
// x = LN(x + res16) * g + be, in place; also emit fp16 copy.
// Warp per row, single-pass (sum + sumsq). grid NTOK/8, block 256.
// ---------------------------------------------------------------------------
__global__ void __launch_bounds__(256) ln_kernel(
    float* __restrict__ x, const __half* __restrict__ res,
    const float* __restrict__ g, const float* __restrict__ be,
    __half* __restrict__ x16)
{
    const int wid  = threadIdx.x >> 5;
    const int lane = threadIdx.x & 31;
    const size_t row = (size_t)blockIdx.x * 8 + wid;
    float* xr = x + row * DD;
    const __half* rr = res + row * DD;
    __half* hr = x16 + row * DD;

    float v[16];
    float s = 0.f, q = 0.f;
#pragma unroll
    for (int k = 0; k < 4; k++) {
        float4 xv = ((const float4*)xr)[lane + (k << 5)];
        uint2  rv = ((const uint2*)rr)[lane + (k << 5)];
        __half2 r01 = *(__half2*)&rv.x;
        __half2 r23 = *(__half2*)&rv.y;
        v[4*k+0] = xv.x + __low2float(r01);
        v[4*k+1] = xv.y + __high2float(r01);
        v[4*k+2] = xv.z + __low2float(r23);
        v[4*k+3] = xv.w + __high2float(r23);
#pragma unroll
        for (int j = 0; j < 4; j++) {
            s += v[4*k+j];
            q += v[4*k+j] * v[4*k+j];
        }
    }
#pragma unroll
    for (int o = 16; o > 0; o >>= 1) {
        s += __shfl_xor_sync(0xffffffffu, s, o);
        q += __shfl_xor_sync(0xffffffffu, q, o);
    }
    float mu  = s * (1.f / (float)DD);
    float var = q * (1.f / (float)DD) - mu * mu;
    float rstd = rsqrtf(var + 1e-5f);

#pragma unroll
    for (int k = 0; k < 4; k++) {
        float4 gv = ((const float4*)g)[lane + (k << 5)];
        float4 bv = ((const float4*)be)[lane + (k << 5)];
        float o0 = (v[4*k+0] - mu) * rstd * gv.x + bv.x;
        float o1 = (v[4*k+1] - mu) * rstd * gv.y + bv.y;
        float o2 = (v[4*k+2] - mu) * rstd * gv.z + bv.z;
        float o3 = (v[4*k+3] - mu) * rstd * gv.w + bv.w;
        ((float4*)xr)[lane + (k << 5)] = make_float4(o0, o1, o2, o3);
        __half2 h01 = __floats2half2_rn(o0, o1);
        __half2 h23 = __floats2half2_rn(o2, o3);
        uint2 hv;
        hv.x = *(uint32_t*)&h01;
        hv.y = *(uint32_t*)&h23;
        ((uint2*)hr)[lane + (k << 5)] = hv;
    }
}

// ---------------------------------------------------------------------------
// Head projection: out[M,N] = A[M,256] @ W[256,N] + bias, N<=6.
// Warp per row; lane covers 8 K-elements; warp-reduce each output.
// ---------------------------------------------------------------------------
template <int N>
__global__ void __launch_bounds__(256) head_kernel(
    const float* __restrict__ A, const float* __restrict__ W,
    const float* __restrict__ bias, float* __restrict__ out, int M)
{
    __shared__ float ws[N * 256];
    for (int i = threadIdx.x; i < N * 256; i += 256) {
        int n = i >> 8, k = i & 255;
        ws[i] = W[k * N + n];
    }
    __syncthreads();

    const int wid  = threadIdx.x >> 5;
    const int lane = threadIdx.x & 31;
    const int m = blockIdx.x * 8 + wid;
    if (m >= M) return;

    const float4* a4 = (const float4*)(A + (size_t)m * 256);
    float4 v0 = a4[lane];
    float4 v1 = a4[lane + 32];
    const int k0 = lane * 4;
    const int k1 = 128 + lane * 4;

    float acc[N];
#pragma unroll
    for (int n = 0; n < N; n++) {
        const float* w = ws + n * 256;
        acc[n] = v0.x * w[k0] + v0.y * w[k0 + 1] + v0.z * w[k0 + 2] + v0.w * w[k0 + 3]
               + v1.x * w[k1] + v1.y * w[k1 + 1] + v1.z * w[k1 + 2] + v1.w * w[k1 + 3];
    }
#pragma unroll
    for (int n = 0; n < N; n++)
#pragma unroll
        for (int o = 16; o > 0; o >>= 1)
            acc[n] += __shfl_xor_sync(0xffffffffu, acc[n], o);

    if (lane < N)
        out[(size_t)m * N + lane] = acc[lane] + bias[lane];
}

// ---------------------------------------------------------------------------
// Host launcher
// ---------------------------------------------------------------------------
extern "C" void kernel_launch(void* const* d_in, const int* in_sizes, int n_in,
                              void* d_out, int out_size)
{
    const float* z_style   = (const float*)d_in[0];
    const float* z_skill   = (const float*)d_in[1];
    const float* W_lat     = (const float*)d_in[2];
    const float* b_lat     = (const float*)d_in[3];
    const float* temp_bias = (const float*)d_in[4];
    const float* Wq  = (const float*)d_in[5];
    const float* bq  = (const float*)d_in[6];
    const float* Wk  = (const float*)d_in[7];
    const float* bk  = (const float*)d_in[8];
    const float* Wv  = (const float*)d_in[9];
    const float* bv  = (const float*)d_in[10];
    const float* Wo  = (const float*)d_in[11];
    const float* bo  = (const float*)d_in[12];
    const float* g1  = (const float*)d_in[13];
    const float* be1 = (const float*)d_in[14];
    const float* g2  = (const float*)d_in[15];
    const float* be2 = (const float*)d_in[16];
    const float* W1  = (const float*)d_in[17];
    const float* bf1 = (const float*)d_in[18];
    const float* W2  = (const float*)d_in[19];
    const float* bf2 = (const float*)d_in[20];
    const float* Wp1 = (const float*)d_in[21];
    const float* bp1 = (const float*)d_in[22];
    const float* Wp2 = (const float*)d_in[23];
    const float* bp2 = (const float*)d_in[24];
    const float* Ws1 = (const float*)d_in[25];
    const float* bs1 = (const float*)d_in[26];
    const float* Ws2 = (const float*)d_in[27];
    const float* bs2 = (const float*)d_in[28];
    float* out = (float*)d_out;

    float *x, *t1, *s1, *bqkv, *pe;
    __half *z16, *x16, *qkv16, *ctx16, *h116, *tmp16;
    __half *wqkvT, *woT, *w1T, *w2T, *wlatT, *wp1T, *ws1T;
    cudaGetSymbolAddress((void**)&x,     g_x);
    cudaGetSymbolAddress((void**)&t1,    g_t1);
    cudaGetSymbolAddress((void**)&s1,    g_s1);
    cudaGetSymbolAddress((void**)&bqkv,  g_bqkv);
    cudaGetSymbolAddress((void**)&pe,    g_pe);
    cudaGetSymbolAddress((void**)&z16,   g_z16);
    cudaGetSymbolAddress((void**)&x16,   g_x16);
    cudaGetSymbolAddress((void**)&qkv16, g_qkv16);
    cudaGetSymbolAddress((void**)&ctx16, g_ctx16);
    cudaGetSymbolAddress((void**)&h116,  g_h116);
    cudaGetSymbolAddress((void**)&tmp16, g_tmp16);
    cudaGetSymbolAddress((void**)&wqkvT, g_wqkvT);
    cudaGetSymbolAddress((void**)&woT,   g_woT);
    cudaGetSymbolAddress((void**)&w1T,   g_w1T);
    cudaGetSymbolAddress((void**)&w2T,   g_w2T);
    cudaGetSymbolAddress((void**)&wlatT, g_wlatT);
    cudaGetSymbolAddress((void**)&wp1T,  g_wp1T);
    cudaGetSymbolAddress((void**)&ws1T,  g_ws1T);

    cudaFuncSetAttribute(hgemm_kernel<0,1>, cudaFuncAttributeMaxDynamicSharedMemorySize, GSMEM);
    cudaFuncSetAttribute(hgemm_kernel<0,2>, cudaFuncAttributeMaxDynamicSharedMemorySize, GSMEM);
    cudaFuncSetAttribute(hgemm_kernel<1,1>, cudaFuncAttributeMaxDynamicSharedMemorySize, GSMEM);
    cudaFuncSetAttribute(hgemm_kernel<1,2>, cudaFuncAttributeMaxDynamicSharedMemorySize, GSMEM);
    cudaFuncSetAttribute(hgemm_kernel<2,3>, cudaFuncAttributeMaxDynamicSharedMemorySize, GSMEM);
    cudaFuncSetAttribute(attn_mma_kernel, cudaFuncAttributeMaxDynamicSharedMemorySize, ASMEM);

    const dim3 tb(8, 32);

    pe_kernel<<<SS, DD>>>(pe);
    transp_kernel<<<dim3((DD*SS)/32, LAT/32, 1), tb>>>(W_lat, wlatT, LAT, DD*SS, 0, 0);
    concat_z_kernel<<<(BB * LAT + 255) / 256, 256>>>(z_style, z_skill, z16);

    // latent GEMM: x = gelu(z @ W_lat + b_lat) + PE
    hgemm_kernel<2,3><<<dim3((DD*SS)/128, 1), 256, GSMEM>>>(
        BB, DD*SS, LAT, z16, wlatT, b_lat, x, x16, pe);

    transp_kernel<<<dim3(16, 16, LL), tb>>>(Wq, wqkvT,                   DD, DD, (size_t)DD*DD, (size_t)3*DD*DD);
    transp_kernel<<<dim3(16, 16, LL), tb>>>(Wk, wqkvT + (size_t)DD*DD,   DD, DD, (size_t)DD*DD, (size_t)3*DD*DD);
    transp_kernel<<<dim3(16, 16, LL), tb>>>(Wv, wqkvT + (size_t)2*DD*DD, DD, DD, (size_t)DD*DD, (size_t)3*DD*DD);
    transp_kernel<<<dim3(16, 16, LL), tb>>>(Wo, woT,  DD, DD,  (size_t)DD*DD,  (size_t)DD*DD);
    transp_kernel<<<dim3(64, 16, LL), tb>>>(W1, w1T,  DD, DFF, (size_t)DD*DFF, (size_t)DFF*DD);
    transp_kernel<<<dim3(16, 64, LL), tb>>>(W2, w2T,  DFF, DD, (size_t)DFF*DD, (size_t)DD*DFF);
    transp_kernel<<<dim3((DD/2)/32, DD/32, 1),  tb>>>(Wp1, wp1T, DD, DD/2, 0, 0);
    transp_kernel<<<dim3((DD/2)/32, LAT/32, 1), tb>>>(Ws1, ws1T, LAT, DD/2, 0, 0);
    concat_bqkv_kernel<<<(LL * 3 * DD + 255) / 256, 256>>>(bq, bk, bv, bqkv);

    for (int l = 0; l < LL; l++) {
        const __half* wqkv_l = wqkvT + (size_t)l * 3 * DD * DD;
        const __half* wo_l   = woT   + (size_t)l * DD * DD;
        const __half* w1_l   = w1T   + (size_t)l * DFF * DD;
        const __half* w2_l   = w2T   + (size_t)l * DD * DFF;

        hgemm_kernel<0,2><<<dim3(12, NTOK/128), 256, GSMEM>>>(
            NTOK, 3*DD, DD, x16, wqkv_l, bqkv + (size_t)l*3*DD, nullptr, qkv16, nullptr);

        attn_mma_kernel<<<dim3(4, HH, BB), 256, ASMEM>>>(qkv16, temp_bias, ctx16);

        hgemm_kernel<0,2><<<dim3(4, NTOK/128), 256, GSMEM>>>(
            NTOK, DD, DD, ctx16, wo_l, bo + (size_t)l*DD, nullptr, tmp16, nullptr);
        ln_kernel<<<NTOK/8, 256>>>(x, tmp16, g1 + l*DD, be1 + l*DD, x16);

        hgemm_kernel<1,2><<<dim3(16, NTOK/128), 256, GSMEM>>>(
            NTOK, DFF, DD, x16, w1_l, bf1 + (size_t)l*DFF, nullptr, h116, nullptr);
        hgemm_kernel<0,2><<<dim3(4, NTOK/128), 256, GSMEM>>>(
            NTOK, DD, DFF, h116, w2_l, bf2 + (size_t)l*DD, nullptr, tmp16, nullptr);
        ln_kernel<<<NTOK/8, 256>>>(x, tmp16, g2 + l*DD, be2 + l*DD, x16);
    }

    hgemm_kernel<1,1><<<dim3((DD/2)/128, NTOK/128), 256, GSMEM>>>(
        NTOK, DD/2, DD, x16, wp1T, bp1, t1, nullptr, nullptr);
    head_kernel<OUTD><<<(NTOK + 7) / 8, 256>>>(
        t1, Wp2, bp2, out, NTOK);

    hgemm_kernel<1,1><<<dim3((DD/2)/128, 1), 256, GSMEM>>>(
        BB, DD/2, LAT, z16, ws1T, bs1, s1, nullptr, nullptr);
    head_kernel<5><<<(BB + 7) / 8, 256>>>(
        s1, Ws2, bs2, out + (size_t)NTOK * OUTD, BB);
}

// round 15
// speedup vs baseline: 1.1802x; 1.0334x over previous
#include <cuda_runtime.h>
#include <cuda_fp16.h>
#include <cstdint>
#include <cstddef>

// ---------------------------------------------------------------------------
// Problem constants
// ---------------------------------------------------------------------------
#define BB   128
#define DD   512
#define HH   8
#define LL   6
#define SS   200
#define LAT  256
#define OUTD 6
#define DKH  64
#define DFF  2048
#define NTOK (BB*SS)   // 25600

// ---------------------------------------------------------------------------
// Device scratch
// ---------------------------------------------------------------------------
__device__ __align__(256) float  g_t1  [NTOK*(DD/2)];
__device__ __align__(256) float  g_s1  [BB*(DD/2)];
__device__ __align__(256) float  g_bqkv[LL*3*DD];
__device__ __align__(256) float  g_pe  [SS*DD];

__device__ __align__(256) __half g_z16  [BB*LAT];
__device__ __align__(256) __half g_x16  [NTOK*DD];
__device__ __align__(256) __half g_qkv16[NTOK*3*DD];
__device__ __align__(256) __half g_ctx16[NTOK*DD];
__device__ __align__(256) __half g_h116 [NTOK*DFF];
__device__ __align__(256) __half g_tmp16[NTOK*DD];

__device__ __align__(256) __half g_wqkvT[LL*3*DD*DD];
__device__ __align__(256) __half g_woT  [LL*DD*DD];
__device__ __align__(256) __half g_w1T  [LL*DFF*DD];
__device__ __align__(256) __half g_w2T  [LL*DD*DFF];
__device__ __align__(256) __half g_wlatT[(size_t)(DD*SS)*LAT];
__device__ __align__(256) __half g_wp1T [(DD/2)*DD];
__device__ __align__(256) __half g_ws1T [(DD/2)*LAT];

// ---------------------------------------------------------------------------
// Helpers
// ---------------------------------------------------------------------------
__device__ __forceinline__ uint32_t smem_u32(const void* p) {
    uint32_t a;
    asm("{ .reg .u64 t; cvta.to.shared.u64 t, %1; cvt.u32.u64 %0, t; }"
        : "=r"(a) : "l"(p));
    return a;
}
__device__ __forceinline__ float gelu_f(float x) {
    return 0.5f * x * (1.0f + erff(x * 0.7071067811865475f));
}

#define LDMATRIX_X4(r0, r1, r2, r3, addr)                                     \
    asm volatile("ldmatrix.sync.aligned.m8n8.x4.shared.b16 "                  \
                 "{%0, %1, %2, %3}, [%4];"                                    \
                 : "=r"(r0), "=r"(r1), "=r"(r2), "=r"(r3) : "r"(addr))

#define LDMATRIX_X4_T(r0, r1, r2, r3, addr)                                   \
    asm volatile("ldmatrix.sync.aligned.m8n8.x4.trans.shared.b16 "            \
                 "{%0, %1, %2, %3}, [%4];"                                    \
                 : "=r"(r0), "=r"(r1), "=r"(r2), "=r"(r3) : "r"(addr))

#define MMA16816(c, a, b)                                                     \
    asm volatile("mma.sync.aligned.m16n8k16.row.col.f32.f16.f16.f32 "         \
                 "{%0, %1, %2, %3}, {%4, %5, %6, %7}, {%8, %9}, "             \
                 "{%0, %1, %2, %3};"                                          \
                 : "+f"((c)[0]), "+f"((c)[1]), "+f"((c)[2]), "+f"((c)[3])     \
                 : "r"((a)[0]), "r"((a)[1]), "r"((a)[2]), "r"((a)[3]),        \
                   "r"((b)[0]), "r"((b)[1]))

// swizzled byte offset inside a 128x64h (128B-row) tile
__device__ __forceinline__ uint32_t swz(int row, int colb) {
    return (uint32_t)(row * 128 + (colb ^ ((row & 7) << 4)));
}

// ---------------------------------------------------------------------------
// fp16 tensor-core GEMM (mma.sync):  C[M,N] = act(A[M,K] @ Bt[N,K]^T + bias)
//   CTA tile 128x128, warp tile 64x32 (8 warps, 2x4). 3-stage cp.async
//   pipeline (2 in flight), swizzled smem, ONE barrier per stage.
//   Hoisted LDSM addressing (swizzle mask invariant under row+=16k).
//   grid = (N/128, M/128), block = 256.
//   OM bit0: fp32 C; bit1: fp16 C16.  ACT: 0 none, 1 gelu, 2 gelu + pe[col].
// ---------------------------------------------------------------------------
#define TBUF  16384
#define GSMEM (6*TBUF)

template <int ACT, int OM>
__global__ void __launch_bounds__(256, 2)
hgemm_kernel(int M, int N, int K,
             const __half* __restrict__ A, const __half* __restrict__ Bt,
             const float* __restrict__ bias,
             float* __restrict__ C, __half* __restrict__ C16,
             const float* __restrict__ pe)
{
    extern __shared__ char smem[];
    const uint32_t sb = smem_u32(smem);
    const int tid  = threadIdx.x;
    const int wid  = tid >> 5;
    const int lane = tid & 31;
    const int wm   = wid >> 2;
    const int wn   = wid & 3;

    const size_t n0 = (size_t)blockIdx.x * 128;
    const size_t m0 = (size_t)blockIdx.y * 128;
    const __half* Ab = A  + m0 * (size_t)K;
    const __half* Bb = Bt + n0 * (size_t)K;
    const int NS = K >> 6;

    const int ldr  = tid >> 3;
    const int ldcb = (tid & 7) << 4;

    auto load_stage = [&](int s) {
        const uint32_t st  = (uint32_t)(s % 3);
        const uint32_t sa  = sb + st * TBUF;
        const uint32_t sbb = sb + 3 * TBUF + st * TBUF;
        const int k0 = s << 6;
#pragma unroll
        for (int i = 0; i < 4; i++) {
            int r = ldr + (i << 5);
            uint32_t off = swz(r, ldcb);
            const void* ag = Ab + (size_t)r * K + k0 + (ldcb >> 1);
            asm volatile("cp.async.cg.shared.global [%0], [%1], 16;"
                         :: "r"(sa + off), "l"(ag) : "memory");
            const void* bg = Bb + (size_t)r * K + k0 + (ldcb >> 1);
            asm volatile("cp.async.cg.shared.global [%0], [%1], 16;"
                         :: "r"(sbb + off), "l"(bg) : "memory");
        }
        asm volatile("cp.async.commit_group;" ::: "memory");
    };

    load_stage(0);
    load_stage(1);

    float acc[4][4][4];
#pragma unroll
    for (int i = 0; i < 4; i++)
#pragma unroll
        for (int j = 0; j < 4; j++)
#pragma unroll
            for (int kq = 0; kq < 4; kq++) acc[i][j][kq] = 0.f;

    const int a_row = wm * 64 + (lane & 15);
    const int a_kob = (lane >> 4) << 4;
    const int b_row = wn * 32 + (lane & 7) + ((lane >> 4) << 3);
    const int b_kob = ((lane >> 3) & 1) << 4;

    const uint32_t a_msk = (uint32_t)((a_row & 7) << 4);
    const uint32_t b_msk = (uint32_t)((b_row & 7) << 4);
    uint32_t a_off[4], b_off[4];
#pragma unroll
    for (int ks = 0; ks < 4; ks++) {
        a_off[ks] = (uint32_t)(a_row * 128) +
                    ((uint32_t)(ks * 32 + a_kob) ^ a_msk);
        b_off[ks] = (uint32_t)(b_row * 128) +
                    ((uint32_t)(ks * 32 + b_kob) ^ b_msk);
    }

    for (int s = 0; s < NS; s++) {
        if (s + 1 < NS) asm volatile("cp.async.wait_group 1;" ::: "memory");
        else            asm volatile("cp.async.wait_group 0;" ::: "memory");
        __syncthreads();

        if (s + 2 < NS) load_stage(s + 2);

        const uint32_t st  = (uint32_t)(s % 3);
        const uint32_t sa  = sb + st * TBUF;
        const uint32_t sbb = sb + 3 * TBUF + st * TBUF;

#pragma unroll
        for (int ks = 0; ks < 4; ks++) {
            const uint32_t abase = sa  + a_off[ks];
            const uint32_t bbase = sbb + b_off[ks];
            uint32_t af[4][4];
#pragma unroll
            for (int mt = 0; mt < 4; mt++) {
                LDMATRIX_X4(af[mt][0], af[mt][1], af[mt][2], af[mt][3],
                            abase + (uint32_t)(mt * 2048));
            }
            uint32_t bf[4][2];
#pragma unroll
            for (int nt2 = 0; nt2 < 2; nt2++) {
                LDMATRIX_X4(bf[2*nt2][0], bf[2*nt2][1],
                            bf[2*nt2+1][0], bf[2*nt2+1][1],
                            bbase + (uint32_t)(nt2 * 2048));
            }
#pragma unroll
            for (int mt = 0; mt < 4; mt++)
#pragma unroll
                for (int nt = 0; nt < 4; nt++)
                    MMA16816(acc[mt][nt], af[mt], bf[nt]);
        }
    }

    // --- epilogue ---
#pragma unroll
    for (int mt = 0; mt < 4; mt++) {
#pragma unroll
        for (int nt = 0; nt < 4; nt++) {
            const size_t col = n0 + wn * 32 + nt * 8 + (lane & 3) * 2;
            const float b0 = bias[col], b1 = bias[col + 1];
            float p0 = 0.f, p1 = 0.f;
            if (ACT == 2) { p0 = pe[col]; p1 = pe[col + 1]; }
#pragma unroll
            for (int hh = 0; hh < 2; hh++) {
                const size_t row = m0 + wm * 64 + mt * 16 + (lane >> 2) + hh * 8;
                float v0 = acc[mt][nt][2*hh]   + b0;
                float v1 = acc[mt][nt][2*hh+1] + b1;
                if (ACT >= 1) { v0 = gelu_f(v0); v1 = gelu_f(v1); }
                if (ACT == 2) { v0 += p0; v1 += p1; }
                if (OM & 1) {
                    float2* dst = (float2*)(C + row * (size_t)N + col);
                    *dst = make_float2(v0, v1);
                }
                if (OM & 2) {
                    __half2* dst = (__half2*)(C16 + row * (size_t)N + col);
                    *dst = __floats2half2_rn(v0, v1);
                }
            }
        }
    }
}

// ---------------------------------------------------------------------------
// Tensor-core attention. grid = (4, H, B); block = 256 (8 warps).
// ---------------------------------------------------------------------------
#define KVST 72
#define PST  232
#define AK_OFF 0
#define AV_OFF 32256
#define AS_OFF 64512
#define ASMEM  94208

__global__ void __launch_bounds__(256, 2)
attn_mma_kernel(const __half* __restrict__ QKV, const float* __restrict__ bias,
                __half* __restrict__ O)
{
    extern __shared__ char smem[];
    const uint32_t sb = smem_u32(smem);
    const int it  = blockIdx.x;
    const int h   = blockIdx.y;
    const int b   = blockIdx.z;
    const int tid = threadIdx.x;
    const int wid = tid >> 5, lane = tid & 31;
    const int i0  = it * 64;
    const size_t tok0 = (size_t)b * SS;
    const int hoff = h * DKH;

    for (int p = tid; p < 224 * 8; p += 256) {
        int j = p >> 3, c = (p & 7) << 3;
        uint4 kv = make_uint4(0, 0, 0, 0), vv = make_uint4(0, 0, 0, 0);
        if (j < SS) {
            kv = *(const uint4*)(QKV + (tok0 + j) * 1536 + 512 + hoff + c);
            vv = *(const uint4*)(QKV + (tok0 + j) * 1536 + 1024 + hoff + c);
        }
        *(uint4*)(smem + AK_OFF + j * (KVST * 2) + c * 2) = kv;
        *(uint4*)(smem + AV_OFF + j * (KVST * 2) + c * 2) = vv;
    }
    __syncthreads();

    // ---- scores = QK^T / 8 -> fp16 buffer ----
    {
        const int wm = wid & 3;
        const int wn = wid >> 2;
        uint32_t aq[4][4];
        {
            const int r_lo = i0 + wm * 16 + (lane >> 2);
            const int r_hi = r_lo + 8;
            const int h2   = lane & 3;
#pragma unroll
            for (int ks = 0; ks < 4; ks++) {
                uint32_t v0 = 0, v1 = 0, v2 = 0, v3 = 0;
                if (r_lo < SS) {
                    const uint32_t* p =
                        (const uint32_t*)(QKV + (tok0 + r_lo) * 1536 + hoff);
                    v0 = p[8 * ks + h2];
                    v2 = p[8 * ks + 4 + h2];
                }
                if (r_hi < SS) {
                    const uint32_t* p =
                        (const uint32_t*)(QKV + (tok0 + r_hi) * 1536 + hoff);
                    v1 = p[8 * ks + h2];
                    v3 = p[8 * ks + 4 + h2];
                }
                aq[ks][0] = v0; aq[ks][1] = v1; aq[ks][2] = v2; aq[ks][3] = v3;
            }
        }
        const int brow = (lane & 7) + ((lane >> 4) << 3);
        const int bkof = ((lane >> 3) & 1) << 3;
        float acc[7][2][4];
#pragma unroll
        for (int g = 0; g < 7; g++)
#pragma unroll
            for (int q = 0; q < 2; q++)
#pragma unroll
                for (int r = 0; r < 4; r++) acc[g][q][r] = 0.f;

#pragma unroll
        for (int ks = 0; ks < 4; ks++) {
#pragma unroll
            for (int g = 0; g < 7; g++) {
                int ncol = wn * 112 + g * 16;
                uint32_t baddr = sb + AK_OFF +
                    (uint32_t)((ncol + brow) * (KVST * 2) + (ks * 16 + bkof) * 2);
                uint32_t b0, b1, b2, b3;
                LDMATRIX_X4(b0, b1, b2, b3, baddr);
                uint32_t bf0[2] = {b0, b1}, bf1[2] = {b2, b3};
                MMA16816(acc[g][0], aq[ks], bf0);
                MMA16816(acc[g][1], aq[ks], bf1);
            }
        }
        __half* ps = (__half*)(smem + AS_OFF);
        const int r0 = wm * 16 + (lane >> 2);
#pragma unroll
        for (int g = 0; g < 7; g++)
#pragma unroll
            for (int q = 0; q < 2; q++) {
                int col = wn * 112 + g * 16 + q * 8 + (lane & 3) * 2;
                *(__half2*)&ps[r0 * PST + col] =
                    __floats2half2_rn(acc[g][q][0] * 0.125f, acc[g][q][1] * 0.125f);
                *(__half2*)&ps[(r0 + 8) * PST + col] =
                    __floats2half2_rn(acc[g][q][2] * 0.125f, acc[g][q][3] * 0.125f);
            }
    }
    __syncthreads();

    // ---- softmax (+bias), in place fp16 -> P ----
    {
        __half* ps = (__half*)(smem + AS_OFF);
        for (int i = wid; i < 64; i += 8) {
            int gi = i0 + i;
            if (gi < SS) {
                const float* brow = bias + ((size_t)h * SS + gi) * SS;
                float vals[7];
                float m = -1e30f;
#pragma unroll
                for (int t = 0; t < 7; t++) {
                    int j = lane + t * 32;
                    float s = -1e30f;
                    if (j < SS) s = __half2float(ps[i * PST + j]) + brow[j];
                    vals[t] = s;
                    m = fmaxf(m, s);
                }
#pragma unroll
                for (int o = 16; o > 0; o >>= 1)
                    m = fmaxf(m, __shfl_xor_sync(0xffffffffu, m, o));
                float sum = 0.f;
#pragma unroll
                for (int t = 0; t < 7; t++) {
                    int j = lane + t * 32;
                    float e = (j < SS) ? expf(vals[t] - m) : 0.f;
                    vals[t] = e;
                    sum += e;
                }
#pragma unroll
                for (int o = 16; o > 0; o >>= 1)
                    sum += __shfl_xor_sync(0xffffffffu, sum, o);
                float inv = 1.f / sum;
#pragma unroll
                for (int t = 0; t < 7; t++)
                    ps[i * PST + lane + t * 32] = __float2half(vals[t] * inv);
            } else {
#pragma unroll
                for (int t = 0; t < 7; t++)
                    ps[i * PST + lane + t * 32] = __float2half(0.f);
            }
        }
    }
    __syncthreads();

    // ---- ctx = P @ V ----
    {
        const int wm = wid & 3;
        const int wn = wid >> 2;
        const int arow = wm * 16 + (lane & 15);
        const int akof = (lane >> 4) << 3;
        const int vrow = lane & 15;
        const int vcol = (lane >> 4) << 3;
        float acc[4][4];
#pragma unroll
        for (int i = 0; i < 4; i++)
#pragma unroll
            for (int j = 0; j < 4; j++) acc[i][j] = 0.f;

#pragma unroll
        for (int ks = 0; ks < 14; ks++) {
            uint32_t a[4];
            uint32_t aaddr = sb + AS_OFF +
                (uint32_t)(arow * (PST * 2) + (ks * 16 + akof) * 2);
            LDMATRIX_X4(a[0], a[1], a[2], a[3], aaddr);
#pragma unroll
            for (int g = 0; g < 2; g++) {
                int n0c = wn * 32 + g * 16;
                uint32_t baddr = sb + AV_OFF +
                    (uint32_t)((ks * 16 + vrow) * (KVST * 2) + (n0c + vcol) * 2);
                uint32_t b0, b1, b2, b3;
                LDMATRIX_X4_T(b0, b1, b2, b3, baddr);
                uint32_t bf0[2] = {b0, b1}, bf1[2] = {b2, b3};
                MMA16816(acc[g * 2 + 0], a, bf0);
                MMA16816(acc[g * 2 + 1], a, bf1);
            }
        }
#pragma unroll
        for (int nt = 0; nt < 4; nt++) {
            int col = hoff + wn * 32 + nt * 8 + (lane & 3) * 2;
#pragma unroll
            for (int hh = 0; hh < 2; hh++) {
                int row = i0 + wm * 16 + (lane >> 2) + hh * 8;
                if (row < SS) {
                    __half2* dst = (__half2*)(O + (tok0 + row) * DD + col);
                    *dst = __floats2half2_rn(acc[nt][2 * hh], acc[nt][2 * hh + 1]);
                }
            }
        }
    }
}

// ---------------------------------------------------------------------------
// transpose + convert: src f32 [R,C] -> dst f16 [C,R]  (R,C % 32 == 0)
// ---------------------------------------------------------------------------
__global__ void transp_kernel(const float* __restrict__ src,
                              __half* __restrict__ dst,
                              int R, int C, size_t sstride, size_t dstride)
{
    __shared__ float t[32][33];
    src += (size_t)blockIdx.z * sstride;
    dst += (size_t)blockIdx.z * dstride;
    const int c0 = blockIdx.x << 5, r0 = blockIdx.y << 5;
    const int x = threadIdx.x;    // 0..7
    const int y = threadIdx.y;    // 0..31

    float4 v = *(const float4*)(src + (size_t)(r0 + y) * C + c0 + x * 4);
    t[y][x * 4 + 0] = v.x;
    t[y][x * 4 + 1] = v.y;
    t[y][x * 4 + 2] = v.z;
    t[y][x * 4 + 3] = v.w;
    __syncthreads();

    __half2 h01 = __floats2half2_rn(t[x * 4 + 0][y], t[x * 4 + 1][y]);
    __half2 h23 = __floats2half2_rn(t[x * 4 + 2][y], t[x * 4 + 3][y]);
    uint2 hv;
    hv.x = *(uint32_t*)&h01;
    hv.y = *(uint32_t*)&h23;
    *(uint2*)(dst + (size_t)(c0 + y) * R + r0 + x * 4) = hv;
}

__global__ void concat_z_kernel(const float* __restrict__ zs,
                                const float* __restrict__ zk,
                                __half* __restrict__ z16)
{
    int i = blockIdx.x * blockDim.x + threadIdx.x;
    if (i >= BB * LAT) return;
    int b = i >> 8, c = i & 255;
    float v = (c < 128) ? zs[b * 128 + c] : zk[b * 128 + (c - 128)];
    z16[i] = __float2half(v);
}

__global__ void concat_bqkv_kernel(const float* __restrict__ bq,
                                   const float* __restrict__ bk,
                                   const float* __restrict__ bv,
                                   float* __restrict__ dst)
{
    int i = blockIdx.x * blockDim.x + threadIdx.x;
    if (i >= LL * 3 * DD) return;
    int l = i / (3 * DD), r = i % (3 * DD), part = r / DD, c = r % DD;
    const float* s = (part == 0) ? bq : (part == 1) ? bk : bv;
    dst[i] = s[l * DD + c];
}

// PE table: pe[s*512+d], bit-identical formula to the reference path.
__global__ void pe_kernel(float* __restrict__ pe)
{
    int s = blockIdx.x;
    int d = threadIdx.x;
    const float c = -9.210340371976184f / (float)DD;
    int de = d & ~1;
    float div = expf((float)de * c);
    float ang = (float)s * div;
    pe[s * DD + d] = (d & 1) ? cosf(ang) : sinf(ang);
}

// ---------------------------------------------------------------------------
// x16 = LN(x16 + res16) * g + be, in place on fp16 residual stream.
// Warp per row, single-pass (sum + sumsq), fp32 math. grid NTOK/8, block 256.
// ---------------------------------------------------------------------------
__global__ void __launch_bounds__(256) ln_kernel(
    __half* __restrict__ x16, const __half* __restrict__ res,
    const float* __restrict__ g, const float* __restrict__ be)
{
    const int wid  = threadIdx.x >> 5;
    const int lane = threadIdx.x & 31;
    const size_t row = (size_t)blockIdx.x * 8 + wid;
    __half* xr = x16 + row * DD;
    const __half* rr = res + row * DD;

    float v[16];
    float s = 0.f, q = 0.f;
#pragma unroll
    for (int k = 0; k < 4; k++) {
        uint2 xv = ((const uint2*)xr)[lane + (k << 5)];
        uint2 rv = ((const uint2*)rr)[lane + (k << 5)];
        __half2 x01 = *(__half2*)&xv.x;
        __half2 x23 = *(__half2*)&xv.y;
        __half2 r01 = *(__half2*)&rv.x;
        __half2 r23 = *(__half2*)&rv.y;
        v[4*k+0] = __low2float(x01)  + __low2float(r01);
        v[4*k+1] = __high2float(x01) + __high2float(r01);
        v[4*k+2] = __low2float(x23)  + __low2float(r23);
        v[4*k+3] = __high2float(x23) + __high2float(r23);
#pragma unroll
        for (int j = 0; j < 4; j++) {
            s += v[4*k+j];
            q += v[4*k+j] * v[4*k+j];
        }
    }
#pragma unroll
    for (int o = 16; o > 0; o >>= 1) {
        s += __shfl_xor_sync(0xffffffffu, s, o);
        q += __shfl_xor_sync(0xffffffffu, q, o);
    }
    float mu  = s * (1.f / (float)DD);
    float var = q * (1.f / (float)DD) - mu * mu;
    float rstd = rsqrtf(var + 1e-5f);

#pragma unroll
    for (int k = 0; k < 4; k++) {
        float4 gv = ((const float4*)g)[lane + (k << 5)];
        float4 bv = ((const float4*)be)[lane + (k << 5)];
        float o0 = (v[4*k+0] - mu) * rstd * gv.x + bv.x;
        float o1 = (v[4*k+1] - mu) * rstd * gv.y + bv.y;
        float o2 = (v[4*k+2] - mu) * rstd * gv.z + bv.z;
        float o3 = (v[4*k+3] - mu) * rstd * gv.w + bv.w;
        __half2 h01 = __floats2half2_rn(o0, o1);
        __half2 h23 = __floats2half2_rn(o2, o3);
        uint2 hv;
        hv.x = *(uint32_t*)&h01;
        hv.y = *(uint32_t*)&h23;
        ((uint2*)xr)[lane + (k << 5)] = hv;
    }
}

// ---------------------------------------------------------------------------
// Head projection: out[M,N] = A[M,256] @ W[256,N] + bias, N<=6.
// Warp per row; lane covers 8 K-elements; warp-reduce each output.
// ---------------------------------------------------------------------------
template <int N>
__global__ void __launch_bounds__(256) head_kernel(
    const float* __restrict__ A, const float* __restrict__ W,
    const float* __restrict__ bias, float* __restrict__ out, int M)
{
    __shared__ float ws[N * 256];
    for (int i = threadIdx.x; i < N * 256; i += 256) {
        int n = i >> 8, k = i & 255;
        ws[i] = W[k * N + n];
    }
    __syncthreads();

    const int wid  = threadIdx.x >> 5;
    const int lane = threadIdx.x & 31;
    const int m = blockIdx.x * 8 + wid;
    if (m >= M) return;

    const float4* a4 = (const float4*)(A + (size_t)m * 256);
    float4 v0 = a4[lane];
    float4 v1 = a4[lane + 32];
    const int k0 = lane * 4;
    const int k1 = 128 + lane * 4;

    float acc[N];
#pragma unroll
    for (int n = 0; n < N; n++) {
        const float* w = ws + n * 256;
        acc[n] = v0.x * w[k0] + v0.y * w[k0 + 1] + v0.z * w[k0 + 2] + v0.w * w[k0 + 3]
               + v1.x * w[k1] + v1.y * w[k1 + 1] + v1.z * w[k1 + 2] + v1.w * w[k1 + 3];
    }
#pragma unroll
    for (int n = 0; n < N; n++)
#pragma unroll
        for (int o = 16; o > 0; o >>= 1)
            acc[n] += __shfl_xor_sync(0xffffffffu, acc[n], o);

    if (lane < N)
        out[(size_t)m * N + lane] = acc[lane] + bias[lane];
}

// ---------------------------------------------------------------------------
// Host launcher
// ---------------------------------------------------------------------------
extern "C" void kernel_launch(void* const* d_in, const int* in_sizes, int n_in,
                              void* d_out, int out_size)
{
    const float* z_style   = (const float*)d_in[0];
    const float* z_skill   = (const float*)d_in[1];
    const float* W_lat     = (const float*)d_in[2];
    const float* b_lat     = (const float*)d_in[3];
    const float* temp_bias = (const float*)d_in[4];
    const float* Wq  = (const float*)d_in[5];
    const float* bq  = (const float*)d_in[6];
    const float* Wk  = (const float*)d_in[7];
    const float* bk  = (const float*)d_in[8];
    const float* Wv  = (const float*)d_in[9];
    const float* bv  = (const float*)d_in[10];
    const float* Wo  = (const float*)d_in[11];
    const float* bo  = (const float*)d_in[12];
    const float* g1  = (const float*)d_in[13];
    const float* be1 = (const float*)d_in[14];
    const float* g2  = (const float*)d_in[15];
    const float* be2 = (const float*)d_in[16];
    const float* W1  = (const float*)d_in[17];
    const float* bf1 = (const float*)d_in[18];
    const float* W2  = (const float*)d_in[19];
    const float* bf2 = (const float*)d_in[20];
    const float* Wp1 = (const float*)d_in[21];
    const float* bp1 = (const float*)d_in[22];
    const float* Wp2 = (const float*)d_in[23];
    const float* bp2 = (const float*)d_in[24];
    const float* Ws1 = (const float*)d_in[25];
    const float* bs1 = (const float*)d_in[26];
    const float* Ws2 = (const float*)d_in[27];
    const float* bs2 = (const float*)d_in[28];
    float* out = (float*)d_out;

    float *t1, *s1, *bqkv, *pe;
    __half *z16, *x16, *qkv16, *ctx16, *h116, *tmp16;
    __half *wqkvT, *woT, *w1T, *w2T, *wlatT, *wp1T, *ws1T;
    cudaGetSymbolAddress((void**)&t1,    g_t1);
    cudaGetSymbolAddress((void**)&s1,    g_s1);
    cudaGetSymbolAddress((void**)&bqkv,  g_bqkv);
    cudaGetSymbolAddress((void**)&pe,    g_pe);
    cudaGetSymbolAddress((void**)&z16,   g_z16);
    cudaGetSymbolAddress((void**)&x16,   g_x16);
    cudaGetSymbolAddress((void**)&qkv16, g_qkv16);
    cudaGetSymbolAddress((void**)&ctx16, g_ctx16);
    cudaGetSymbolAddress((void**)&h116,  g_h116);
    cudaGetSymbolAddress((void**)&tmp16, g_tmp16);
    cudaGetSymbolAddress((void**)&wqkvT, g_wqkvT);
    cudaGetSymbolAddress((void**)&woT,   g_woT);
    cudaGetSymbolAddress((void**)&w1T,   g_w1T);
    cudaGetSymbolAddress((void**)&w2T,   g_w2T);
    cudaGetSymbolAddress((void**)&wlatT, g_wlatT);
    cudaGetSymbolAddress((void**)&wp1T,  g_wp1T);
    cudaGetSymbolAddress((void**)&ws1T,  g_ws1T);

    cudaFuncSetAttribute(hgemm_kernel<0,1>, cudaFuncAttributeMaxDynamicSharedMemorySize, GSMEM);
    cudaFuncSetAttribute(hgemm_kernel<0,2>, cudaFuncAttributeMaxDynamicSharedMemorySize, GSMEM);
    cudaFuncSetAttribute(hgemm_kernel<1,1>, cudaFuncAttributeMaxDynamicSharedMemorySize, GSMEM);
    cudaFuncSetAttribute(hgemm_kernel<1,2>, cudaFuncAttributeMaxDynamicSharedMemorySize, GSMEM);
    cudaFuncSetAttribute(hgemm_kernel<2,2>, cudaFuncAttributeMaxDynamicSharedMemorySize, GSMEM);
    cudaFuncSetAttribute(attn_mma_kernel, cudaFuncAttributeMaxDynamicSharedMemorySize, ASMEM);

    const dim3 tb(8, 32);

    pe_kernel<<<SS, DD>>>(pe);
    transp_kernel<<<dim3((DD*SS)/32, LAT/32, 1), tb>>>(W_lat, wlatT, LAT, DD*SS, 0, 0);
    concat_z_kernel<<<(BB * LAT + 255) / 256, 256>>>(z_style, z_skill, z16);

    // latent GEMM: x16 = gelu(z @ W_lat + b_lat) + PE   (fp16 residual stream)
    hgemm_kernel<2,2><<<dim3((DD*SS)/128, 1), 256, GSMEM>>>(
        BB, DD*SS, LAT, z16, wlatT, b_lat, nullptr, x16, pe);

    transp_kernel<<<dim3(16, 16, LL), tb>>>(Wq, wqkvT,                   DD, DD, (size_t)DD*DD, (size_t)3*DD*DD);
    transp_kernel<<<dim3(16, 16, LL), tb>>>(Wk, wqkvT + (size_t)DD*DD,   DD, DD, (size_t)DD*DD, (size_t)3*DD*DD);
    transp_kernel<<<dim3(16, 16, LL), tb>>>(Wv, wqkvT + (size_t)2*DD*DD, DD, DD, (size_t)DD*DD, (size_t)3*DD*DD);
    transp_kernel<<<dim3(16, 16, LL), tb>>>(Wo, woT,  DD, DD,  (size_t)DD*DD,  (size_t)DD*DD);
    transp_kernel<<<dim3(64, 16, LL), tb>>>(W1, w1T,  DD, DFF, (size_t)DD*DFF, (size_t)DFF*DD);
    transp_kernel<<<dim3(16, 64, LL), tb>>>(W2, w2T,  DFF, DD, (size_t)DFF*DD, (size_t)DD*DFF);
    transp_kernel<<<dim3((DD/2)/32, DD/32, 1),  tb>>>(Wp1, wp1T, DD, DD/2, 0, 0);
    transp_kernel<<<dim3((DD/2)/32, LAT/32, 1), tb>>>(Ws1, ws1T, LAT, DD/2, 0, 0);
    concat_bqkv_kernel<<<(LL * 3 * DD + 255) / 256, 256>>>(bq, bk, bv, bqkv);

    for (int l = 0; l < LL; l++) {
        const __half* wqkv_l = wqkvT + (size_t)l * 3 * DD * DD;
        const __half* wo_l   = woT   + (size_t)l * DD * DD;
        const __half* w1_l   = w1T   + (size_t)l * DFF * DD;
        const __half* w2_l   = w2T   + (size_t)l * DD * DFF;

        hgemm_kernel<0,2><<<dim3(12, NTOK/128), 256, GSMEM>>>(
            NTOK, 3*DD, DD, x16, wqkv_l, bqkv + (size_t)l*3*DD, nullptr, qkv16, nullptr);

        attn_mma_kernel<<<dim3(4, HH, BB), 256, ASMEM>>>(qkv16, temp_bias, ctx16);

        hgemm_kernel<0,2><<<dim3(4, NTOK/128), 256, GSMEM>>>(
            NTOK, DD, DD, ctx16, wo_l, bo + (size_t)l*DD, nullptr, tmp16, nullptr);
        ln_kernel<<<NTOK/8, 256>>>(x16, tmp16, g1 + l*DD, be1 + l*DD);

        hgemm_kernel<1,2><<<dim3(16, NTOK/128), 256, GSMEM>>>(
            NTOK, DFF, DD, x16, w1_l, bf1 + (size_t)l*DFF, nullptr, h116, nullptr);
        hgemm_kernel<0,2><<<dim3(4, NTOK/128), 256, GSMEM>>>(
            NTOK, DD, DFF, h116, w2_l, bf2 + (size_t)l*DD, nullptr, tmp16, nullptr);
        ln_kernel<<<NTOK/8, 256>>>(x16, tmp16, g2 + l*DD, be2 + l*DD);
    }

    hgemm_kernel<1,1><<<dim3((DD/2)/128, NTOK/128), 256, GSMEM>>>(
        NTOK, DD/2, DD, x16, wp1T, bp1, t1, nullptr, nullptr);
    head_kernel<OUTD><<<(NTOK + 7) / 8, 256>>>(
        t1, Wp2, bp2, out, NTOK);

    hgemm_kernel<1,1><<<dim3((DD/2)/128, 1), 256, GSMEM>>>(
        BB, DD/2, LAT, z16, ws1T, bs1, s1, nullptr, nullptr);
    head_kernel<5><<<(BB + 7) / 8, 256>>>(
        s1, Ws2, bs2, out + (size_t)NTOK * OUTD, BB);
}

// round 16
// speedup vs baseline: 1.1845x; 1.0037x over previous
#include <cuda_runtime.h>
#include <cuda_fp16.h>
#include <cstdint>
#include <cstddef>

// ---------------------------------------------------------------------------
// Problem constants
// ---------------------------------------------------------------------------
#define BB   128
#define DD   512
#define HH   8
#define LL   6
#define SS   200
#define LAT  256
#define OUTD 6
#define DKH  64
#define DFF  2048
#define NTOK (BB*SS)   // 25600

// ---------------------------------------------------------------------------
// Device scratch
// ---------------------------------------------------------------------------
__device__ __align__(256) float  g_t1  [NTOK*(DD/2)];
__device__ __align__(256) float  g_s1  [BB*(DD/2)];
__device__ __align__(256) float  g_bqkv[LL*3*DD];
__device__ __align__(256) float  g_pe  [SS*DD];

__device__ __align__(256) __half g_z16  [BB*LAT];
__device__ __align__(256) __half g_x16  [NTOK*DD];
__device__ __align__(256) __half g_qkv16[NTOK*3*DD];
__device__ __align__(256) __half g_ctx16[NTOK*DD];
__device__ __align__(256) __half g_h116 [NTOK*DFF];
__device__ __align__(256) __half g_tmp16[NTOK*DD];

__device__ __align__(256) __half g_wqkvT[LL*3*DD*DD];
__device__ __align__(256) __half g_woT  [LL*DD*DD];
__device__ __align__(256) __half g_w1T  [LL*DFF*DD];
__device__ __align__(256) __half g_w2T  [LL*DD*DFF];
__device__ __align__(256) __half g_wlatT[(size_t)(DD*SS)*LAT];
__device__ __align__(256) __half g_wp1T [(DD/2)*DD];
__device__ __align__(256) __half g_ws1T [(DD/2)*LAT];

// ---------------------------------------------------------------------------
// Helpers
// ---------------------------------------------------------------------------
__device__ __forceinline__ uint32_t smem_u32(const void* p) {
    uint32_t a;
    asm("{ .reg .u64 t; cvta.to.shared.u64 t, %1; cvt.u32.u64 %0, t; }"
        : "=r"(a) : "l"(p));
    return a;
}
__device__ __forceinline__ float gelu_f(float x) {
    return 0.5f * x * (1.0f + erff(x * 0.7071067811865475f));
}

#define LDMATRIX_X4(r0, r1, r2, r3, addr)                                     \
    asm volatile("ldmatrix.sync.aligned.m8n8.x4.shared.b16 "                  \
                 "{%0, %1, %2, %3}, [%4];"                                    \
                 : "=r"(r0), "=r"(r1), "=r"(r2), "=r"(r3) : "r"(addr))

#define LDMATRIX_X4_T(r0, r1, r2, r3, addr)                                   \
    asm volatile("ldmatrix.sync.aligned.m8n8.x4.trans.shared.b16 "            \
                 "{%0, %1, %2, %3}, [%4];"                                    \
                 : "=r"(r0), "=r"(r1), "=r"(r2), "=r"(r3) : "r"(addr))

#define MMA16816(c, a, b)                                                     \
    asm volatile("mma.sync.aligned.m16n8k16.row.col.f32.f16.f16.f32 "         \
                 "{%0, %1, %2, %3}, {%4, %5, %6, %7}, {%8, %9}, "             \
                 "{%0, %1, %2, %3};"                                          \
                 : "+f"((c)[0]), "+f"((c)[1]), "+f"((c)[2]), "+f"((c)[3])     \
                 : "r"((a)[0]), "r"((a)[1]), "r"((a)[2]), "r"((a)[3]),        \
                   "r"((b)[0]), "r"((b)[1]))

// swizzled byte offset inside a 128x64h (128B-row) tile
__device__ __forceinline__ uint32_t swz(int row, int colb) {
    return (uint32_t)(row * 128 + (colb ^ ((row & 7) << 4)));
}

// ---------------------------------------------------------------------------
// fp16 tensor-core GEMM (mma.sync):  C[M,N] = act(A[M,K] @ Bt[N,K]^T + bias)
//   CTA tile 128x128, warp tile 64x32 (8 warps, 2x4). 3-stage cp.async
//   pipeline (2 in flight), swizzled smem, ONE barrier per stage.
//   Hoisted LDSM addressing (swizzle mask invariant under row+=16k).
//   grid = (N/128, M/128), block = 256.
//   OM bit0: fp32 C; bit1: fp16 C16.  ACT: 0 none, 1 gelu, 2 gelu + pe[col].
// ---------------------------------------------------------------------------
#define TBUF  16384
#define GSMEM (6*TBUF)

template <int ACT, int OM>
__global__ void __launch_bounds__(256, 2)
hgemm_kernel(int M, int N, int K,
             const __half* __restrict__ A, const __half* __restrict__ Bt,
             const float* __restrict__ bias,
             float* __restrict__ C, __half* __restrict__ C16,
             const float* __restrict__ pe)
{
    extern __shared__ char smem[];
    const uint32_t sb = smem_u32(smem);
    const int tid  = threadIdx.x;
    const int wid  = tid >> 5;
    const int lane = tid & 31;
    const int wm   = wid >> 2;
    const int wn   = wid & 3;

    const size_t n0 = (size_t)blockIdx.x * 128;
    const size_t m0 = (size_t)blockIdx.y * 128;
    const __half* Ab = A  + m0 * (size_t)K;
    const __half* Bb = Bt + n0 * (size_t)K;
    const int NS = K >> 6;

    const int ldr  = tid >> 3;
    const int ldcb = (tid & 7) << 4;

    auto load_stage = [&](int s) {
        const uint32_t st  = (uint32_t)(s % 3);
        const uint32_t sa  = sb + st * TBUF;
        const uint32_t sbb = sb + 3 * TBUF + st * TBUF;
        const int k0 = s << 6;
#pragma unroll
        for (int i = 0; i < 4; i++) {
            int r = ldr + (i << 5);
            uint32_t off = swz(r, ldcb);
            const void* ag = Ab + (size_t)r * K + k0 + (ldcb >> 1);
            asm volatile("cp.async.cg.shared.global [%0], [%1], 16;"
                         :: "r"(sa + off), "l"(ag) : "memory");
            const void* bg = Bb + (size_t)r * K + k0 + (ldcb >> 1);
            asm volatile("cp.async.cg.shared.global [%0], [%1], 16;"
                         :: "r"(sbb + off), "l"(bg) : "memory");
        }
        asm volatile("cp.async.commit_group;" ::: "memory");
    };

    load_stage(0);
    load_stage(1);

    float acc[4][4][4];
#pragma unroll
    for (int i = 0; i < 4; i++)
#pragma unroll
        for (int j = 0; j < 4; j++)
#pragma unroll
            for (int kq = 0; kq < 4; kq++) acc[i][j][kq] = 0.f;

    const int a_row = wm * 64 + (lane & 15);
    const int a_kob = (lane >> 4) << 4;
    const int b_row = wn * 32 + (lane & 7) + ((lane >> 4) << 3);
    const int b_kob = ((lane >> 3) & 1) << 4;

    const uint32_t a_msk = (uint32_t)((a_row & 7) << 4);
    const uint32_t b_msk = (uint32_t)((b_row & 7) << 4);
    uint32_t a_off[4], b_off[4];
#pragma unroll
    for (int ks = 0; ks < 4; ks++) {
        a_off[ks] = (uint32_t)(a_row * 128) +
                    ((uint32_t)(ks * 32 + a_kob) ^ a_msk);
        b_off[ks] = (uint32_t)(b_row * 128) +
                    ((uint32_t)(ks * 32 + b_kob) ^ b_msk);
    }

    for (int s = 0; s < NS; s++) {
        if (s + 1 < NS) asm volatile("cp.async.wait_group 1;" ::: "memory");
        else            asm volatile("cp.async.wait_group 0;" ::: "memory");
        __syncthreads();

        if (s + 2 < NS) load_stage(s + 2);

        const uint32_t st  = (uint32_t)(s % 3);
        const uint32_t sa  = sb + st * TBUF;
        const uint32_t sbb = sb + 3 * TBUF + st * TBUF;

#pragma unroll
        for (int ks = 0; ks < 4; ks++) {
            const uint32_t abase = sa  + a_off[ks];
            const uint32_t bbase = sbb + b_off[ks];
            uint32_t af[4][4];
#pragma unroll
            for (int mt = 0; mt < 4; mt++) {
                LDMATRIX_X4(af[mt][0], af[mt][1], af[mt][2], af[mt][3],
                            abase + (uint32_t)(mt * 2048));
            }
            uint32_t bf[4][2];
#pragma unroll
            for (int nt2 = 0; nt2 < 2; nt2++) {
                LDMATRIX_X4(bf[2*nt2][0], bf[2*nt2][1],
                            bf[2*nt2+1][0], bf[2*nt2+1][1],
                            bbase + (uint32_t)(nt2 * 2048));
            }
#pragma unroll
            for (int mt = 0; mt < 4; mt++)
#pragma unroll
                for (int nt = 0; nt < 4; nt++)
                    MMA16816(acc[mt][nt], af[mt], bf[nt]);
        }
    }

    // --- epilogue ---
#pragma unroll
    for (int mt = 0; mt < 4; mt++) {
#pragma unroll
        for (int nt = 0; nt < 4; nt++) {
            const size_t col = n0 + wn * 32 + nt * 8 + (lane & 3) * 2;
            const float b0 = bias[col], b1 = bias[col + 1];
            float p0 = 0.f, p1 = 0.f;
            if (ACT == 2) { p0 = pe[col]; p1 = pe[col + 1]; }
#pragma unroll
            for (int hh = 0; hh < 2; hh++) {
                const size_t row = m0 + wm * 64 + mt * 16 + (lane >> 2) + hh * 8;
                float v0 = acc[mt][nt][2*hh]   + b0;
                float v1 = acc[mt][nt][2*hh+1] + b1;
                if (ACT >= 1) { v0 = gelu_f(v0); v1 = gelu_f(v1); }
                if (ACT == 2) { v0 += p0; v1 += p1; }
                if (OM & 1) {
                    float2* dst = (float2*)(C + row * (size_t)N + col);
                    *dst = make_float2(v0, v1);
                }
                if (OM & 2) {
                    __half2* dst = (__half2*)(C16 + row * (size_t)N + col);
                    *dst = __floats2half2_rn(v0, v1);
                }
            }
        }
    }
}

// ---------------------------------------------------------------------------
// Tensor-core attention. grid = (4, H, B); block = 256 (8 warps).
// ---------------------------------------------------------------------------
#define KVST 72
#define PST  232
#define AK_OFF 0
#define AV_OFF 32256
#define AS_OFF 64512
#define ASMEM  94208

__global__ void __launch_bounds__(256, 2)
attn_mma_kernel(const __half* __restrict__ QKV, const float* __restrict__ bias,
                __half* __restrict__ O)
{
    extern __shared__ char smem[];
    const uint32_t sb = smem_u32(smem);
    const int it  = blockIdx.x;
    const int h   = blockIdx.y;
    const int b   = blockIdx.z;
    const int tid = threadIdx.x;
    const int wid = tid >> 5, lane = tid & 31;
    const int i0  = it * 64;
    const size_t tok0 = (size_t)b * SS;
    const int hoff = h * DKH;

    for (int p = tid; p < 224 * 8; p += 256) {
        int j = p >> 3, c = (p & 7) << 3;
        uint4 kv = make_uint4(0, 0, 0, 0), vv = make_uint4(0, 0, 0, 0);
        if (j < SS) {
            kv = *(const uint4*)(QKV + (tok0 + j) * 1536 + 512 + hoff + c);
            vv = *(const uint4*)(QKV + (tok0 + j) * 1536 + 1024 + hoff + c);
        }
        *(uint4*)(smem + AK_OFF + j * (KVST * 2) + c * 2) = kv;
        *(uint4*)(smem + AV_OFF + j * (KVST * 2) + c * 2) = vv;
    }
    __syncthreads();

    // ---- scores = QK^T / 8 -> fp16 buffer ----
    {
        const int wm = wid & 3;
        const int wn = wid >> 2;
        uint32_t aq[4][4];
        {
            const int r_lo = i0 + wm * 16 + (lane >> 2);
            const int r_hi = r_lo + 8;
            const int h2   = lane & 3;
#pragma unroll
            for (int ks = 0; ks < 4; ks++) {
                uint32_t v0 = 0, v1 = 0, v2 = 0, v3 = 0;
                if (r_lo < SS) {
                    const uint32_t* p =
                        (const uint32_t*)(QKV + (tok0 + r_lo) * 1536 + hoff);
                    v0 = p[8 * ks + h2];
                    v2 = p[8 * ks + 4 + h2];
                }
                if (r_hi < SS) {
                    const uint32_t* p =
                        (const uint32_t*)(QKV + (tok0 + r_hi) * 1536 + hoff);
                    v1 = p[8 * ks + h2];
                    v3 = p[8 * ks + 4 + h2];
                }
                aq[ks][0] = v0; aq[ks][1] = v1; aq[ks][2] = v2; aq[ks][3] = v3;
            }
        }
        const int brow = (lane & 7) + ((lane >> 4) << 3);
        const int bkof = ((lane >> 3) & 1) << 3;
        float acc[7][2][4];
#pragma unroll
        for (int g = 0; g < 7; g++)
#pragma unroll
            for (int q = 0; q < 2; q++)
#pragma unroll
                for (int r = 0; r < 4; r++) acc[g][q][r] = 0.f;

#pragma unroll
        for (int ks = 0; ks < 4; ks++) {
#pragma unroll
            for (int g = 0; g < 7; g++) {
                int ncol = wn * 112 + g * 16;
                uint32_t baddr = sb + AK_OFF +
                    (uint32_t)((ncol + brow) * (KVST * 2) + (ks * 16 + bkof) * 2);
                uint32_t b0, b1, b2, b3;
                LDMATRIX_X4(b0, b1, b2, b3, baddr);
                uint32_t bf0[2] = {b0, b1}, bf1[2] = {b2, b3};
                MMA16816(acc[g][0], aq[ks], bf0);
                MMA16816(acc[g][1], aq[ks], bf1);
            }
        }
        __half* ps = (__half*)(smem + AS_OFF);
        const int r0 = wm * 16 + (lane >> 2);
#pragma unroll
        for (int g = 0; g < 7; g++)
#pragma unroll
            for (int q = 0; q < 2; q++) {
                int col = wn * 112 + g * 16 + q * 8 + (lane & 3) * 2;
                *(__half2*)&ps[r0 * PST + col] =
                    __floats2half2_rn(acc[g][q][0] * 0.125f, acc[g][q][1] * 0.125f);
                *(__half2*)&ps[(r0 + 8) * PST + col] =
                    __floats2half2_rn(acc[g][q][2] * 0.125f, acc[g][q][3] * 0.125f);
            }
    }
    __syncthreads();

    // ---- softmax (+bias), in place fp16 -> P ----
    {
        __half* ps = (__half*)(smem + AS_OFF);
        for (int i = wid; i < 64; i += 8) {
            int gi = i0 + i;
            if (gi < SS) {
                const float* brow = bias + ((size_t)h * SS + gi) * SS;
                float vals[7];
                float m = -1e30f;
#pragma unroll
                for (int t = 0; t < 7; t++) {
                    int j = lane + t * 32;
                    float s = -1e30f;
                    if (j < SS) s = __half2float(ps[i * PST + j]) + brow[j];
                    vals[t] = s;
                    m = fmaxf(m, s);
                }
#pragma unroll
                for (int o = 16; o > 0; o >>= 1)
                    m = fmaxf(m, __shfl_xor_sync(0xffffffffu, m, o));
                float sum = 0.f;
#pragma unroll
                for (int t = 0; t < 7; t++) {
                    int j = lane + t * 32;
                    float e = (j < SS) ? expf(vals[t] - m) : 0.f;
                    vals[t] = e;
                    sum += e;
                }
#pragma unroll
                for (int o = 16; o > 0; o >>= 1)
                    sum += __shfl_xor_sync(0xffffffffu, sum, o);
                float inv = 1.f / sum;
#pragma unroll
                for (int t = 0; t < 7; t++)
                    ps[i * PST + lane + t * 32] = __float2half(vals[t] * inv);
            } else {
#pragma unroll
                for (int t = 0; t < 7; t++)
                    ps[i * PST + lane + t * 32] = __float2half(0.f);
            }
        }
    }
    __syncthreads();

    // ---- ctx = P @ V ----
    {
        const int wm = wid & 3;
        const int wn = wid >> 2;
        const int arow = wm * 16 + (lane & 15);
        const int akof = (lane >> 4) << 3;
        const int vrow = lane & 15;
        const int vcol = (lane >> 4) << 3;
        float acc[4][4];
#pragma unroll
        for (int i = 0; i < 4; i++)
#pragma unroll
            for (int j = 0; j < 4; j++) acc[i][j] = 0.f;

#pragma unroll
        for (int ks = 0; ks < 14; ks++) {
            uint32_t a[4];
            uint32_t aaddr = sb + AS_OFF +
                (uint32_t)(arow * (PST * 2) + (ks * 16 + akof) * 2);
            LDMATRIX_X4(a[0], a[1], a[2], a[3], aaddr);
#pragma unroll
            for (int g = 0; g < 2; g++) {
                int n0c = wn * 32 + g * 16;
                uint32_t baddr = sb + AV_OFF +
                    (uint32_t)((ks * 16 + vrow) * (KVST * 2) + (n0c + vcol) * 2);
                uint32_t b0, b1, b2, b3;
                LDMATRIX_X4_T(b0, b1, b2, b3, baddr);
                uint32_t bf0[2] = {b0, b1}, bf1[2] = {b2, b3};
                MMA16816(acc[g * 2 + 0], a, bf0);
                MMA16816(acc[g * 2 + 1], a, bf1);
            }
        }
#pragma unroll
        for (int nt = 0; nt < 4; nt++) {
            int col = hoff + wn * 32 + nt * 8 + (lane & 3) * 2;
#pragma unroll
            for (int hh = 0; hh < 2; hh++) {
                int row = i0 + wm * 16 + (lane >> 2) + hh * 8;
                if (row < SS) {
                    __half2* dst = (__half2*)(O + (tok0 + row) * DD + col);
                    *dst = __floats2half2_rn(acc[nt][2 * hh], acc[nt][2 * hh + 1]);
                }
            }
        }
    }
}

// ---------------------------------------------------------------------------
// transpose + convert: src f32 [R,C] -> dst f16 [C,R]  (R % 128, C % 32 == 0)
// block (8,32), 128x32 tile per block (4 row-subtiles): 4 loads in flight,
// one barrier, 4 stores. grid (C/32, R/128, batch).
// ---------------------------------------------------------------------------
__global__ void transp_kernel(const float* __restrict__ src,
                              __half* __restrict__ dst,
                              int R, int C, size_t sstride, size_t dstride)
{
    __shared__ float t[4][32][33];
    src += (size_t)blockIdx.z * sstride;
    dst += (size_t)blockIdx.z * dstride;
    const int c0 = blockIdx.x << 5, r0 = blockIdx.y << 7;
    const int x = threadIdx.x;    // 0..7
    const int y = threadIdx.y;    // 0..31

    float4 v[4];
#pragma unroll
    for (int i = 0; i < 4; i++)
        v[i] = *(const float4*)(src + (size_t)(r0 + i * 32 + y) * C + c0 + x * 4);
#pragma unroll
    for (int i = 0; i < 4; i++) {
        t[i][y][x * 4 + 0] = v[i].x;
        t[i][y][x * 4 + 1] = v[i].y;
        t[i][y][x * 4 + 2] = v[i].z;
        t[i][y][x * 4 + 3] = v[i].w;
    }
    __syncthreads();

#pragma unroll
    for (int i = 0; i < 4; i++) {
        __half2 h01 = __floats2half2_rn(t[i][x * 4 + 0][y], t[i][x * 4 + 1][y]);
        __half2 h23 = __floats2half2_rn(t[i][x * 4 + 2][y], t[i][x * 4 + 3][y]);
        uint2 hv;
        hv.x = *(uint32_t*)&h01;
        hv.y = *(uint32_t*)&h23;
        *(uint2*)(dst + (size_t)(c0 + y) * R + r0 + i * 32 + x * 4) = hv;
    }
}

__global__ void concat_z_kernel(const float* __restrict__ zs,
                                const float* __restrict__ zk,
                                __half* __restrict__ z16)
{
    int i = blockIdx.x * blockDim.x + threadIdx.x;
    if (i >= BB * LAT) return;
    int b = i >> 8, c = i & 255;
    float v = (c < 128) ? zs[b * 128 + c] : zk[b * 128 + (c - 128)];
    z16[i] = __float2half(v);
}

__global__ void concat_bqkv_kernel(const float* __restrict__ bq,
                                   const float* __restrict__ bk,
                                   const float* __restrict__ bv,
                                   float* __restrict__ dst)
{
    int i = blockIdx.x * blockDim.x + threadIdx.x;
    if (i >= LL * 3 * DD) return;
    int l = i / (3 * DD), r = i % (3 * DD), part = r / DD, c = r % DD;
    const float* s = (part == 0) ? bq : (part == 1) ? bk : bv;
    dst[i] = s[l * DD + c];
}

// PE table: pe[s*512+d], bit-identical formula to the reference path.
__global__ void pe_kernel(float* __restrict__ pe)
{
    int s = blockIdx.x;
    int d = threadIdx.x;
    const float c = -9.210340371976184f / (float)DD;
    int de = d & ~1;
    float div = expf((float)de * c);
    float ang = (float)s * div;
    pe[s * DD + d] = (d & 1) ? cosf(ang) : sinf(ang);
}

// ---------------------------------------------------------------------------
// x16 = LN(x16 + res16) * g + be, in place on fp16 residual stream.
// Warp per row, single-pass (sum + sumsq), fp32 math. grid NTOK/8, block 256.
// ---------------------------------------------------------------------------
__global__ void __launch_bounds__(256) ln_kernel(
    __half* __restrict__ x16, const __half* __restrict__ res,
    const float* __restrict__ g, const float* __restrict__ be)
{
    const int wid  = threadIdx.x >> 5;
    const int lane = threadIdx.x & 31;
    const size_t row = (size_t)blockIdx.x * 8 + wid;
    __half* xr = x16 + row * DD;
    const __half* rr = res + row * DD;

    float v[16];
    float s = 0.f, q = 0.f;
#pragma unroll
    for (int k = 0; k < 4; k++) {
        uint2 xv = ((const uint2*)xr)[lane + (k << 5)];
        uint2 rv = ((const uint2*)rr)[lane + (k << 5)];
        __half2 x01 = *(__half2*)&xv.x;
        __half2 x23 = *(__half2*)&xv.y;
        __half2 r01 = *(__half2*)&rv.x;
        __half2 r23 = *(__half2*)&rv.y;
        v[4*k+0] = __low2float(x01)  + __low2float(r01);
        v[4*k+1] = __high2float(x01) + __high2float(r01);
        v[4*k+2] = __low2float(x23)  + __low2float(r23);
        v[4*k+3] = __high2float(x23) + __high2float(r23);
#pragma unroll
        for (int j = 0; j < 4; j++) {
            s += v[4*k+j];
            q += v[4*k+j] * v[4*k+j];
        }
    }
#pragma unroll
    for (int o = 16; o > 0; o >>= 1) {
        s += __shfl_xor_sync(0xffffffffu, s, o);
        q += __shfl_xor_sync(0xffffffffu, q, o);
    }
    float mu  = s * (1.f / (float)DD);
    float var = q * (1.f / (float)DD) - mu * mu;
    float rstd = rsqrtf(var + 1e-5f);

#pragma unroll
    for (int k = 0; k < 4; k++) {
        float4 gv = ((const float4*)g)[lane + (k << 5)];
        float4 bv = ((const float4*)be)[lane + (k << 5)];
        float o0 = (v[4*k+0] - mu) * rstd * gv.x + bv.x;
        float o1 = (v[4*k+1] - mu) * rstd * gv.y + bv.y;
        float o2 = (v[4*k+2] - mu) * rstd * gv.z + bv.z;
        float o3 = (v[4*k+3] - mu) * rstd * gv.w + bv.w;
        __half2 h01 = __floats2half2_rn(o0, o1);
        __half2 h23 = __floats2half2_rn(o2, o3);
        uint2 hv;
        hv.x = *(uint32_t*)&h01;
        hv.y = *(uint32_t*)&h23;
        ((uint2*)xr)[lane + (k << 5)] = hv;
    }
}

// ---------------------------------------------------------------------------
// Head projection: out[M,N] = A[M,256] @ W[256,N] + bias, N<=6.
// Warp per row; lane covers 8 K-elements; warp-reduce each output.
// ---------------------------------------------------------------------------
template <int N>
__global__ void __launch_bounds__(256) head_kernel(
    const float* __restrict__ A, const float* __restrict__ W,
    const float* __restrict__ bias, float* __restrict__ out, int M)
{
    __shared__ float ws[N * 256];
    for (int i = threadIdx.x; i < N * 256; i += 256) {
        int n = i >> 8, k = i & 255;
        ws[i] = W[k * N + n];
    }
    __syncthreads();

    const int wid  = threadIdx.x >> 5;
    const int lane = threadIdx.x & 31;
    const int m = blockIdx.x * 8 + wid;
    if (m >= M) return;

    const float4* a4 = (const float4*)(A + (size_t)m * 256);
    float4 v0 = a4[lane];
    float4 v1 = a4[lane + 32];
    const int k0 = lane * 4;
    const int k1 = 128 + lane * 4;

    float acc[N];
#pragma unroll
    for (int n = 0; n < N; n++) {
        const float* w = ws + n * 256;
        acc[n] = v0.x * w[k0] + v0.y * w[k0 + 1] + v0.z * w[k0 + 2] + v0.w * w[k0 + 3]
               + v1.x * w[k1] + v1.y * w[k1 + 1] + v1.z * w[k1 + 2] + v1.w * w[k1 + 3];
    }
#pragma unroll
    for (int n = 0; n < N; n++)
#pragma unroll
        for (int o = 16; o > 0; o >>= 1)
            acc[n] += __shfl_xor_sync(0xffffffffu, acc[n], o);

    if (lane < N)
        out[(size_t)m * N + lane] = acc[lane] + bias[lane];
}

// ---------------------------------------------------------------------------
// Host launcher
// ---------------------------------------------------------------------------
extern "C" void kernel_launch(void* const* d_in, const int* in_sizes, int n_in,
                              void* d_out, int out_size)
{
    const float* z_style   = (const float*)d_in[0];
    const float* z_skill   = (const float*)d_in[1];
    const float* W_lat     = (const float*)d_in[2];
    const float* b_lat     = (const float*)d_in[3];
    const float* temp_bias = (const float*)d_in[4];
    const float* Wq  = (const float*)d_in[5];
    const float* bq  = (const float*)d_in[6];
    const float* Wk  = (const float*)d_in[7];
    const float* bk  = (const float*)d_in[8];
    const float* Wv  = (const float*)d_in[9];
    const float* bv  = (const float*)d_in[10];
    const float* Wo  = (const float*)d_in[11];
    const float* bo  = (const float*)d_in[12];
    const float* g1  = (const float*)d_in[13];
    const float* be1 = (const float*)d_in[14];
    const float* g2  = (const float*)d_in[15];
    const float* be2 = (const float*)d_in[16];
    const float* W1  = (const float*)d_in[17];
    const float* bf1 = (const float*)d_in[18];
    const float* W2  = (const float*)d_in[19];
    const float* bf2 = (const float*)d_in[20];
    const float* Wp1 = (const float*)d_in[21];
    const float* bp1 = (const float*)d_in[22];
    const float* Wp2 = (const float*)d_in[23];
    const float* bp2 = (const float*)d_in[24];
    const float* Ws1 = (const float*)d_in[25];
    const float* bs1 = (const float*)d_in[26];
    const float* Ws2 = (const float*)d_in[27];
    const float* bs2 = (const float*)d_in[28];
    float* out = (float*)d_out;

    float *t1, *s1, *bqkv, *pe;
    __half *z16, *x16, *qkv16, *ctx16, *h116, *tmp16;
    __half *wqkvT, *woT, *w1T, *w2T, *wlatT, *wp1T, *ws1T;
    cudaGetSymbolAddress((void**)&t1,    g_t1);
    cudaGetSymbolAddress((void**)&s1,    g_s1);
    cudaGetSymbolAddress((void**)&bqkv,  g_bqkv);
    cudaGetSymbolAddress((void**)&pe,    g_pe);
    cudaGetSymbolAddress((void**)&z16,   g_z16);
    cudaGetSymbolAddress((void**)&x16,   g_x16);
    cudaGetSymbolAddress((void**)&qkv16, g_qkv16);
    cudaGetSymbolAddress((void**)&ctx16, g_ctx16);
    cudaGetSymbolAddress((void**)&h116,  g_h116);
    cudaGetSymbolAddress((void**)&tmp16, g_tmp16);
    cudaGetSymbolAddress((void**)&wqkvT, g_wqkvT);
    cudaGetSymbolAddress((void**)&woT,   g_woT);
    cudaGetSymbolAddress((void**)&w1T,   g_w1T);
    cudaGetSymbolAddress((void**)&w2T,   g_w2T);
    cudaGetSymbolAddress((void**)&wlatT, g_wlatT);
    cudaGetSymbolAddress((void**)&wp1T,  g_wp1T);
    cudaGetSymbolAddress((void**)&ws1T,  g_ws1T);

    cudaFuncSetAttribute(hgemm_kernel<0,1>, cudaFuncAttributeMaxDynamicSharedMemorySize, GSMEM);
    cudaFuncSetAttribute(hgemm_kernel<0,2>, cudaFuncAttributeMaxDynamicSharedMemorySize, GSMEM);
    cudaFuncSetAttribute(hgemm_kernel<1,1>, cudaFuncAttributeMaxDynamicSharedMemorySize, GSMEM);
    cudaFuncSetAttribute(hgemm_kernel<1,2>, cudaFuncAttributeMaxDynamicSharedMemorySize, GSMEM);
    cudaFuncSetAttribute(hgemm_kernel<2,2>, cudaFuncAttributeMaxDynamicSharedMemorySize, GSMEM);
    cudaFuncSetAttribute(attn_mma_kernel, cudaFuncAttributeMaxDynamicSharedMemorySize, ASMEM);

    const dim3 tb(8, 32);

    pe_kernel<<<SS, DD>>>(pe);
    transp_kernel<<<dim3((DD*SS)/32, LAT/128, 1), tb>>>(W_lat, wlatT, LAT, DD*SS, 0, 0);
    concat_z_kernel<<<(BB * LAT + 255) / 256, 256>>>(z_style, z_skill, z16);

    // latent GEMM: x16 = gelu(z @ W_lat + b_lat) + PE   (fp16 residual stream)
    hgemm_kernel<2,2><<<dim3((DD*SS)/128, 1), 256, GSMEM>>>(
        BB, DD*SS, LAT, z16, wlatT, b_lat, nullptr, x16, pe);

    transp_kernel<<<dim3(16, 4, LL), tb>>>(Wq, wqkvT,                   DD, DD, (size_t)DD*DD, (size_t)3*DD*DD);
    transp_kernel<<<dim3(16, 4, LL), tb>>>(Wk, wqkvT + (size_t)DD*DD,   DD, DD, (size_t)DD*DD, (size_t)3*DD*DD);
    transp_kernel<<<dim3(16, 4, LL), tb>>>(Wv, wqkvT + (size_t)2*DD*DD, DD, DD, (size_t)DD*DD, (size_t)3*DD*DD);
    transp_kernel<<<dim3(16, 4, LL), tb>>>(Wo, woT,  DD, DD,  (size_t)DD*DD,  (size_t)DD*DD);
    transp_kernel<<<dim3(64, 4, LL), tb>>>(W1, w1T,  DD, DFF, (size_t)DD*DFF, (size_t)DFF*DD);
    transp_kernel<<<dim3(16, 16, LL), tb>>>(W2, w2T,  DFF, DD, (size_t)DFF*DD, (size_t)DD*DFF);
    transp_kernel<<<dim3((DD/2)/32, DD/128, 1),  tb>>>(Wp1, wp1T, DD, DD/2, 0, 0);
    transp_kernel<<<dim3((DD/2)/32, LAT/128, 1), tb>>>(Ws1, ws1T, LAT, DD/2, 0, 0);
    concat_bqkv_kernel<<<(LL * 3 * DD + 255) / 256, 256>>>(bq, bk, bv, bqkv);

    for (int l = 0; l < LL; l++) {
        const __half* wqkv_l = wqkvT + (size_t)l * 3 * DD * DD;
        const __half* wo_l   = woT   + (size_t)l * DD * DD;
        const __half* w1_l   = w1T   + (size_t)l * DFF * DD;
        const __half* w2_l   = w2T   + (size_t)l * DD * DFF;

        hgemm_kernel<0,2><<<dim3(12, NTOK/128), 256, GSMEM>>>(
            NTOK, 3*DD, DD, x16, wqkv_l, bqkv + (size_t)l*3*DD, nullptr, qkv16, nullptr);

        attn_mma_kernel<<<dim3(4, HH, BB), 256, ASMEM>>>(qkv16, temp_bias, ctx16);

        hgemm_kernel<0,2><<<dim3(4, NTOK/128), 256, GSMEM>>>(
            NTOK, DD, DD, ctx16, wo_l, bo + (size_t)l*DD, nullptr, tmp16, nullptr);
        ln_kernel<<<NTOK/8, 256>>>(x16, tmp16, g1 + l*DD, be1 + l*DD);

        hgemm_kernel<1,2><<<dim3(16, NTOK/128), 256, GSMEM>>>(
            NTOK, DFF, DD, x16, w1_l, bf1 + (size_t)l*DFF, nullptr, h116, nullptr);
        hgemm_kernel<0,2><<<dim3(4, NTOK/128), 256, GSMEM>>>(
            NTOK, DD, DFF, h116, w2_l, bf2 + (size_t)l*DD, nullptr, tmp16, nullptr);
        ln_kernel<<<NTOK/8, 256>>>(x16, tmp16, g2 + l*DD, be2 + l*DD);
    }

    hgemm_kernel<1,1><<<dim3((DD/2)/128, NTOK/128), 256, GSMEM>>>(
        NTOK, DD/2, DD, x16, wp1T, bp1, t1, nullptr, nullptr);
    head_kernel<OUTD><<<(NTOK + 7) / 8, 256>>>(
        t1, Wp2, bp2, out, NTOK);

    hgemm_kernel<1,1><<<dim3((DD/2)/128, 1), 256, GSMEM>>>(
        BB, DD/2, LAT, z16, ws1T, bs1, s1, nullptr, nullptr);
    head_kernel<5><<<(BB + 7) / 8, 256>>>(
        s1, Ws2, bs2, out + (size_t)NTOK * OUTD, BB);
}

// round 17
// speedup vs baseline: 1.2210x; 1.0308x over previous
#include <cuda_runtime.h>
#include <cuda_fp16.h>
#include <cstdint>
#include <cstddef>

// ---------------------------------------------------------------------------
// Problem constants
// ---------------------------------------------------------------------------
#define BB   128
#define DD   512
#define HH   8
#define LL   6
#define SS   200
#define LAT  256
#define OUTD 6
#define DKH  64
#define DFF  2048
#define NTOK (BB*SS)   // 25600

// ---------------------------------------------------------------------------
// Device scratch
// ---------------------------------------------------------------------------
__device__ __align__(256) float  g_t1  [NTOK*(DD/2)];
__device__ __align__(256) float  g_s1  [BB*(DD/2)];
__device__ __align__(256) float  g_bqkv[LL*3*DD];
__device__ __align__(256) float  g_pe  [SS*DD];

__device__ __align__(256) __half g_z16  [BB*LAT];
__device__ __align__(256) __half g_x16  [NTOK*DD];
__device__ __align__(256) __half g_qkv16[NTOK*3*DD];
__device__ __align__(256) __half g_ctx16[NTOK*DD];
__device__ __align__(256) __half g_h116 [NTOK*DFF];
__device__ __align__(256) __half g_tmp16[NTOK*DD];

__device__ __align__(256) __half g_wqkvT[LL*3*DD*DD];
__device__ __align__(256) __half g_woT  [LL*DD*DD];
__device__ __align__(256) __half g_w1T  [LL*DFF*DD];
__device__ __align__(256) __half g_w2T  [LL*DD*DFF];
__device__ __align__(256) __half g_wlatT[(size_t)(DD*SS)*LAT];
__device__ __align__(256) __half g_wp1T [(DD/2)*DD];
__device__ __align__(256) __half g_ws1T [(DD/2)*LAT];

// ---------------------------------------------------------------------------
// Helpers
// ---------------------------------------------------------------------------
__device__ __forceinline__ uint32_t smem_u32(const void* p) {
    uint32_t a;
    asm("{ .reg .u64 t; cvta.to.shared.u64 t, %1; cvt.u32.u64 %0, t; }"
        : "=r"(a) : "l"(p));
    return a;
}
__device__ __forceinline__ float gelu_f(float x) {
    return 0.5f * x * (1.0f + erff(x * 0.7071067811865475f));
}

#define LDMATRIX_X4(r0, r1, r2, r3, addr)                                     \
    asm volatile("ldmatrix.sync.aligned.m8n8.x4.shared.b16 "                  \
                 "{%0, %1, %2, %3}, [%4];"                                    \
                 : "=r"(r0), "=r"(r1), "=r"(r2), "=r"(r3) : "r"(addr))

#define LDMATRIX_X4_T(r0, r1, r2, r3, addr)                                   \
    asm volatile("ldmatrix.sync.aligned.m8n8.x4.trans.shared.b16 "            \
                 "{%0, %1, %2, %3}, [%4];"                                    \
                 : "=r"(r0), "=r"(r1), "=r"(r2), "=r"(r3) : "r"(addr))

#define MMA16816(c, a, b)                                                     \
    asm volatile("mma.sync.aligned.m16n8k16.row.col.f32.f16.f16.f32 "         \
                 "{%0, %1, %2, %3}, {%4, %5, %6, %7}, {%8, %9}, "             \
                 "{%0, %1, %2, %3};"                                          \
                 : "+f"((c)[0]), "+f"((c)[1]), "+f"((c)[2]), "+f"((c)[3])     \
                 : "r"((a)[0]), "r"((a)[1]), "r"((a)[2]), "r"((a)[3]),        \
                   "r"((b)[0]), "r"((b)[1]))

// swizzled byte offset inside a 128x64h (128B-row) tile
__device__ __forceinline__ uint32_t swz(int row, int colb) {
    return (uint32_t)(row * 128 + (colb ^ ((row & 7) << 4)));
}

// ---------------------------------------------------------------------------
// fp16 tensor-core GEMM (mma.sync):  C[M,N] = act(A[M,K] @ Bt[N,K]^T + bias)
//   CTA tile 128x128, warp tile 64x32 (8 warps, 2x4). 3-stage cp.async
//   pipeline (2 in flight), swizzled smem, ONE barrier per stage.
//   Hoisted LDSM addressing. grid = (N/128, M/128), block = 256.
//   OM bit0: fp32 C; bit1: fp16 C16.  ACT: 0 none, 1 gelu, 2 gelu + pe[col].
// ---------------------------------------------------------------------------
#define TBUF  16384
#define GSMEM (6*TBUF)

template <int ACT, int OM>
__global__ void __launch_bounds__(256, 2)
hgemm_kernel(int M, int N, int K,
             const __half* __restrict__ A, const __half* __restrict__ Bt,
             const float* __restrict__ bias,
             float* __restrict__ C, __half* __restrict__ C16,
             const float* __restrict__ pe)
{
    extern __shared__ char smem[];
    const uint32_t sb = smem_u32(smem);
    const int tid  = threadIdx.x;
    const int wid  = tid >> 5;
    const int lane = tid & 31;
    const int wm   = wid >> 2;
    const int wn   = wid & 3;

    const size_t n0 = (size_t)blockIdx.x * 128;
    const size_t m0 = (size_t)blockIdx.y * 128;
    const __half* Ab = A  + m0 * (size_t)K;
    const __half* Bb = Bt + n0 * (size_t)K;
    const int NS = K >> 6;

    const int ldr  = tid >> 3;
    const int ldcb = (tid & 7) << 4;

    auto load_stage = [&](int s) {
        const uint32_t st  = (uint32_t)(s % 3);
        const uint32_t sa  = sb + st * TBUF;
        const uint32_t sbb = sb + 3 * TBUF + st * TBUF;
        const int k0 = s << 6;
#pragma unroll
        for (int i = 0; i < 4; i++) {
            int r = ldr + (i << 5);
            uint32_t off = swz(r, ldcb);
            const void* ag = Ab + (size_t)r * K + k0 + (ldcb >> 1);
            asm volatile("cp.async.cg.shared.global [%0], [%1], 16;"
                         :: "r"(sa + off), "l"(ag) : "memory");
            const void* bg = Bb + (size_t)r * K + k0 + (ldcb >> 1);
            asm volatile("cp.async.cg.shared.global [%0], [%1], 16;"
                         :: "r"(sbb + off), "l"(bg) : "memory");
        }
        asm volatile("cp.async.commit_group;" ::: "memory");
    };

    load_stage(0);
    load_stage(1);

    float acc[4][4][4];
#pragma unroll
    for (int i = 0; i < 4; i++)
#pragma unroll
        for (int j = 0; j < 4; j++)
#pragma unroll
            for (int kq = 0; kq < 4; kq++) acc[i][j][kq] = 0.f;

    const int a_row = wm * 64 + (lane & 15);
    const int a_kob = (lane >> 4) << 4;
    const int b_row = wn * 32 + (lane & 7) + ((lane >> 4) << 3);
    const int b_kob = ((lane >> 3) & 1) << 4;

    const uint32_t a_msk = (uint32_t)((a_row & 7) << 4);
    const uint32_t b_msk = (uint32_t)((b_row & 7) << 4);
    uint32_t a_off[4], b_off[4];
#pragma unroll
    for (int ks = 0; ks < 4; ks++) {
        a_off[ks] = (uint32_t)(a_row * 128) +
                    ((uint32_t)(ks * 32 + a_kob) ^ a_msk);
        b_off[ks] = (uint32_t)(b_row * 128) +
                    ((uint32_t)(ks * 32 + b_kob) ^ b_msk);
    }

    for (int s = 0; s < NS; s++) {
        if (s + 1 < NS) asm volatile("cp.async.wait_group 1;" ::: "memory");
        else            asm volatile("cp.async.wait_group 0;" ::: "memory");
        __syncthreads();

        if (s + 2 < NS) load_stage(s + 2);

        const uint32_t st  = (uint32_t)(s % 3);
        const uint32_t sa  = sb + st * TBUF;
        const uint32_t sbb = sb + 3 * TBUF + st * TBUF;

#pragma unroll
        for (int ks = 0; ks < 4; ks++) {
            const uint32_t abase = sa  + a_off[ks];
            const uint32_t bbase = sbb + b_off[ks];
            uint32_t af[4][4];
#pragma unroll
            for (int mt = 0; mt < 4; mt++) {
                LDMATRIX_X4(af[mt][0], af[mt][1], af[mt][2], af[mt][3],
                            abase + (uint32_t)(mt * 2048));
            }
            uint32_t bf[4][2];
#pragma unroll
            for (int nt2 = 0; nt2 < 2; nt2++) {
                LDMATRIX_X4(bf[2*nt2][0], bf[2*nt2][1],
                            bf[2*nt2+1][0], bf[2*nt2+1][1],
                            bbase + (uint32_t)(nt2 * 2048));
            }
#pragma unroll
            for (int mt = 0; mt < 4; mt++)
#pragma unroll
                for (int nt = 0; nt < 4; nt++)
                    MMA16816(acc[mt][nt], af[mt], bf[nt]);
        }
    }

    // --- epilogue ---
#pragma unroll
    for (int mt = 0; mt < 4; mt++) {
#pragma unroll
        for (int nt = 0; nt < 4; nt++) {
            const size_t col = n0 + wn * 32 + nt * 8 + (lane & 3) * 2;
            const float b0 = bias[col], b1 = bias[col + 1];
            float p0 = 0.f, p1 = 0.f;
            if (ACT == 2) { p0 = pe[col]; p1 = pe[col + 1]; }
#pragma unroll
            for (int hh = 0; hh < 2; hh++) {
                const size_t row = m0 + wm * 64 + mt * 16 + (lane >> 2) + hh * 8;
                float v0 = acc[mt][nt][2*hh]   + b0;
                float v1 = acc[mt][nt][2*hh+1] + b1;
                if (ACT >= 1) { v0 = gelu_f(v0); v1 = gelu_f(v1); }
                if (ACT == 2) { v0 += p0; v1 += p1; }
                if (OM & 1) {
                    float2* dst = (float2*)(C + row * (size_t)N + col);
                    *dst = make_float2(v0, v1);
                }
                if (OM & 2) {
                    __half2* dst = (__half2*)(C16 + row * (size_t)N + col);
                    *dst = __floats2half2_rn(v0, v1);
                }
            }
        }
    }
}

// ---------------------------------------------------------------------------
// Tensor-core attention. grid = (H, B); block = 256 (8 warps).
// One CTA per (b,h): K/V loaded ONCE into smem, then 4 query-tiles of 64
// rows processed in a loop (scores -> softmax -> P@V), reusing the fp16
// score/P buffer each iteration. Arithmetic identical per tile.
// ---------------------------------------------------------------------------
#define KVST 72
#define PST  232
#define AK_OFF 0
#define AV_OFF 32256
#define AS_OFF 64512
#define ASMEM  94208

__global__ void __launch_bounds__(256, 2)
attn_mma_kernel(const __half* __restrict__ QKV, const float* __restrict__ bias,
                __half* __restrict__ O)
{
    extern __shared__ char smem[];
    const uint32_t sb = smem_u32(smem);
    const int h   = blockIdx.x;
    const int b   = blockIdx.y;
    const int tid = threadIdx.x;
    const int wid = tid >> 5, lane = tid & 31;
    const size_t tok0 = (size_t)b * SS;
    const int hoff = h * DKH;

    // ---- load K, V once (zero-fill j >= 200) ----
    for (int p = tid; p < 224 * 8; p += 256) {
        int j = p >> 3, c = (p & 7) << 3;
        uint4 kv = make_uint4(0, 0, 0, 0), vv = make_uint4(0, 0, 0, 0);
        if (j < SS) {
            kv = *(const uint4*)(QKV + (tok0 + j) * 1536 + 512 + hoff + c);
            vv = *(const uint4*)(QKV + (tok0 + j) * 1536 + 1024 + hoff + c);
        }
        *(uint4*)(smem + AK_OFF + j * (KVST * 2) + c * 2) = kv;
        *(uint4*)(smem + AV_OFF + j * (KVST * 2) + c * 2) = vv;
    }
    __syncthreads();

    for (int it = 0; it < 4; it++) {
        const int i0 = it * 64;

        // ---- scores = QK^T / 8 -> fp16 buffer ----
        {
            const int wm = wid & 3;
            const int wn = wid >> 2;
            uint32_t aq[4][4];
            {
                const int r_lo = i0 + wm * 16 + (lane >> 2);
                const int r_hi = r_lo + 8;
                const int h2   = lane & 3;
#pragma unroll
                for (int ks = 0; ks < 4; ks++) {
                    uint32_t v0 = 0, v1 = 0, v2 = 0, v3 = 0;
                    if (r_lo < SS) {
                        const uint32_t* p =
                            (const uint32_t*)(QKV + (tok0 + r_lo) * 1536 + hoff);
                        v0 = p[8 * ks + h2];
                        v2 = p[8 * ks + 4 + h2];
                    }
                    if (r_hi < SS) {
                        const uint32_t* p =
                            (const uint32_t*)(QKV + (tok0 + r_hi) * 1536 + hoff);
                        v1 = p[8 * ks + h2];
                        v3 = p[8 * ks + 4 + h2];
                    }
                    aq[ks][0] = v0; aq[ks][1] = v1; aq[ks][2] = v2; aq[ks][3] = v3;
                }
            }
            const int brow = (lane & 7) + ((lane >> 4) << 3);
            const int bkof = ((lane >> 3) & 1) << 3;
            float acc[7][2][4];
#pragma unroll
            for (int g = 0; g < 7; g++)
#pragma unroll
                for (int q = 0; q < 2; q++)
#pragma unroll
                    for (int r = 0; r < 4; r++) acc[g][q][r] = 0.f;

#pragma unroll
            for (int ks = 0; ks < 4; ks++) {
#pragma unroll
                for (int g = 0; g < 7; g++) {
                    int ncol = wn * 112 + g * 16;
                    uint32_t baddr = sb + AK_OFF +
                        (uint32_t)((ncol + brow) * (KVST * 2) + (ks * 16 + bkof) * 2);
                    uint32_t b0, b1, b2, b3;
                    LDMATRIX_X4(b0, b1, b2, b3, baddr);
                    uint32_t bf0[2] = {b0, b1}, bf1[2] = {b2, b3};
                    MMA16816(acc[g][0], aq[ks], bf0);
                    MMA16816(acc[g][1], aq[ks], bf1);
                }
            }
            __half* ps = (__half*)(smem + AS_OFF);
            const int r0 = wm * 16 + (lane >> 2);
#pragma unroll
            for (int g = 0; g < 7; g++)
#pragma unroll
                for (int q = 0; q < 2; q++) {
                    int col = wn * 112 + g * 16 + q * 8 + (lane & 3) * 2;
                    *(__half2*)&ps[r0 * PST + col] =
                        __floats2half2_rn(acc[g][q][0] * 0.125f, acc[g][q][1] * 0.125f);
                    *(__half2*)&ps[(r0 + 8) * PST + col] =
                        __floats2half2_rn(acc[g][q][2] * 0.125f, acc[g][q][3] * 0.125f);
                }
        }
        __syncthreads();

        // ---- softmax (+bias), in place fp16 -> P ----
        {
            __half* ps = (__half*)(smem + AS_OFF);
            for (int i = wid; i < 64; i += 8) {
                int gi = i0 + i;
                if (gi < SS) {
                    const float* brow = bias + ((size_t)h * SS + gi) * SS;
                    float vals[7];
                    float m = -1e30f;
#pragma unroll
                    for (int t = 0; t < 7; t++) {
                        int j = lane + t * 32;
                        float s = -1e30f;
                        if (j < SS) s = __half2float(ps[i * PST + j]) + brow[j];
                        vals[t] = s;
                        m = fmaxf(m, s);
                    }
#pragma unroll
                    for (int o = 16; o > 0; o >>= 1)
                        m = fmaxf(m, __shfl_xor_sync(0xffffffffu, m, o));
                    float sum = 0.f;
#pragma unroll
                    for (int t = 0; t < 7; t++) {
                        int j = lane + t * 32;
                        float e = (j < SS) ? expf(vals[t] - m) : 0.f;
                        vals[t] = e;
                        sum += e;
                    }
#pragma unroll
                    for (int o = 16; o > 0; o >>= 1)
                        sum += __shfl_xor_sync(0xffffffffu, sum, o);
                    float inv = 1.f / sum;
#pragma unroll
                    for (int t = 0; t < 7; t++)
                        ps[i * PST + lane + t * 32] = __float2half(vals[t] * inv);
                } else {
#pragma unroll
                    for (int t = 0; t < 7; t++)
                        ps[i * PST + lane + t * 32] = __float2half(0.f);
                }
            }
        }
        __syncthreads();

        // ---- ctx = P @ V ----
        {
            const int wm = wid & 3;
            const int wn = wid >> 2;
            const int arow = wm * 16 + (lane & 15);
            const int akof = (lane >> 4) << 3;
            const int vrow = lane & 15;
            const int vcol = (lane >> 4) << 3;
            float acc[4][4];
#pragma unroll
            for (int i = 0; i < 4; i++)
#pragma unroll
                for (int j = 0; j < 4; j++) acc[i][j] = 0.f;

#pragma unroll
            for (int ks = 0; ks < 14; ks++) {
                uint32_t a[4];
                uint32_t aaddr = sb + AS_OFF +
                    (uint32_t)(arow * (PST * 2) + (ks * 16 + akof) * 2);
                LDMATRIX_X4(a[0], a[1], a[2], a[3], aaddr);
#pragma unroll
                for (int g = 0; g < 2; g++) {
                    int n0c = wn * 32 + g * 16;
                    uint32_t baddr = sb + AV_OFF +
                        (uint32_t)((ks * 16 + vrow) * (KVST * 2) + (n0c + vcol) * 2);
                    uint32_t b0, b1, b2, b3;
                    LDMATRIX_X4_T(b0, b1, b2, b3, baddr);
                    uint32_t bf0[2] = {b0, b1}, bf1[2] = {b2, b3};
                    MMA16816(acc[g * 2 + 0], a, bf0);
                    MMA16816(acc[g * 2 + 1], a, bf1);
                }
            }
#pragma unroll
            for (int nt = 0; nt < 4; nt++) {
                int col = hoff + wn * 32 + nt * 8 + (lane & 3) * 2;
#pragma unroll
                for (int hh = 0; hh < 2; hh++) {
                    int row = i0 + wm * 16 + (lane >> 2) + hh * 8;
                    if (row < SS) {
                        __half2* dst = (__half2*)(O + (tok0 + row) * DD + col);
                        *dst = __floats2half2_rn(acc[nt][2 * hh], acc[nt][2 * hh + 1]);
                    }
                }
            }
        }
        __syncthreads();   // protect score/P buffer before next iteration
    }
}

// ---------------------------------------------------------------------------
// transpose + convert: src f32 [R,C] -> dst f16 [C,R]  (R % 128, C % 32 == 0)
// ---------------------------------------------------------------------------
__global__ void transp_kernel(const float* __restrict__ src,
                              __half* __restrict__ dst,
                              int R, int C, size_t sstride, size_t dstride)
{
    __shared__ float t[4][32][33];
    src += (size_t)blockIdx.z * sstride;
    dst += (size_t)blockIdx.z * dstride;
    const int c0 = blockIdx.x << 5, r0 = blockIdx.y << 7;
    const int x = threadIdx.x;    // 0..7
    const int y = threadIdx.y;    // 0..31

    float4 v[4];
#pragma unroll
    for (int i = 0; i < 4; i++)
        v[i] = *(const float4*)(src + (size_t)(r0 + i * 32 + y) * C + c0 + x * 4);
#pragma unroll
    for (int i = 0; i < 4; i++) {
        t[i][y][x * 4 + 0] = v[i].x;
        t[i][y][x * 4 + 1] = v[i].y;
        t[i][y][x * 4 + 2] = v[i].z;
        t[i][y][x * 4 + 3] = v[i].w;
    }
    __syncthreads();

#pragma unroll
    for (int i = 0; i < 4; i++) {
        __half2 h01 = __floats2half2_rn(t[i][x * 4 + 0][y], t[i][x * 4 + 1][y]);
        __half2 h23 = __floats2half2_rn(t[i][x * 4 + 2][y], t[i][x * 4 + 3][y]);
        uint2 hv;
        hv.x = *(uint32_t*)&h01;
        hv.y = *(uint32_t*)&h23;
        *(uint2*)(dst + (size_t)(c0 + y) * R + r0 + i * 32 + x * 4) = hv;
    }
}

__global__ void concat_z_kernel(const float* __restrict__ zs,
                                const float* __restrict__ zk,
                                __half* __restrict__ z16)
{
    int i = blockIdx.x * blockDim.x + threadIdx.x;
    if (i >= BB * LAT) return;
    int b = i >> 8, c = i & 255;
    float v = (c < 128) ? zs[b * 128 + c] : zk[b * 128 + (c - 128)];
    z16[i] = __float2half(v);
}

__global__ void concat_bqkv_kernel(const float* __restrict__ bq,
                                   const float* __restrict__ bk,
                                   const float* __restrict__ bv,
                                   float* __restrict__ dst)
{
    int i = blockIdx.x * blockDim.x + threadIdx.x;
    if (i >= LL * 3 * DD) return;
    int l = i / (3 * DD), r = i % (3 * DD), part = r / DD, c = r % DD;
    const float* s = (part == 0) ? bq : (part == 1) ? bk : bv;
    dst[i] = s[l * DD + c];
}

// PE table: pe[s*512+d], bit-identical formula to the reference path.
__global__ void pe_kernel(float* __restrict__ pe)
{
    int s = blockIdx.x;
    int d = threadIdx.x;
    const float c = -9.210340371976184f / (float)DD;
    int de = d & ~1;
    float div = expf((float)de * c);
    float ang = (float)s * div;
    pe[s * DD + d] = (d & 1) ? cosf(ang) : sinf(ang);
}

// ---------------------------------------------------------------------------
// x16 = LN(x16 + res16) * g + be, in place on fp16 residual stream.
// Warp per row, single-pass (sum + sumsq), fp32 math. grid NTOK/8, block 256.
// ---------------------------------------------------------------------------
__global__ void __launch_bounds__(256) ln_kernel(
    __half* __restrict__ x16, const __half* __restrict__ res,
    const float* __restrict__ g, const float* __restrict__ be)
{
    const int wid  = threadIdx.x >> 5;
    const int lane = threadIdx.x & 31;
    const size_t row = (size_t)blockIdx.x * 8 + wid;
    __half* xr = x16 + row * DD;
    const __half* rr = res + row * DD;

    float v[16];
    float s = 0.f, q = 0.f;
#pragma unroll
    for (int k = 0; k < 4; k++) {
        uint2 xv = ((const uint2*)xr)[lane + (k << 5)];
        uint2 rv = ((const uint2*)rr)[lane + (k << 5)];
        __half2 x01 = *(__half2*)&xv.x;
        __half2 x23 = *(__half2*)&xv.y;
        __half2 r01 = *(__half2*)&rv.x;
        __half2 r23 = *(__half2*)&rv.y;
        v[4*k+0] = __low2float(x01)  + __low2float(r01);
        v[4*k+1] = __high2float(x01) + __high2float(r01);
        v[4*k+2] = __low2float(x23)  + __low2float(r23);
        v[4*k+3] = __high2float(x23) + __high2float(r23);
#pragma unroll
        for (int j = 0; j < 4; j++) {
            s += v[4*k+j];
            q += v[4*k+j] * v[4*k+j];
        }
    }
#pragma unroll
    for (int o = 16; o > 0; o >>= 1) {
        s += __shfl_xor_sync(0xffffffffu, s, o);
        q += __shfl_xor_sync(0xffffffffu, q, o);
    }
    float mu  = s * (1.f / (float)DD);
    float var = q * (1.f / (float)DD) - mu * mu;
    float rstd = rsqrtf(var + 1e-5f);

#pragma unroll
    for (int k = 0; k < 4; k++) {
        float4 gv = ((const float4*)g)[lane + (k << 5)];
        float4 bv = ((const float4*)be)[lane + (k << 5)];
        float o0 = (v[4*k+0] - mu) * rstd * gv.x + bv.x;
        float o1 = (v[4*k+1] - mu) * rstd * gv.y + bv.y;
        float o2 = (v[4*k+2] - mu) * rstd * gv.z + bv.z;
        float o3 = (v[4*k+3] - mu) * rstd * gv.w + bv.w;
        __half2 h01 = __floats2half2_rn(o0, o1);
        __half2 h23 = __floats2half2_rn(o2, o3);
        uint2 hv;
        hv.x = *(uint32_t*)&h01;
        hv.y = *(uint32_t*)&h23;
        ((uint2*)xr)[lane + (k << 5)] = hv;
    }
}

// ---------------------------------------------------------------------------
// Head projection: out[M,N] = A[M,256] @ W[256,N] + bias, N<=6.
// Warp per row; lane covers 8 K-elements; warp-reduce each output.
// ---------------------------------------------------------------------------
template <int N>
__global__ void __launch_bounds__(256) head_kernel(
    const float* __restrict__ A, const float* __restrict__ W,
    const float* __restrict__ bias, float* __restrict__ out, int M)
{
    __shared__ float ws[N * 256];
    for (int i = threadIdx.x; i < N * 256; i += 256) {
        int n = i >> 8, k = i & 255;
        ws[i] = W[k * N + n];
    }
    __syncthreads();

    const int wid  = threadIdx.x >> 5;
    const int lane = threadIdx.x & 31;
    const int m = blockIdx.x * 8 + wid;
    if (m >= M) return;

    const float4* a4 = (const float4*)(A + (size_t)m * 256);
    float4 v0 = a4[lane];
    float4 v1 = a4[lane + 32];
    const int k0 = lane * 4;
    const int k1 = 128 + lane * 4;

    float acc[N];
#pragma unroll
    for (int n = 0; n < N; n++) {
        const float* w = ws + n * 256;
        acc[n] = v0.x * w[k0] + v0.y * w[k0 + 1] + v0.z * w[k0 + 2] + v0.w * w[k0 + 3]
               + v1.x * w[k1] + v1.y * w[k1 + 1] + v1.z * w[k1 + 2] + v1.w * w[k1 + 3];
    }
#pragma unroll
    for (int n = 0; n < N; n++)
#pragma unroll
        for (int o = 16; o > 0; o >>= 1)
            acc[n] += __shfl_xor_sync(0xffffffffu, acc[n], o);

    if (lane < N)
        out[(size_t)m * N + lane] = acc[lane] + bias[lane];
}

// ---------------------------------------------------------------------------
// Host launcher
// ---------------------------------------------------------------------------
extern "C" void kernel_launch(void* const* d_in, const int* in_sizes, int n_in,
                              void* d_out, int out_size)
{
    const float* z_style   = (const float*)d_in[0];
    const float* z_skill   = (const float*)d_in[1];
    const float* W_lat     = (const float*)d_in[2];
    const float* b_lat     = (const float*)d_in[3];
    const float* temp_bias = (const float*)d_in[4];
    const float* Wq  = (const float*)d_in[5];
    const float* bq  = (const float*)d_in[6];
    const float* Wk  = (const float*)d_in[7];
    const float* bk  = (const float*)d_in[8];
    const float* Wv  = (const float*)d_in[9];
    const float* bv  = (const float*)d_in[10];
    const float* Wo  = (const float*)d_in[11];
    const float* bo  = (const float*)d_in[12];
    const float* g1  = (const float*)d_in[13];
    const float* be1 = (const float*)d_in[14];
    const float* g2  = (const float*)d_in[15];
    const float* be2 = (const float*)d_in[16];
    const float* W1  = (const float*)d_in[17];
    const float* bf1 = (const float*)d_in[18];
    const float* W2  = (const float*)d_in[19];
    const float* bf2 = (const float*)d_in[20];
    const float* Wp1 = (const float*)d_in[21];
    const float* bp1 = (const float*)d_in[22];
    const float* Wp2 = (const float*)d_in[23];
    const float* bp2 = (const float*)d_in[24];
    const float* Ws1 = (const float*)d_in[25];
    const float* bs1 = (const float*)d_in[26];
    const float* Ws2 = (const float*)d_in[27];
    const float* bs2 = (const float*)d_in[28];
    float* out = (float*)d_out;

    float *t1, *s1, *bqkv, *pe;
    __half *z16, *x16, *qkv16, *ctx16, *h116, *tmp16;
    __half *wqkvT, *woT, *w1T, *w2T, *wlatT, *wp1T, *ws1T;
    cudaGetSymbolAddress((void**)&t1,    g_t1);
    cudaGetSymbolAddress((void**)&s1,    g_s1);
    cudaGetSymbolAddress((void**)&bqkv,  g_bqkv);
    cudaGetSymbolAddress((void**)&pe,    g_pe);
    cudaGetSymbolAddress((void**)&z16,   g_z16);
    cudaGetSymbolAddress((void**)&x16,   g_x16);
    cudaGetSymbolAddress((void**)&qkv16, g_qkv16);
    cudaGetSymbolAddress((void**)&ctx16, g_ctx16);
    cudaGetSymbolAddress((void**)&h116,  g_h116);
    cudaGetSymbolAddress((void**)&tmp16, g_tmp16);
    cudaGetSymbolAddress((void**)&wqkvT, g_wqkvT);
    cudaGetSymbolAddress((void**)&woT,   g_woT);
    cudaGetSymbolAddress((void**)&w1T,   g_w1T);
    cudaGetSymbolAddress((void**)&w2T,   g_w2T);
    cudaGetSymbolAddress((void**)&wlatT, g_wlatT);
    cudaGetSymbolAddress((void**)&wp1T,  g_wp1T);
    cudaGetSymbolAddress((void**)&ws1T,  g_ws1T);

    cudaFuncSetAttribute(hgemm_kernel<0,1>, cudaFuncAttributeMaxDynamicSharedMemorySize, GSMEM);
    cudaFuncSetAttribute(hgemm_kernel<0,2>, cudaFuncAttributeMaxDynamicSharedMemorySize, GSMEM);
    cudaFuncSetAttribute(hgemm_kernel<1,1>, cudaFuncAttributeMaxDynamicSharedMemorySize, GSMEM);
    cudaFuncSetAttribute(hgemm_kernel<1,2>, cudaFuncAttributeMaxDynamicSharedMemorySize, GSMEM);
    cudaFuncSetAttribute(hgemm_kernel<2,2>, cudaFuncAttributeMaxDynamicSharedMemorySize, GSMEM);
    cudaFuncSetAttribute(attn_mma_kernel, cudaFuncAttributeMaxDynamicSharedMemorySize, ASMEM);

    const dim3 tb(8, 32);

    pe_kernel<<<SS, DD>>>(pe);
    transp_kernel<<<dim3((DD*SS)/32, LAT/128, 1), tb>>>(W_lat, wlatT, LAT, DD*SS, 0, 0);
    concat_z_kernel<<<(BB * LAT + 255) / 256, 256>>>(z_style, z_skill, z16);

    // latent GEMM: x16 = gelu(z @ W_lat + b_lat) + PE   (fp16 residual stream)
    hgemm_kernel<2,2><<<dim3((DD*SS)/128, 1), 256, GSMEM>>>(
        BB, DD*SS, LAT, z16, wlatT, b_lat, nullptr, x16, pe);

    transp_kernel<<<dim3(16, 4, LL), tb>>>(Wq, wqkvT,                   DD, DD, (size_t)DD*DD, (size_t)3*DD*DD);
    transp_kernel<<<dim3(16, 4, LL), tb>>>(Wk, wqkvT + (size_t)DD*DD,   DD, DD, (size_t)DD*DD, (size_t)3*DD*DD);
    transp_kernel<<<dim3(16, 4, LL), tb>>>(Wv, wqkvT + (size_t)2*DD*DD, DD, DD, (size_t)DD*DD, (size_t)3*DD*DD);
    transp_kernel<<<dim3(16, 4, LL), tb>>>(Wo, woT,  DD, DD,  (size_t)DD*DD,  (size_t)DD*DD);
    transp_kernel<<<dim3(64, 4, LL), tb>>>(W1, w1T,  DD, DFF, (size_t)DD*DFF, (size_t)DFF*DD);
    transp_kernel<<<dim3(16, 16, LL), tb>>>(W2, w2T,  DFF, DD, (size_t)DFF*DD, (size_t)DD*DFF);
    transp_kernel<<<dim3((DD/2)/32, DD/128, 1),  tb>>>(Wp1, wp1T, DD, DD/2, 0, 0);
    transp_kernel<<<dim3((DD/2)/32, LAT/128, 1), tb>>>(Ws1, ws1T, LAT, DD/2, 0, 0);
    concat_bqkv_kernel<<<(LL * 3 * DD + 255) / 256, 256>>>(bq, bk, bv, bqkv);

    for (int l = 0; l < LL; l++) {
        const __half* wqkv_l = wqkvT + (size_t)l * 3 * DD * DD;
        const __half* wo_l   = woT   + (size_t)l * DD * DD;
        const __half* w1_l   = w1T   + (size_t)l * DFF * DD;
        const __half* w2_l   = w2T   + (size_t)l * DD * DFF;

        hgemm_kernel<0,2><<<dim3(12, NTOK/128), 256, GSMEM>>>(
            NTOK, 3*DD, DD, x16, wqkv_l, bqkv + (size_t)l*3*DD, nullptr, qkv16, nullptr);

        attn_mma_kernel<<<dim3(HH, BB), 256, ASMEM>>>(qkv16, temp_bias, ctx16);

        hgemm_kernel<0,2><<<dim3(4, NTOK/128), 256, GSMEM>>>(
            NTOK, DD, DD, ctx16, wo_l, bo + (size_t)l*DD, nullptr, tmp16, nullptr);
        ln_kernel<<<NTOK/8, 256>>>(x16, tmp16, g1 + l*DD, be1 + l*DD);

        hgemm_kernel<1,2><<<dim3(16, NTOK/128), 256, GSMEM>>>(
            NTOK, DFF, DD, x16, w1_l, bf1 + (size_t)l*DFF, nullptr, h116, nullptr);
        hgemm_kernel<0,2><<<dim3(4, NTOK/128), 256, GSMEM>>>(
            NTOK, DD, DFF, h116, w2_l, bf2 + (size_t)l*DD, nullptr, tmp16, nullptr);
        ln_kernel<<<NTOK/8, 256>>>(x16, tmp16, g2 + l*DD, be2 + l*DD);
    }

    hgemm_kernel<1,1><<<dim3((DD/2)/128, NTOK/128), 256, GSMEM>>>(
        NTOK, DD/2, DD, x16, wp1T, bp1, t1, nullptr, nullptr);
    head_kernel<OUTD><<<(NTOK + 7) / 8, 256>>>(
        t1, Wp2, bp2, out, NTOK);

    hgemm_kernel<1,1><<<dim3((DD/2)/128, 1), 256, GSMEM>>>(
        BB, DD/2, LAT, z16, ws1T, bs1, s1, nullptr, nullptr);
    head_kernel<5><<<(BB + 7) / 8, 256>>>(
        s1, Ws2, bs2, out + (size_t)NTOK * OUTD, BB);
}